// round 1
// baseline (speedup 1.0000x reference)
#include <cuda_runtime.h>
#include <math.h>
#include <stdint.h>

// Problem constants
constexpr int DIM  = 1024;
constexpr int NH   = 16;
constexpr int HDm  = 64;
constexpr int FFD  = 4096;
constexpr int BATCH= 2;
constexpr int SEQ  = 2048;
constexpr int MTOK = BATCH * SEQ;   // 4096

// ---------------- scratch (device globals; no allocation allowed) ----------
__device__ float g_q  [MTOK * DIM];
__device__ float g_k  [MTOK * DIM];
__device__ float g_v  [MTOK * DIM];
__device__ float g_ctx[MTOK * DIM];
__device__ float g_tmp[MTOK * DIM];   // attn_out, then ffn2 output
__device__ float g_x1 [MTOK * DIM];
__device__ float g_h  [MTOK * FFD];
__device__ float g_ff [MTOK * DIM];

// ---------------- SGEMM: C[M,N] = A[M,K] @ W[K,N] + bias (+GELU) -----------
// BM=BN=128, BK=16, TM=TN=8, 256 threads. All dims divisible (4096/1024).
template<bool GELU>
__global__ __launch_bounds__(256)
void sgemm_bias(const float* __restrict__ A, const float* __restrict__ W,
                const float* __restrict__ bias, float* __restrict__ C,
                int M, int N, int K)
{
    __shared__ float As[16][128 + 4];   // [k][m], padded
    __shared__ float Bs[16][128 + 4];   // [k][n], padded

    const int tid = threadIdx.x;
    const int tx = tid & 15;            // 0..15 (cols)
    const int ty = tid >> 4;            // 0..15 (rows)
    const int blockRow = blockIdx.y * 128;
    const int blockCol = blockIdx.x * 128;

    // A tile loads: 128x16 = 512 float4, 2 per thread
    const int a_r = tid >> 2;           // 0..63
    const int a_c = (tid & 3) * 4;      // 0,4,8,12
    // B tile loads: 16x128 = 512 float4, 2 per thread
    const int b_r = tid >> 5;           // 0..7
    const int b_c = (tid & 31) * 4;

    float acc[8][8];
    #pragma unroll
    for (int i = 0; i < 8; i++)
        #pragma unroll
        for (int j = 0; j < 8; j++) acc[i][j] = 0.f;

    for (int k0 = 0; k0 < K; k0 += 16) {
        #pragma unroll
        for (int it = 0; it < 2; it++) {
            int r = a_r + it * 64;
            float4 t = *(const float4*)(A + (size_t)(blockRow + r) * K + k0 + a_c);
            As[a_c + 0][r] = t.x;
            As[a_c + 1][r] = t.y;
            As[a_c + 2][r] = t.z;
            As[a_c + 3][r] = t.w;
        }
        #pragma unroll
        for (int it = 0; it < 2; it++) {
            int r = b_r + it * 8;
            *(float4*)(&Bs[r][b_c]) =
                *(const float4*)(W + (size_t)(k0 + r) * N + blockCol + b_c);
        }
        __syncthreads();

        #pragma unroll
        for (int kk = 0; kk < 16; kk++) {
            float a_frag[8], b_frag[8];
            *(float4*)&a_frag[0] = *(const float4*)&As[kk][ty * 8 + 0];
            *(float4*)&a_frag[4] = *(const float4*)&As[kk][ty * 8 + 4];
            *(float4*)&b_frag[0] = *(const float4*)&Bs[kk][tx * 8 + 0];
            *(float4*)&b_frag[4] = *(const float4*)&Bs[kk][tx * 8 + 4];
            #pragma unroll
            for (int i = 0; i < 8; i++)
                #pragma unroll
                for (int j = 0; j < 8; j++)
                    acc[i][j] += a_frag[i] * b_frag[j];
        }
        __syncthreads();
    }

    #pragma unroll
    for (int i = 0; i < 8; i++) {
        const size_t r = blockRow + ty * 8 + i;
        #pragma unroll
        for (int j = 0; j < 8; j += 4) {
            const int c = blockCol + tx * 8 + j;
            float4 v;
            v.x = acc[i][j + 0] + bias[c + 0];
            v.y = acc[i][j + 1] + bias[c + 1];
            v.z = acc[i][j + 2] + bias[c + 2];
            v.w = acc[i][j + 3] + bias[c + 3];
            if (GELU) {
                v.x = 0.5f * v.x * (1.f + erff(v.x * 0.70710678118654752f));
                v.y = 0.5f * v.y * (1.f + erff(v.y * 0.70710678118654752f));
                v.z = 0.5f * v.z * (1.f + erff(v.z * 0.70710678118654752f));
                v.w = 0.5f * v.w * (1.f + erff(v.w * 0.70710678118654752f));
            }
            *(float4*)(C + r * N + c) = v;
        }
    }
}

// ---------------- Flash attention (fp32, online softmax) -------------------
// grid: (SEQ/64, BATCH*NH), block 256. Tile: 64 queries x 64 keys, HD=64.
// Thread layout 16x16, each thread a 4x4 micro-tile.
constexpr int FL_STRIDE = 68;                       // padded row stride
constexpr int FLASH_SMEM = (4 * 64 * FL_STRIDE + 64) * (int)sizeof(float);

__global__ __launch_bounds__(256)
void flash_attn(const float* __restrict__ Q, const float* __restrict__ K,
                const float* __restrict__ V, const int* __restrict__ amask,
                float* __restrict__ O)
{
    extern __shared__ float sm[];
    float* Qs  = sm;                       // [k][m]  64 x 68
    float* Ks  = Qs + 64 * FL_STRIDE;      // [k][n]
    float* Vs  = Ks + 64 * FL_STRIDE;      // [j][d]
    float* Ps  = Vs + 64 * FL_STRIDE;      // [j][m]
    float* msk = Ps + 64 * FL_STRIDE;      // [64]

    const int tid = threadIdx.x;
    const int tx = tid & 15, ty = tid >> 4;
    const int bh = blockIdx.y;
    const int b = bh >> 4, h = bh & 15;
    const int q0 = blockIdx.x * 64;

    const float* Qb = Q + ((size_t)b * SEQ) * DIM + h * HDm;
    const float* Kb = K + ((size_t)b * SEQ) * DIM + h * HDm;
    const float* Vb = V + ((size_t)b * SEQ) * DIM + h * HDm;

    // load Q tile (transposed to [k][m])
    #pragma unroll
    for (int it = 0; it < 4; it++) {
        int idx = tid + it * 256;
        int r = idx >> 4, c4 = (idx & 15) * 4;
        float4 t = *(const float4*)(Qb + (size_t)(q0 + r) * DIM + c4);
        Qs[(c4 + 0) * FL_STRIDE + r] = t.x;
        Qs[(c4 + 1) * FL_STRIDE + r] = t.y;
        Qs[(c4 + 2) * FL_STRIDE + r] = t.z;
        Qs[(c4 + 3) * FL_STRIDE + r] = t.w;
    }

    float m_i[4], l_i[4], o[4][4];
    #pragma unroll
    for (int i = 0; i < 4; i++) {
        m_i[i] = -INFINITY; l_i[i] = 0.f;
        #pragma unroll
        for (int d = 0; d < 4; d++) o[i][d] = 0.f;
    }

    for (int k0 = 0; k0 < SEQ; k0 += 64) {
        __syncthreads();   // previous P@V done before overwriting K/V/P
        #pragma unroll
        for (int it = 0; it < 4; it++) {
            int idx = tid + it * 256;
            int r = idx >> 4, c4 = (idx & 15) * 4;
            float4 t = *(const float4*)(Kb + (size_t)(k0 + r) * DIM + c4);
            Ks[(c4 + 0) * FL_STRIDE + r] = t.x;
            Ks[(c4 + 1) * FL_STRIDE + r] = t.y;
            Ks[(c4 + 2) * FL_STRIDE + r] = t.z;
            Ks[(c4 + 3) * FL_STRIDE + r] = t.w;
            float4 u = *(const float4*)(Vb + (size_t)(k0 + r) * DIM + c4);
            *(float4*)(Vs + r * FL_STRIDE + c4) = u;
        }
        if (tid < 64) msk[tid] = (float)amask[b * SEQ + k0 + tid];
        __syncthreads();

        // S = Q K^T / 8
        float acc[4][4];
        #pragma unroll
        for (int i = 0; i < 4; i++)
            #pragma unroll
            for (int j = 0; j < 4; j++) acc[i][j] = 0.f;

        #pragma unroll 8
        for (int kk = 0; kk < 64; kk++) {
            float4 aq = *(const float4*)(Qs + kk * FL_STRIDE + ty * 4);
            float4 bk = *(const float4*)(Ks + kk * FL_STRIDE + tx * 4);
            float a[4] = {aq.x, aq.y, aq.z, aq.w};
            float bb[4] = {bk.x, bk.y, bk.z, bk.w};
            #pragma unroll
            for (int i = 0; i < 4; i++)
                #pragma unroll
                for (int j = 0; j < 4; j++)
                    acc[i][j] += a[i] * bb[j];
        }

        float s[4][4];
        #pragma unroll
        for (int i = 0; i < 4; i++)
            #pragma unroll
            for (int j = 0; j < 4; j++) {
                float sv = acc[i][j] * 0.125f;
                if (msk[tx * 4 + j] == 0.f) sv = -1e9f;
                s[i][j] = sv;
            }

        // online softmax
        float tmax[4], rsum[4];
        #pragma unroll
        for (int i = 0; i < 4; i++) {
            float t = fmaxf(fmaxf(s[i][0], s[i][1]), fmaxf(s[i][2], s[i][3]));
            #pragma unroll
            for (int mm = 8; mm; mm >>= 1)
                t = fmaxf(t, __shfl_xor_sync(0xffffffffu, t, mm));
            tmax[i] = t;
        }
        float p[4][4];
        #pragma unroll
        for (int i = 0; i < 4; i++) {
            float mnew = fmaxf(m_i[i], tmax[i]);
            float f = __expf(m_i[i] - mnew);
            float rs = 0.f;
            #pragma unroll
            for (int j = 0; j < 4; j++) {
                float pv = __expf(s[i][j] - mnew);
                p[i][j] = pv;
                rs += pv;
            }
            #pragma unroll
            for (int mm = 8; mm; mm >>= 1)
                rs += __shfl_xor_sync(0xffffffffu, rs, mm);
            l_i[i] = l_i[i] * f + rs;
            m_i[i] = mnew;
            #pragma unroll
            for (int d = 0; d < 4; d++) o[i][d] *= f;
        }
        // store P transposed to [j][m]
        #pragma unroll
        for (int i = 0; i < 4; i++)
            #pragma unroll
            for (int j = 0; j < 4; j++)
                Ps[(tx * 4 + j) * FL_STRIDE + (ty * 4 + i)] = p[i][j];
        __syncthreads();

        // O += P V
        #pragma unroll 8
        for (int j = 0; j < 64; j++) {
            float4 ap = *(const float4*)(Ps + j * FL_STRIDE + ty * 4);
            float4 bv = *(const float4*)(Vs + j * FL_STRIDE + tx * 4);
            float a[4] = {ap.x, ap.y, ap.z, ap.w};
            float bb[4] = {bv.x, bv.y, bv.z, bv.w};
            #pragma unroll
            for (int i = 0; i < 4; i++)
                #pragma unroll
                for (int d = 0; d < 4; d++)
                    o[i][d] += a[i] * bb[d];
        }
    }

    float* Ob = O + ((size_t)b * SEQ) * DIM + h * HDm;
    #pragma unroll
    for (int i = 0; i < 4; i++) {
        float inv = 1.f / l_i[i];
        float4 r;
        r.x = o[i][0] * inv; r.y = o[i][1] * inv;
        r.z = o[i][2] * inv; r.w = o[i][3] * inv;
        *(float4*)(Ob + (size_t)(q0 + ty * 4 + i) * DIM + tx * 4) = r;
    }
}

// ---------------- residual add + LayerNorm ---------------------------------
// out = LN(a + b; g, beta, eps). One block per row, 256 threads, D=1024.
__global__ __launch_bounds__(256)
void ln_residual(const float* __restrict__ A, const float* __restrict__ Bv,
                 const float* __restrict__ g, const float* __restrict__ be,
                 float* __restrict__ out, float eps)
{
    const int row = blockIdx.x;
    const int tid = threadIdx.x;
    const float4 va = ((const float4*)(A  + (size_t)row * DIM))[tid];
    const float4 vb = ((const float4*)(Bv + (size_t)row * DIM))[tid];
    float4 v;
    v.x = va.x + vb.x; v.y = va.y + vb.y;
    v.z = va.z + vb.z; v.w = va.w + vb.w;

    float sum = v.x + v.y + v.z + v.w;
    float sq  = v.x * v.x + v.y * v.y + v.z * v.z + v.w * v.w;
    #pragma unroll
    for (int mm = 16; mm; mm >>= 1) {
        sum += __shfl_xor_sync(0xffffffffu, sum, mm);
        sq  += __shfl_xor_sync(0xffffffffu, sq,  mm);
    }
    __shared__ float ssum[8], ssq[8], stats[2];
    const int wid = tid >> 5, lane = tid & 31;
    if (lane == 0) { ssum[wid] = sum; ssq[wid] = sq; }
    __syncthreads();
    if (tid == 0) {
        float S = 0.f, Qq = 0.f;
        #pragma unroll
        for (int i = 0; i < 8; i++) { S += ssum[i]; Qq += ssq[i]; }
        float mean = S * (1.f / DIM);
        float var  = fmaxf(Qq * (1.f / DIM) - mean * mean, 0.f);
        stats[0] = mean;
        stats[1] = rsqrtf(var + eps);
    }
    __syncthreads();
    const float mean = stats[0], rstd = stats[1];
    const float4 gg = ((const float4*)g)[tid];
    const float4 bb = ((const float4*)be)[tid];
    float4 r;
    r.x = (v.x - mean) * rstd * gg.x + bb.x;
    r.y = (v.y - mean) * rstd * gg.y + bb.y;
    r.z = (v.z - mean) * rstd * gg.z + bb.z;
    r.w = (v.w - mean) * rstd * gg.w + bb.w;
    ((float4*)(out + (size_t)row * DIM))[tid] = r;
}

// ---------------- launch ----------------------------------------------------
extern "C" void kernel_launch(void* const* d_in, const int* in_sizes, int n_in,
                              void* d_out, int out_size)
{
    const float* x     = (const float*)d_in[0];
    const int*   amask = (const int*  )d_in[1];
    const float* wq = (const float*)d_in[2];
    const float* bq = (const float*)d_in[3];
    const float* wk = (const float*)d_in[4];
    const float* bk = (const float*)d_in[5];
    const float* wv = (const float*)d_in[6];
    const float* bv = (const float*)d_in[7];
    const float* wo = (const float*)d_in[8];
    const float* bo = (const float*)d_in[9];
    const float* ln1_g = (const float*)d_in[10];
    const float* ln1_b = (const float*)d_in[11];
    const float* w1 = (const float*)d_in[12];
    const float* b1 = (const float*)d_in[13];
    const float* w2 = (const float*)d_in[14];
    const float* b2 = (const float*)d_in[15];
    const float* lnf_g = (const float*)d_in[16];
    const float* lnf_b = (const float*)d_in[17];
    const float* ln2_g = (const float*)d_in[18];
    const float* ln2_b = (const float*)d_in[19];
    float* out = (float*)d_out;

    float *q, *k, *v, *ctx, *tmp, *x1, *hb, *ff;
    cudaGetSymbolAddress((void**)&q,   g_q);
    cudaGetSymbolAddress((void**)&k,   g_k);
    cudaGetSymbolAddress((void**)&v,   g_v);
    cudaGetSymbolAddress((void**)&ctx, g_ctx);
    cudaGetSymbolAddress((void**)&tmp, g_tmp);
    cudaGetSymbolAddress((void**)&x1,  g_x1);
    cudaGetSymbolAddress((void**)&hb,  g_h);
    cudaGetSymbolAddress((void**)&ff,  g_ff);

    cudaFuncSetAttribute(flash_attn,
                         cudaFuncAttributeMaxDynamicSharedMemorySize, FLASH_SMEM);

    const dim3 blk(256);
    const dim3 gQKV(DIM / 128, MTOK / 128);          // (8, 32)
    const dim3 gFF1(FFD / 128, MTOK / 128);          // (32, 32)
    const dim3 gFF2(DIM / 128, MTOK / 128);          // (8, 32)

    // QKV projections
    sgemm_bias<false><<<gQKV, blk>>>(x, wq, bq, q, MTOK, DIM, DIM);
    sgemm_bias<false><<<gQKV, blk>>>(x, wk, bk, k, MTOK, DIM, DIM);
    sgemm_bias<false><<<gQKV, blk>>>(x, wv, bv, v, MTOK, DIM, DIM);

    // attention
    flash_attn<<<dim3(SEQ / 64, BATCH * NH), blk, FLASH_SMEM>>>(q, k, v, amask, ctx);

    // output projection + residual LN1
    sgemm_bias<false><<<gQKV, blk>>>(ctx, wo, bo, tmp, MTOK, DIM, DIM);
    ln_residual<<<MTOK, blk>>>(x, tmp, ln1_g, ln1_b, x1, 1e-5f);

    // FFN
    sgemm_bias<true ><<<gFF1, blk>>>(x1, w1, b1, hb, MTOK, FFD, DIM);
    sgemm_bias<false><<<gFF2, blk>>>(hb, w2, b2, tmp, MTOK, DIM, FFD);
    ln_residual<<<MTOK, blk>>>(tmp, x1, lnf_g, lnf_b, ff, 1e-12f);

    // final LN
    ln_residual<<<MTOK, blk>>>(x1, ff, ln2_g, ln2_b, out, 1e-5f);
}

// round 3
// speedup vs baseline: 1.6909x; 1.6909x over previous
#include <cuda_runtime.h>
#include <cuda_bf16.h>
#include <math.h>
#include <stdint.h>

// Problem constants
constexpr int DIM  = 1024;
constexpr int NH   = 16;
constexpr int HDm  = 64;
constexpr int FFD  = 4096;
constexpr int BATCH= 2;
constexpr int SEQ  = 2048;
constexpr int MTOK = BATCH * SEQ;   // 4096

// ---------------------------------------------------------------------------
// helpers
// ---------------------------------------------------------------------------
__device__ __forceinline__ uint32_t smem_to_u32(const void* p) {
    uint32_t a;
    asm("{ .reg .u64 t; cvta.to.shared.u64 t, %1; cvt.u32.u64 %0, t; }"
        : "=r"(a) : "l"(p));
    return a;
}

__device__ __forceinline__ void ldsm_x4(uint32_t* r, uint32_t addr) {
    asm volatile("ldmatrix.sync.aligned.m8n8.x4.shared.b16 {%0,%1,%2,%3}, [%4];"
                 : "=r"(r[0]), "=r"(r[1]), "=r"(r[2]), "=r"(r[3]) : "r"(addr));
}

__device__ __forceinline__ void mma16816(float* c, const uint32_t* a, const uint32_t* b) {
    asm volatile(
        "mma.sync.aligned.m16n8k16.row.col.f32.bf16.bf16.f32 "
        "{%0,%1,%2,%3}, {%4,%5,%6,%7}, {%8,%9}, {%0,%1,%2,%3};"
        : "+f"(c[0]), "+f"(c[1]), "+f"(c[2]), "+f"(c[3])
        : "r"(a[0]), "r"(a[1]), "r"(a[2]), "r"(a[3]), "r"(b[0]), "r"(b[1]));
}

// ---------------------------------------------------------------------------
// scratch (device globals; no allocation allowed)
// ---------------------------------------------------------------------------
__device__ __align__(256) float g_q  [MTOK * DIM];
__device__ __align__(256) float g_k  [MTOK * DIM];
__device__ __align__(256) float g_v  [MTOK * DIM];
__device__ __align__(256) float g_ctx[MTOK * DIM];
__device__ __align__(256) float g_tmp[MTOK * DIM];
__device__ __align__(256) float g_x1 [MTOK * DIM];
__device__ __align__(256) float g_ff [MTOK * DIM];

// bf16 hi/lo activations
__device__ __align__(256) __nv_bfloat16 g_xh [MTOK * DIM],  g_xl [MTOK * DIM];
__device__ __align__(256) __nv_bfloat16 g_ctxh[MTOK * DIM], g_ctxl[MTOK * DIM];
__device__ __align__(256) __nv_bfloat16 g_x1h[MTOK * DIM],  g_x1l[MTOK * DIM];
__device__ __align__(256) __nv_bfloat16 g_hh [MTOK * FFD],  g_hl [MTOK * FFD];
// bf16 hi/lo transposed weights [N][K]
__device__ __align__(256) __nv_bfloat16 g_wqh[DIM * DIM], g_wql[DIM * DIM];
__device__ __align__(256) __nv_bfloat16 g_wkh[DIM * DIM], g_wkl[DIM * DIM];
__device__ __align__(256) __nv_bfloat16 g_wvh[DIM * DIM], g_wvl[DIM * DIM];
__device__ __align__(256) __nv_bfloat16 g_woh[DIM * DIM], g_wol[DIM * DIM];
__device__ __align__(256) __nv_bfloat16 g_w1h[DIM * FFD], g_w1l[DIM * FFD];  // [FFD][DIM]
__device__ __align__(256) __nv_bfloat16 g_w2h[FFD * DIM], g_w2l[FFD * DIM];  // [DIM][FFD]

// ---------------------------------------------------------------------------
// hi/lo split: hi = bf16(x), lo = bf16(x - hi)
// ---------------------------------------------------------------------------
__device__ __forceinline__ void split_hilo(float v, __nv_bfloat16& h, __nv_bfloat16& l) {
    h = __float2bfloat16(v);
    l = __float2bfloat16(v - __bfloat162float(h));
}

__global__ __launch_bounds__(256)
void convert_hilo(const float* __restrict__ in, __nv_bfloat16* __restrict__ oh,
                  __nv_bfloat16* __restrict__ ol, int count)
{
    int i = (blockIdx.x * 256 + threadIdx.x) * 4;
    if (i >= count) return;
    float4 v = *(const float4*)(in + i);
    __nv_bfloat16 h0, l0, h1, l1, h2, l2, h3, l3;
    split_hilo(v.x, h0, l0); split_hilo(v.y, h1, l1);
    split_hilo(v.z, h2, l2); split_hilo(v.w, h3, l3);
    __nv_bfloat162 hA(h0, h1), hB(h2, h3), lA(l0, l1), lB(l2, l3);
    *(uint2*)(oh + i) = make_uint2(*(uint32_t*)&hA, *(uint32_t*)&hB);
    *(uint2*)(ol + i) = make_uint2(*(uint32_t*)&lA, *(uint32_t*)&lB);
}

// transpose + split: in[K][N] fp32 -> oh/ol[N][K] bf16
__global__ __launch_bounds__(256)
void transpose_convert(const float* __restrict__ in, __nv_bfloat16* __restrict__ oh,
                       __nv_bfloat16* __restrict__ ol, int K, int N)
{
    __shared__ float t[32][33];
    const int n0 = blockIdx.x * 32, k0 = blockIdx.y * 32;
    const int tx = threadIdx.x & 31, ty = threadIdx.x >> 5;  // 32 x 8
    #pragma unroll
    for (int j = 0; j < 32; j += 8)
        t[ty + j][tx] = in[(size_t)(k0 + ty + j) * N + n0 + tx];
    __syncthreads();
    #pragma unroll
    for (int j = 0; j < 32; j += 8) {
        float v = t[tx][ty + j];
        int n = n0 + ty + j, k = k0 + tx;
        __nv_bfloat16 h, l;
        split_hilo(v, h, l);
        oh[(size_t)n * K + k] = h;
        ol[(size_t)n * K + k] = l;
    }
}

// ---------------------------------------------------------------------------
// HMMA bf16x3 GEMM: C[M,N] = A[M,K] @ Bt[N,K]^T + bias (+GELU, +hi/lo emit)
// Tile 128x128, BK=32, 256 threads (8 warps, 2x4), warp tile 64x32.
// cp.async double-buffered smem; ldmatrix fragment loads; mma.sync bf16.
// ---------------------------------------------------------------------------
constexpr int HG_RSTRIDE = 80;                 // bytes per row (32 bf16 + 8 pad)
constexpr int HG_TILE    = 128 * HG_RSTRIDE;   // 10240 B
constexpr int HG_STAGE   = 4 * HG_TILE;        // Ah, Al, Bh, Bl = 40960 B
constexpr int HG_SMEM    = 2 * HG_STAGE;       // 81920 B

__device__ __forceinline__ void hg_load_tile(const __nv_bfloat16* __restrict__ src,
                                             int rowBase, int K, int k0,
                                             uint32_t dstBase, int tid)
{
    #pragma unroll
    for (int i = 0; i < 2; i++) {
        int c = tid + i * 256;                 // 0..511 chunk id (16B chunks)
        int row = c >> 2, cc = c & 3;
        uint32_t dst = dstBase + row * HG_RSTRIDE + cc * 16;
        const void* s = src + (size_t)(rowBase + row) * K + k0 + cc * 8;
        asm volatile("cp.async.ca.shared.global [%0], [%1], 16;" :: "r"(dst), "l"(s));
    }
}

template<bool GELU, bool WRITE_F32, bool EMIT_BF16>
__global__ __launch_bounds__(256, 1)
void hmma_gemm(const __nv_bfloat16* __restrict__ Ah, const __nv_bfloat16* __restrict__ Al,
               const __nv_bfloat16* __restrict__ Bh, const __nv_bfloat16* __restrict__ Bl,
               const float* __restrict__ bias, float* __restrict__ C,
               __nv_bfloat16* __restrict__ Ch, __nv_bfloat16* __restrict__ Cl,
               int M, int N, int K)
{
    extern __shared__ char smem[];
    const uint32_t sb = smem_to_u32(smem);
    const int tid = threadIdx.x, wid = tid >> 5, lane = tid & 31;
    const int warpM = wid >> 2, warpN = wid & 3;     // 2 x 4 warp grid
    const int bRow = blockIdx.y * 128, bCol = blockIdx.x * 128;

    float acc[4][4][4];
    #pragma unroll
    for (int m = 0; m < 4; m++)
        #pragma unroll
        for (int n = 0; n < 4; n++)
            #pragma unroll
            for (int e = 0; e < 4; e++) acc[m][n][e] = 0.f;

    // prologue: stage 0
    {
        uint32_t base = sb;
        hg_load_tile(Ah, bRow, K, 0, base + 0 * HG_TILE, tid);
        hg_load_tile(Al, bRow, K, 0, base + 1 * HG_TILE, tid);
        hg_load_tile(Bh, bCol, K, 0, base + 2 * HG_TILE, tid);
        hg_load_tile(Bl, bCol, K, 0, base + 3 * HG_TILE, tid);
        asm volatile("cp.async.commit_group;");
    }

    const int nk = K >> 5;
    for (int ks = 0; ks < nk; ks++) {
        const int s = ks & 1;
        if (ks + 1 < nk) {
            uint32_t base = sb + (s ^ 1) * HG_STAGE;
            const int k0 = (ks + 1) << 5;
            hg_load_tile(Ah, bRow, K, k0, base + 0 * HG_TILE, tid);
            hg_load_tile(Al, bRow, K, k0, base + 1 * HG_TILE, tid);
            hg_load_tile(Bh, bCol, K, k0, base + 2 * HG_TILE, tid);
            hg_load_tile(Bl, bCol, K, k0, base + 3 * HG_TILE, tid);
            asm volatile("cp.async.commit_group;");
            asm volatile("cp.async.wait_group 1;");
        } else {
            asm volatile("cp.async.wait_group 0;");
        }
        __syncthreads();

        const uint32_t stg = sb + s * HG_STAGE;
        #pragma unroll
        for (int h = 0; h < 2; h++) {
            const int ke = h * 16;
            uint32_t aHi[4][4], aLo[4][4], bHi[4][2], bLo[4][2];
            #pragma unroll
            for (int m = 0; m < 4; m++) {
                uint32_t ra = stg
                    + (warpM * 64 + m * 16 + (lane & 15)) * HG_RSTRIDE
                    + (ke + (lane >> 4) * 8) * 2;
                ldsm_x4(aHi[m], ra);
                ldsm_x4(aLo[m], ra + HG_TILE);
            }
            #pragma unroll
            for (int jp = 0; jp < 2; jp++) {
                uint32_t rb = stg + 2 * HG_TILE
                    + (warpN * 32 + jp * 16 + (lane >> 4) * 8 + (lane & 7)) * HG_RSTRIDE
                    + (ke + ((lane >> 3) & 1) * 8) * 2;
                uint32_t t4[4];
                ldsm_x4(t4, rb);
                bHi[2*jp][0] = t4[0]; bHi[2*jp][1] = t4[1];
                bHi[2*jp+1][0] = t4[2]; bHi[2*jp+1][1] = t4[3];
                ldsm_x4(t4, rb + HG_TILE);
                bLo[2*jp][0] = t4[0]; bLo[2*jp][1] = t4[1];
                bLo[2*jp+1][0] = t4[2]; bLo[2*jp+1][1] = t4[3];
            }
            #pragma unroll
            for (int m = 0; m < 4; m++)
                #pragma unroll
                for (int n = 0; n < 4; n++) {
                    mma16816(acc[m][n], aHi[m], bHi[n]);
                    mma16816(acc[m][n], aHi[m], bLo[n]);
                    mma16816(acc[m][n], aLo[m], bHi[n]);
                }
        }
        __syncthreads();
    }

    // epilogue
    #pragma unroll
    for (int m = 0; m < 4; m++) {
        #pragma unroll
        for (int half = 0; half < 2; half++) {
            const size_t row = bRow + warpM * 64 + m * 16 + (lane >> 2) + half * 8;
            #pragma unroll
            for (int n = 0; n < 4; n++) {
                const int col = bCol + warpN * 32 + n * 8 + (lane & 3) * 2;
                float v0 = acc[m][n][half * 2 + 0] + bias[col];
                float v1 = acc[m][n][half * 2 + 1] + bias[col + 1];
                if (GELU) {
                    v0 = 0.5f * v0 * (1.f + erff(v0 * 0.70710678118654752f));
                    v1 = 0.5f * v1 * (1.f + erff(v1 * 0.70710678118654752f));
                }
                if (WRITE_F32) {
                    float2 w; w.x = v0; w.y = v1;
                    *(float2*)(C + row * N + col) = w;
                }
                if (EMIT_BF16) {
                    __nv_bfloat16 h0, l0, h1, l1;
                    split_hilo(v0, h0, l0); split_hilo(v1, h1, l1);
                    __nv_bfloat162 hp(h0, h1), lp(l0, l1);
                    *(uint32_t*)(Ch + row * N + col) = *(uint32_t*)&hp;
                    *(uint32_t*)(Cl + row * N + col) = *(uint32_t*)&lp;
                }
            }
        }
    }
}

// ---------------- Flash attention (fp32, online softmax) -------------------
constexpr int FL_STRIDE = 68;
constexpr int FLASH_SMEM = (4 * 64 * FL_STRIDE + 64) * (int)sizeof(float);

__global__ __launch_bounds__(256)
void flash_attn(const float* __restrict__ Q, const float* __restrict__ K,
                const float* __restrict__ V, const int* __restrict__ amask,
                float* __restrict__ O)
{
    extern __shared__ float sm[];
    float* Qs  = sm;
    float* Ks  = Qs + 64 * FL_STRIDE;
    float* Vs  = Ks + 64 * FL_STRIDE;
    float* Ps  = Vs + 64 * FL_STRIDE;
    float* msk = Ps + 64 * FL_STRIDE;

    const int tid = threadIdx.x;
    const int tx = tid & 15, ty = tid >> 4;
    const int bh = blockIdx.y;
    const int b = bh >> 4, h = bh & 15;
    const int q0 = blockIdx.x * 64;

    const float* Qb = Q + ((size_t)b * SEQ) * DIM + h * HDm;
    const float* Kb = K + ((size_t)b * SEQ) * DIM + h * HDm;
    const float* Vb = V + ((size_t)b * SEQ) * DIM + h * HDm;

    #pragma unroll
    for (int it = 0; it < 4; it++) {
        int idx = tid + it * 256;
        int r = idx >> 4, c4 = (idx & 15) * 4;
        float4 t = *(const float4*)(Qb + (size_t)(q0 + r) * DIM + c4);
        Qs[(c4 + 0) * FL_STRIDE + r] = t.x;
        Qs[(c4 + 1) * FL_STRIDE + r] = t.y;
        Qs[(c4 + 2) * FL_STRIDE + r] = t.z;
        Qs[(c4 + 3) * FL_STRIDE + r] = t.w;
    }

    float m_i[4], l_i[4], o[4][4];
    #pragma unroll
    for (int i = 0; i < 4; i++) {
        m_i[i] = -INFINITY; l_i[i] = 0.f;
        #pragma unroll
        for (int d = 0; d < 4; d++) o[i][d] = 0.f;
    }

    for (int k0 = 0; k0 < SEQ; k0 += 64) {
        __syncthreads();
        #pragma unroll
        for (int it = 0; it < 4; it++) {
            int idx = tid + it * 256;
            int r = idx >> 4, c4 = (idx & 15) * 4;
            float4 t = *(const float4*)(Kb + (size_t)(k0 + r) * DIM + c4);
            Ks[(c4 + 0) * FL_STRIDE + r] = t.x;
            Ks[(c4 + 1) * FL_STRIDE + r] = t.y;
            Ks[(c4 + 2) * FL_STRIDE + r] = t.z;
            Ks[(c4 + 3) * FL_STRIDE + r] = t.w;
            float4 uv = *(const float4*)(Vb + (size_t)(k0 + r) * DIM + c4);
            *(float4*)(Vs + r * FL_STRIDE + c4) = uv;
        }
        if (tid < 64) msk[tid] = (float)amask[b * SEQ + k0 + tid];
        __syncthreads();

        float acc[4][4];
        #pragma unroll
        for (int i = 0; i < 4; i++)
            #pragma unroll
            for (int j = 0; j < 4; j++) acc[i][j] = 0.f;

        #pragma unroll 8
        for (int kk = 0; kk < 64; kk++) {
            float4 aq = *(const float4*)(Qs + kk * FL_STRIDE + ty * 4);
            float4 bk = *(const float4*)(Ks + kk * FL_STRIDE + tx * 4);
            float a[4] = {aq.x, aq.y, aq.z, aq.w};
            float bb[4] = {bk.x, bk.y, bk.z, bk.w};
            #pragma unroll
            for (int i = 0; i < 4; i++)
                #pragma unroll
                for (int j = 0; j < 4; j++)
                    acc[i][j] += a[i] * bb[j];
        }

        float s[4][4];
        #pragma unroll
        for (int i = 0; i < 4; i++)
            #pragma unroll
            for (int j = 0; j < 4; j++) {
                float sv = acc[i][j] * 0.125f;
                if (msk[tx * 4 + j] == 0.f) sv = -1e9f;
                s[i][j] = sv;
            }

        float tmax[4];
        #pragma unroll
        for (int i = 0; i < 4; i++) {
            float t = fmaxf(fmaxf(s[i][0], s[i][1]), fmaxf(s[i][2], s[i][3]));
            #pragma unroll
            for (int mm = 8; mm; mm >>= 1)
                t = fmaxf(t, __shfl_xor_sync(0xffffffffu, t, mm));
            tmax[i] = t;
        }
        float p[4][4];
        #pragma unroll
        for (int i = 0; i < 4; i++) {
            float mnew = fmaxf(m_i[i], tmax[i]);
            float f = __expf(m_i[i] - mnew);
            float rs = 0.f;
            #pragma unroll
            for (int j = 0; j < 4; j++) {
                float pv = __expf(s[i][j] - mnew);
                p[i][j] = pv;
                rs += pv;
            }
            #pragma unroll
            for (int mm = 8; mm; mm >>= 1)
                rs += __shfl_xor_sync(0xffffffffu, rs, mm);
            l_i[i] = l_i[i] * f + rs;
            m_i[i] = mnew;
            #pragma unroll
            for (int d = 0; d < 4; d++) o[i][d] *= f;
        }
        #pragma unroll
        for (int i = 0; i < 4; i++)
            #pragma unroll
            for (int j = 0; j < 4; j++)
                Ps[(tx * 4 + j) * FL_STRIDE + (ty * 4 + i)] = p[i][j];
        __syncthreads();

        #pragma unroll 8
        for (int j = 0; j < 64; j++) {
            float4 ap = *(const float4*)(Ps + j * FL_STRIDE + ty * 4);
            float4 bv = *(const float4*)(Vs + j * FL_STRIDE + tx * 4);
            float a[4] = {ap.x, ap.y, ap.z, ap.w};
            float bb[4] = {bv.x, bv.y, bv.z, bv.w};
            #pragma unroll
            for (int i = 0; i < 4; i++)
                #pragma unroll
                for (int d = 0; d < 4; d++)
                    o[i][d] += a[i] * bb[d];
        }
    }

    float* Ob = O + ((size_t)b * SEQ) * DIM + h * HDm;
    #pragma unroll
    for (int i = 0; i < 4; i++) {
        float inv = 1.f / l_i[i];
        float4 r;
        r.x = o[i][0] * inv; r.y = o[i][1] * inv;
        r.z = o[i][2] * inv; r.w = o[i][3] * inv;
        *(float4*)(Ob + (size_t)(q0 + ty * 4 + i) * DIM + tx * 4) = r;
    }
}

// ---------------- residual add + LayerNorm (+optional hi/lo emit) ----------
template<bool EMIT>
__global__ __launch_bounds__(256)
void ln_residual(const float* __restrict__ A, const float* __restrict__ Bv,
                 const float* __restrict__ g, const float* __restrict__ be,
                 float* __restrict__ out, __nv_bfloat16* __restrict__ oh,
                 __nv_bfloat16* __restrict__ ol, float eps)
{
    const int row = blockIdx.x;
    const int tid = threadIdx.x;
    const float4 va = ((const float4*)(A  + (size_t)row * DIM))[tid];
    const float4 vb = ((const float4*)(Bv + (size_t)row * DIM))[tid];
    float4 v;
    v.x = va.x + vb.x; v.y = va.y + vb.y;
    v.z = va.z + vb.z; v.w = va.w + vb.w;

    float sum = v.x + v.y + v.z + v.w;
    float sq  = v.x * v.x + v.y * v.y + v.z * v.z + v.w * v.w;
    #pragma unroll
    for (int mm = 16; mm; mm >>= 1) {
        sum += __shfl_xor_sync(0xffffffffu, sum, mm);
        sq  += __shfl_xor_sync(0xffffffffu, sq,  mm);
    }
    __shared__ float ssum[8], ssq[8], stats[2];
    const int wid = tid >> 5, lane = tid & 31;
    if (lane == 0) { ssum[wid] = sum; ssq[wid] = sq; }
    __syncthreads();
    if (tid == 0) {
        float S = 0.f, Qq = 0.f;
        #pragma unroll
        for (int i = 0; i < 8; i++) { S += ssum[i]; Qq += ssq[i]; }
        float mean = S * (1.f / DIM);
        float var  = fmaxf(Qq * (1.f / DIM) - mean * mean, 0.f);
        stats[0] = mean;
        stats[1] = rsqrtf(var + eps);
    }
    __syncthreads();
    const float mean = stats[0], rstd = stats[1];
    const float4 gg = ((const float4*)g)[tid];
    const float4 bb = ((const float4*)be)[tid];
    float4 r;
    r.x = (v.x - mean) * rstd * gg.x + bb.x;
    r.y = (v.y - mean) * rstd * gg.y + bb.y;
    r.z = (v.z - mean) * rstd * gg.z + bb.z;
    r.w = (v.w - mean) * rstd * gg.w + bb.w;
    ((float4*)(out + (size_t)row * DIM))[tid] = r;
    if (EMIT) {
        __nv_bfloat16 h0,l0,h1,l1,h2,l2,h3,l3;
        split_hilo(r.x,h0,l0); split_hilo(r.y,h1,l1);
        split_hilo(r.z,h2,l2); split_hilo(r.w,h3,l3);
        __nv_bfloat162 hA(h0,h1), hB(h2,h3), lA(l0,l1), lB(l2,l3);
        ((uint2*)(oh + (size_t)row * DIM))[tid] = make_uint2(*(uint32_t*)&hA, *(uint32_t*)&hB);
        ((uint2*)(ol + (size_t)row * DIM))[tid] = make_uint2(*(uint32_t*)&lA, *(uint32_t*)&lB);
    }
}

// ---------------- launch ----------------------------------------------------
extern "C" void kernel_launch(void* const* d_in, const int* in_sizes, int n_in,
                              void* d_out, int out_size)
{
    const float* x     = (const float*)d_in[0];
    const int*   amask = (const int*  )d_in[1];
    const float* wq = (const float*)d_in[2];
    const float* bq = (const float*)d_in[3];
    const float* wk = (const float*)d_in[4];
    const float* bk = (const float*)d_in[5];
    const float* wv = (const float*)d_in[6];
    const float* bv = (const float*)d_in[7];
    const float* wo = (const float*)d_in[8];
    const float* bo = (const float*)d_in[9];
    const float* ln1_g = (const float*)d_in[10];
    const float* ln1_b = (const float*)d_in[11];
    const float* w1 = (const float*)d_in[12];
    const float* b1 = (const float*)d_in[13];
    const float* w2 = (const float*)d_in[14];
    const float* b2 = (const float*)d_in[15];
    const float* lnf_g = (const float*)d_in[16];
    const float* lnf_b = (const float*)d_in[17];
    const float* ln2_g = (const float*)d_in[18];
    const float* ln2_b = (const float*)d_in[19];
    float* out = (float*)d_out;

    float *q, *k, *v, *ctx, *tmp, *x1, *ff;
    cudaGetSymbolAddress((void**)&q,   g_q);
    cudaGetSymbolAddress((void**)&k,   g_k);
    cudaGetSymbolAddress((void**)&v,   g_v);
    cudaGetSymbolAddress((void**)&ctx, g_ctx);
    cudaGetSymbolAddress((void**)&tmp, g_tmp);
    cudaGetSymbolAddress((void**)&x1,  g_x1);
    cudaGetSymbolAddress((void**)&ff,  g_ff);

    __nv_bfloat16 *xh,*xl,*ctxh,*ctxl,*x1h,*x1l,*hh,*hl;
    __nv_bfloat16 *wqh,*wql,*wkh,*wkl,*wvh,*wvl,*woh,*wol,*w1h,*w1l,*w2h,*w2l;
    cudaGetSymbolAddress((void**)&xh,  g_xh);   cudaGetSymbolAddress((void**)&xl,  g_xl);
    cudaGetSymbolAddress((void**)&ctxh,g_ctxh); cudaGetSymbolAddress((void**)&ctxl,g_ctxl);
    cudaGetSymbolAddress((void**)&x1h, g_x1h);  cudaGetSymbolAddress((void**)&x1l, g_x1l);
    cudaGetSymbolAddress((void**)&hh,  g_hh);   cudaGetSymbolAddress((void**)&hl,  g_hl);
    cudaGetSymbolAddress((void**)&wqh, g_wqh);  cudaGetSymbolAddress((void**)&wql, g_wql);
    cudaGetSymbolAddress((void**)&wkh, g_wkh);  cudaGetSymbolAddress((void**)&wkl, g_wkl);
    cudaGetSymbolAddress((void**)&wvh, g_wvh);  cudaGetSymbolAddress((void**)&wvl, g_wvl);
    cudaGetSymbolAddress((void**)&woh, g_woh);  cudaGetSymbolAddress((void**)&wol, g_wol);
    cudaGetSymbolAddress((void**)&w1h, g_w1h);  cudaGetSymbolAddress((void**)&w1l, g_w1l);
    cudaGetSymbolAddress((void**)&w2h, g_w2h);  cudaGetSymbolAddress((void**)&w2l, g_w2l);

    cudaFuncSetAttribute(flash_attn,
                         cudaFuncAttributeMaxDynamicSharedMemorySize, FLASH_SMEM);
    cudaFuncSetAttribute(hmma_gemm<false, true, false>,
                         cudaFuncAttributeMaxDynamicSharedMemorySize, HG_SMEM);
    cudaFuncSetAttribute(hmma_gemm<true, false, true>,
                         cudaFuncAttributeMaxDynamicSharedMemorySize, HG_SMEM);

    const dim3 blk(256);

    // weight transpose + hi/lo split: in[K][N] -> out[N][K]
    transpose_convert<<<dim3(DIM/32, DIM/32), blk>>>(wq, wqh, wql, DIM, DIM);
    transpose_convert<<<dim3(DIM/32, DIM/32), blk>>>(wk, wkh, wkl, DIM, DIM);
    transpose_convert<<<dim3(DIM/32, DIM/32), blk>>>(wv, wvh, wvl, DIM, DIM);
    transpose_convert<<<dim3(DIM/32, DIM/32), blk>>>(wo, woh, wol, DIM, DIM);
    transpose_convert<<<dim3(FFD/32, DIM/32), blk>>>(w1, w1h, w1l, DIM, FFD);
    transpose_convert<<<dim3(DIM/32, FFD/32), blk>>>(w2, w2h, w2l, FFD, DIM);

    // x -> hi/lo
    convert_hilo<<<(MTOK * DIM) / 1024, blk>>>(x, xh, xl, MTOK * DIM);

    // QKV projections (HMMA tensor cores)
    hmma_gemm<false,true,false><<<dim3(DIM/128, MTOK/128), blk, HG_SMEM>>>(
        xh, xl, wqh, wql, bq, q, nullptr, nullptr, MTOK, DIM, DIM);
    hmma_gemm<false,true,false><<<dim3(DIM/128, MTOK/128), blk, HG_SMEM>>>(
        xh, xl, wkh, wkl, bk, k, nullptr, nullptr, MTOK, DIM, DIM);
    hmma_gemm<false,true,false><<<dim3(DIM/128, MTOK/128), blk, HG_SMEM>>>(
        xh, xl, wvh, wvl, bv, v, nullptr, nullptr, MTOK, DIM, DIM);

    // attention (fp32)
    flash_attn<<<dim3(SEQ / 64, BATCH * NH), blk, FLASH_SMEM>>>(q, k, v, amask, ctx);

    // O projection
    convert_hilo<<<(MTOK * DIM) / 1024, blk>>>(ctx, ctxh, ctxl, MTOK * DIM);
    hmma_gemm<false,true,false><<<dim3(DIM/128, MTOK/128), blk, HG_SMEM>>>(
        ctxh, ctxl, woh, wol, bo, tmp, nullptr, nullptr, MTOK, DIM, DIM);
    ln_residual<true><<<MTOK, blk>>>(x, tmp, ln1_g, ln1_b, x1, x1h, x1l, 1e-5f);

    // FFN
    hmma_gemm<true,false,true><<<dim3(FFD/128, MTOK/128), blk, HG_SMEM>>>(
        x1h, x1l, w1h, w1l, b1, nullptr, hh, hl, MTOK, FFD, DIM);
    hmma_gemm<false,true,false><<<dim3(DIM/128, MTOK/128), blk, HG_SMEM>>>(
        hh, hl, w2h, w2l, b2, tmp, nullptr, nullptr, MTOK, DIM, FFD);
    ln_residual<false><<<MTOK, blk>>>(tmp, x1, lnf_g, lnf_b, ff, nullptr, nullptr, 1e-12f);

    // final LN
    ln_residual<false><<<MTOK, blk>>>(x1, ff, ln2_g, ln2_b, out, nullptr, nullptr, 1e-5f);
}

// round 4
// speedup vs baseline: 2.4329x; 1.4388x over previous
#include <cuda_runtime.h>
#include <cuda_bf16.h>
#include <math.h>
#include <stdint.h>

// Problem constants
constexpr int DIM  = 1024;
constexpr int NH   = 16;
constexpr int HDm  = 64;
constexpr int FFD  = 4096;
constexpr int BATCH= 2;
constexpr int SEQ  = 2048;
constexpr int MTOK = BATCH * SEQ;   // 4096

// ---------------------------------------------------------------------------
// helpers
// ---------------------------------------------------------------------------
__device__ __forceinline__ uint32_t smem_to_u32(const void* p) {
    uint32_t a;
    asm("{ .reg .u64 t; cvta.to.shared.u64 t, %1; cvt.u32.u64 %0, t; }"
        : "=r"(a) : "l"(p));
    return a;
}

__device__ __forceinline__ void ldsm_x4(uint32_t* r, uint32_t addr) {
    asm volatile("ldmatrix.sync.aligned.m8n8.x4.shared.b16 {%0,%1,%2,%3}, [%4];"
                 : "=r"(r[0]), "=r"(r[1]), "=r"(r[2]), "=r"(r[3]) : "r"(addr));
}

__device__ __forceinline__ void mma16816(float* c, const uint32_t* a, const uint32_t* b) {
    asm volatile(
        "mma.sync.aligned.m16n8k16.row.col.f32.bf16.bf16.f32 "
        "{%0,%1,%2,%3}, {%4,%5,%6,%7}, {%8,%9}, {%0,%1,%2,%3};"
        : "+f"(c[0]), "+f"(c[1]), "+f"(c[2]), "+f"(c[3])
        : "r"(a[0]), "r"(a[1]), "r"(a[2]), "r"(a[3]), "r"(b[0]), "r"(b[1]));
}

__device__ __forceinline__ void cpa16(uint32_t dst, const void* src) {
    asm volatile("cp.async.ca.shared.global [%0], [%1], 16;" :: "r"(dst), "l"(src));
}

__device__ __forceinline__ uint32_t pk2(float a, float b) {
    __nv_bfloat162 t(__float2bfloat16(a), __float2bfloat16(b));
    return *(uint32_t*)&t;
}
__device__ __forceinline__ float bres(float a) {
    return a - __bfloat162float(__float2bfloat16(a));
}

// ---------------------------------------------------------------------------
// scratch (device globals; no allocation allowed)
// ---------------------------------------------------------------------------
__device__ __align__(256) float g_tmp[MTOK * DIM];
__device__ __align__(256) float g_x1 [MTOK * DIM];
__device__ __align__(256) float g_ff [MTOK * DIM];

// bf16 hi/lo activations
__device__ __align__(256) __nv_bfloat16 g_xh [MTOK * DIM],  g_xl [MTOK * DIM];
__device__ __align__(256) __nv_bfloat16 g_qh [MTOK * DIM],  g_ql [MTOK * DIM];
__device__ __align__(256) __nv_bfloat16 g_kh [MTOK * DIM],  g_kl [MTOK * DIM];
__device__ __align__(256) __nv_bfloat16 g_vh [MTOK * DIM],  g_vl [MTOK * DIM];
__device__ __align__(256) __nv_bfloat16 g_vth[MTOK * DIM],  g_vtl[MTOK * DIM];  // [bh*64+d][seq]
__device__ __align__(256) __nv_bfloat16 g_ctxh[MTOK * DIM], g_ctxl[MTOK * DIM];
__device__ __align__(256) __nv_bfloat16 g_x1h[MTOK * DIM],  g_x1l[MTOK * DIM];
__device__ __align__(256) __nv_bfloat16 g_hh [MTOK * FFD],  g_hl [MTOK * FFD];
// bf16 hi/lo transposed weights [N][K]
__device__ __align__(256) __nv_bfloat16 g_wqh[DIM * DIM], g_wql[DIM * DIM];
__device__ __align__(256) __nv_bfloat16 g_wkh[DIM * DIM], g_wkl[DIM * DIM];
__device__ __align__(256) __nv_bfloat16 g_wvh[DIM * DIM], g_wvl[DIM * DIM];
__device__ __align__(256) __nv_bfloat16 g_woh[DIM * DIM], g_wol[DIM * DIM];
__device__ __align__(256) __nv_bfloat16 g_w1h[DIM * FFD], g_w1l[DIM * FFD];  // [FFD][DIM]
__device__ __align__(256) __nv_bfloat16 g_w2h[FFD * DIM], g_w2l[FFD * DIM];  // [DIM][FFD]

// ---------------------------------------------------------------------------
// hi/lo split: hi = bf16(x), lo = bf16(x - hi)
// ---------------------------------------------------------------------------
__device__ __forceinline__ void split_hilo(float v, __nv_bfloat16& h, __nv_bfloat16& l) {
    h = __float2bfloat16(v);
    l = __float2bfloat16(v - __bfloat162float(h));
}

__global__ __launch_bounds__(256)
void convert_hilo(const float* __restrict__ in, __nv_bfloat16* __restrict__ oh,
                  __nv_bfloat16* __restrict__ ol, int count)
{
    int i = (blockIdx.x * 256 + threadIdx.x) * 4;
    if (i >= count) return;
    float4 v = *(const float4*)(in + i);
    __nv_bfloat16 h0, l0, h1, l1, h2, l2, h3, l3;
    split_hilo(v.x, h0, l0); split_hilo(v.y, h1, l1);
    split_hilo(v.z, h2, l2); split_hilo(v.w, h3, l3);
    __nv_bfloat162 hA(h0, h1), hB(h2, h3), lA(l0, l1), lB(l2, l3);
    *(uint2*)(oh + i) = make_uint2(*(uint32_t*)&hA, *(uint32_t*)&hB);
    *(uint2*)(ol + i) = make_uint2(*(uint32_t*)&lA, *(uint32_t*)&lB);
}

// transpose + split: in[K][N] fp32 -> oh/ol[N][K] bf16
__global__ __launch_bounds__(256)
void transpose_convert(const float* __restrict__ in, __nv_bfloat16* __restrict__ oh,
                       __nv_bfloat16* __restrict__ ol, int K, int N)
{
    __shared__ float t[32][33];
    const int n0 = blockIdx.x * 32, k0 = blockIdx.y * 32;
    const int tx = threadIdx.x & 31, ty = threadIdx.x >> 5;  // 32 x 8
    #pragma unroll
    for (int j = 0; j < 32; j += 8)
        t[ty + j][tx] = in[(size_t)(k0 + ty + j) * N + n0 + tx];
    __syncthreads();
    #pragma unroll
    for (int j = 0; j < 32; j += 8) {
        float v = t[tx][ty + j];
        int n = n0 + ty + j, k = k0 + tx;
        __nv_bfloat16 h, l;
        split_hilo(v, h, l);
        oh[(size_t)n * K + k] = h;
        ol[(size_t)n * K + k] = l;
    }
}

// transpose V per head: vh[token][DIM] -> vth[(bh*64+d)][seq]
__global__ __launch_bounds__(256)
void transpose_v(const __nv_bfloat16* __restrict__ vh, const __nv_bfloat16* __restrict__ vl,
                 __nv_bfloat16* __restrict__ vth, __nv_bfloat16* __restrict__ vtl)
{
    __shared__ __nv_bfloat16 th[64][72], tl[64][72];
    const int tid = threadIdx.x;
    const int s0 = blockIdx.x * 64, bh = blockIdx.y, b = bh >> 4, h = bh & 15;
    #pragma unroll
    for (int i = 0; i < 2; i++) {
        int c = tid + i * 256; int r = c >> 3, cc = (c & 7) * 8;
        *(uint4*)&th[r][cc] = *(const uint4*)(vh + (size_t)(b * SEQ + s0 + r) * DIM + h * HDm + cc);
        *(uint4*)&tl[r][cc] = *(const uint4*)(vl + (size_t)(b * SEQ + s0 + r) * DIM + h * HDm + cc);
    }
    __syncthreads();
    #pragma unroll
    for (int i = 0; i < 2; i++) {
        int c = tid + i * 256; int d = c >> 3, cc = (c & 7) * 8;
        __nv_bfloat16 a[8], bb[8];
        #pragma unroll
        for (int j = 0; j < 8; j++) { a[j] = th[cc + j][d]; bb[j] = tl[cc + j][d]; }
        *(uint4*)(vth + (size_t)(bh * HDm + d) * SEQ + s0 + cc) = *(uint4*)a;
        *(uint4*)(vtl + (size_t)(bh * HDm + d) * SEQ + s0 + cc) = *(uint4*)bb;
    }
}

// ---------------------------------------------------------------------------
// HMMA bf16x3 GEMM: C[M,N] = A[M,K] @ Bt[N,K]^T + bias (+GELU, +hi/lo emit)
// ---------------------------------------------------------------------------
constexpr int HG_RSTRIDE = 80;                 // bytes per row (32 bf16 + 8 pad)
constexpr int HG_TILE    = 128 * HG_RSTRIDE;   // 10240 B
constexpr int HG_STAGE   = 4 * HG_TILE;        // Ah, Al, Bh, Bl = 40960 B
constexpr int HG_SMEM    = 2 * HG_STAGE;       // 81920 B

__device__ __forceinline__ void hg_load_tile(const __nv_bfloat16* __restrict__ src,
                                             int rowBase, int K, int k0,
                                             uint32_t dstBase, int tid)
{
    #pragma unroll
    for (int i = 0; i < 2; i++) {
        int c = tid + i * 256;
        int row = c >> 2, cc = c & 3;
        uint32_t dst = dstBase + row * HG_RSTRIDE + cc * 16;
        const void* s = src + (size_t)(rowBase + row) * K + k0 + cc * 8;
        cpa16(dst, s);
    }
}

template<bool GELU, bool WRITE_F32, bool EMIT_BF16>
__global__ __launch_bounds__(256, 1)
void hmma_gemm(const __nv_bfloat16* __restrict__ Ah, const __nv_bfloat16* __restrict__ Al,
               const __nv_bfloat16* __restrict__ Bh, const __nv_bfloat16* __restrict__ Bl,
               const float* __restrict__ bias, float* __restrict__ C,
               __nv_bfloat16* __restrict__ Ch, __nv_bfloat16* __restrict__ Cl,
               int M, int N, int K)
{
    extern __shared__ char smem[];
    const uint32_t sb = smem_to_u32(smem);
    const int tid = threadIdx.x, wid = tid >> 5, lane = tid & 31;
    const int warpM = wid >> 2, warpN = wid & 3;
    const int bRow = blockIdx.y * 128, bCol = blockIdx.x * 128;

    float acc[4][4][4];
    #pragma unroll
    for (int m = 0; m < 4; m++)
        #pragma unroll
        for (int n = 0; n < 4; n++)
            #pragma unroll
            for (int e = 0; e < 4; e++) acc[m][n][e] = 0.f;

    {
        uint32_t base = sb;
        hg_load_tile(Ah, bRow, K, 0, base + 0 * HG_TILE, tid);
        hg_load_tile(Al, bRow, K, 0, base + 1 * HG_TILE, tid);
        hg_load_tile(Bh, bCol, K, 0, base + 2 * HG_TILE, tid);
        hg_load_tile(Bl, bCol, K, 0, base + 3 * HG_TILE, tid);
        asm volatile("cp.async.commit_group;");
    }

    const int nk = K >> 5;
    for (int ks = 0; ks < nk; ks++) {
        const int s = ks & 1;
        if (ks + 1 < nk) {
            uint32_t base = sb + (s ^ 1) * HG_STAGE;
            const int k0 = (ks + 1) << 5;
            hg_load_tile(Ah, bRow, K, k0, base + 0 * HG_TILE, tid);
            hg_load_tile(Al, bRow, K, k0, base + 1 * HG_TILE, tid);
            hg_load_tile(Bh, bCol, K, k0, base + 2 * HG_TILE, tid);
            hg_load_tile(Bl, bCol, K, k0, base + 3 * HG_TILE, tid);
            asm volatile("cp.async.commit_group;");
            asm volatile("cp.async.wait_group 1;");
        } else {
            asm volatile("cp.async.wait_group 0;");
        }
        __syncthreads();

        const uint32_t stg = sb + s * HG_STAGE;
        #pragma unroll
        for (int h = 0; h < 2; h++) {
            const int ke = h * 16;
            uint32_t aHi[4][4], aLo[4][4], bHi[4][2], bLo[4][2];
            #pragma unroll
            for (int m = 0; m < 4; m++) {
                uint32_t ra = stg
                    + (warpM * 64 + m * 16 + (lane & 15)) * HG_RSTRIDE
                    + (ke + (lane >> 4) * 8) * 2;
                ldsm_x4(aHi[m], ra);
                ldsm_x4(aLo[m], ra + HG_TILE);
            }
            #pragma unroll
            for (int jp = 0; jp < 2; jp++) {
                uint32_t rb = stg + 2 * HG_TILE
                    + (warpN * 32 + jp * 16 + (lane >> 4) * 8 + (lane & 7)) * HG_RSTRIDE
                    + (ke + ((lane >> 3) & 1) * 8) * 2;
                uint32_t t4[4];
                ldsm_x4(t4, rb);
                bHi[2*jp][0] = t4[0]; bHi[2*jp][1] = t4[1];
                bHi[2*jp+1][0] = t4[2]; bHi[2*jp+1][1] = t4[3];
                ldsm_x4(t4, rb + HG_TILE);
                bLo[2*jp][0] = t4[0]; bLo[2*jp][1] = t4[1];
                bLo[2*jp+1][0] = t4[2]; bLo[2*jp+1][1] = t4[3];
            }
            #pragma unroll
            for (int m = 0; m < 4; m++)
                #pragma unroll
                for (int n = 0; n < 4; n++) {
                    mma16816(acc[m][n], aHi[m], bHi[n]);
                    mma16816(acc[m][n], aHi[m], bLo[n]);
                    mma16816(acc[m][n], aLo[m], bHi[n]);
                }
        }
        __syncthreads();
    }

    #pragma unroll
    for (int m = 0; m < 4; m++) {
        #pragma unroll
        for (int half = 0; half < 2; half++) {
            const size_t row = bRow + warpM * 64 + m * 16 + (lane >> 2) + half * 8;
            #pragma unroll
            for (int n = 0; n < 4; n++) {
                const int col = bCol + warpN * 32 + n * 8 + (lane & 3) * 2;
                float v0 = acc[m][n][half * 2 + 0] + bias[col];
                float v1 = acc[m][n][half * 2 + 1] + bias[col + 1];
                if (GELU) {
                    v0 = 0.5f * v0 * (1.f + erff(v0 * 0.70710678118654752f));
                    v1 = 0.5f * v1 * (1.f + erff(v1 * 0.70710678118654752f));
                }
                if (WRITE_F32) {
                    float2 w; w.x = v0; w.y = v1;
                    *(float2*)(C + row * N + col) = w;
                }
                if (EMIT_BF16) {
                    __nv_bfloat16 h0, l0, h1, l1;
                    split_hilo(v0, h0, l0); split_hilo(v1, h1, l1);
                    __nv_bfloat162 hp(h0, h1), lp(l0, l1);
                    *(uint32_t*)(Ch + row * N + col) = *(uint32_t*)&hp;
                    *(uint32_t*)(Cl + row * N + col) = *(uint32_t*)&lp;
                }
            }
        }
    }
}

// ---------------------------------------------------------------------------
// Flash attention, HMMA bf16x3. 128 queries/block, 8 warps, 64-key tiles.
// Layouts (bf16, 72-element padded rows):
//   Qs [128 q][64 hd], Ks [64 k][64 hd], Vts [64 hd][64 k]
// ---------------------------------------------------------------------------
constexpr int FA_ST   = 72;                     // elements per smem row
constexpr int FA_SQH  = 0;
constexpr int FA_SQL  = FA_SQH + 128 * FA_ST * 2;
constexpr int FA_SKH  = FA_SQL + 128 * FA_ST * 2;
constexpr int FA_SKL  = FA_SKH + 64 * FA_ST * 2;
constexpr int FA_SVH  = FA_SKL + 64 * FA_ST * 2;
constexpr int FA_SVL  = FA_SVH + 64 * FA_ST * 2;
constexpr int FA_SMSK = FA_SVL + 64 * FA_ST * 2;
constexpr int FA_SMEM = FA_SMSK + 64 * 4;

__global__ __launch_bounds__(256)
void flash_attn_bf16(const __nv_bfloat16* __restrict__ Qh, const __nv_bfloat16* __restrict__ Ql,
                     const __nv_bfloat16* __restrict__ Kh, const __nv_bfloat16* __restrict__ Kl,
                     const __nv_bfloat16* __restrict__ Vth, const __nv_bfloat16* __restrict__ Vtl,
                     const int* __restrict__ amask,
                     __nv_bfloat16* __restrict__ Ch, __nv_bfloat16* __restrict__ Cl)
{
    extern __shared__ char smc[];
    const uint32_t sb = smem_to_u32(smc);
    const int tid = threadIdx.x, wid = tid >> 5, lane = tid & 31;
    const int bh = blockIdx.y, b = bh >> 4, h = bh & 15;
    const int q0 = blockIdx.x * 128;

    const __nv_bfloat16* Qhg = Qh + (size_t)(b * SEQ + q0) * DIM + h * HDm;
    const __nv_bfloat16* Qlg = Ql + (size_t)(b * SEQ + q0) * DIM + h * HDm;
    const __nv_bfloat16* Khg = Kh + (size_t)(b * SEQ) * DIM + h * HDm;
    const __nv_bfloat16* Klg = Kl + (size_t)(b * SEQ) * DIM + h * HDm;
    const __nv_bfloat16* Vhg = Vth + (size_t)(bh * HDm) * SEQ;
    const __nv_bfloat16* Vlg = Vtl + (size_t)(bh * HDm) * SEQ;
    int* msk = (int*)(smc + FA_SMSK);

    // load Q (128 rows x 8 chunks of 16B, hi+lo)
    #pragma unroll
    for (int i = 0; i < 4; i++) {
        int c = tid + i * 256; int r = c >> 3, cc = c & 7;
        cpa16(sb + FA_SQH + r * (FA_ST * 2) + cc * 16, Qhg + (size_t)r * DIM + cc * 8);
        cpa16(sb + FA_SQL + r * (FA_ST * 2) + cc * 16, Qlg + (size_t)r * DIM + cc * 8);
    }
    asm volatile("cp.async.commit_group;");

    float m0 = -INFINITY, m1 = -INFINITY, l0 = 0.f, l1 = 0.f;
    float o[8][4];
    #pragma unroll
    for (int nt = 0; nt < 8; nt++)
        #pragma unroll
        for (int e = 0; e < 4; e++) o[nt][e] = 0.f;

    const int kb = 2 * (lane & 3);

    for (int k0 = 0; k0 < SEQ; k0 += 64) {
        #pragma unroll
        for (int i = 0; i < 2; i++) {
            int c = tid + i * 256; int r = c >> 3, cc = c & 7;
            cpa16(sb + FA_SKH + r * (FA_ST * 2) + cc * 16, Khg + (size_t)(k0 + r) * DIM + cc * 8);
            cpa16(sb + FA_SKL + r * (FA_ST * 2) + cc * 16, Klg + (size_t)(k0 + r) * DIM + cc * 8);
            cpa16(sb + FA_SVH + r * (FA_ST * 2) + cc * 16, Vhg + (size_t)r * SEQ + k0 + cc * 8);
            cpa16(sb + FA_SVL + r * (FA_ST * 2) + cc * 16, Vlg + (size_t)r * SEQ + k0 + cc * 8);
        }
        if (tid < 64) msk[tid] = amask[b * SEQ + k0 + tid];
        asm volatile("cp.async.commit_group;");
        asm volatile("cp.async.wait_group 0;");
        __syncthreads();

        // ---- S = Q K^T (bf16x3) ----
        float sacc[8][4];
        #pragma unroll
        for (int nt = 0; nt < 8; nt++)
            #pragma unroll
            for (int e = 0; e < 4; e++) sacc[nt][e] = 0.f;

        #pragma unroll
        for (int kk = 0; kk < 4; kk++) {
            uint32_t aH[4], aL[4];
            uint32_t ra = sb + FA_SQH
                + (wid * 16 + (lane & 15)) * (FA_ST * 2)
                + (kk * 16 + (lane >> 4) * 8) * 2;
            ldsm_x4(aH, ra);
            ldsm_x4(aL, ra + (FA_SQL - FA_SQH));
            #pragma unroll
            for (int jp = 0; jp < 4; jp++) {
                uint32_t rb = sb + FA_SKH
                    + (jp * 16 + (lane >> 4) * 8 + (lane & 7)) * (FA_ST * 2)
                    + (kk * 16 + ((lane >> 3) & 1) * 8) * 2;
                uint32_t bH[4], bL[4];
                ldsm_x4(bH, rb);
                ldsm_x4(bL, rb + (FA_SKL - FA_SKH));
                mma16816(sacc[2*jp],   aH, &bH[0]);
                mma16816(sacc[2*jp],   aH, &bL[0]);
                mma16816(sacc[2*jp],   aL, &bH[0]);
                mma16816(sacc[2*jp+1], aH, &bH[2]);
                mma16816(sacc[2*jp+1], aH, &bL[2]);
                mma16816(sacc[2*jp+1], aL, &bH[2]);
            }
        }

        // ---- scale + mask ----
        #pragma unroll
        for (int nt = 0; nt < 8; nt++) {
            bool z0 = msk[nt * 8 + kb] == 0, z1 = msk[nt * 8 + kb + 1] == 0;
            sacc[nt][0] = z0 ? -1e9f : sacc[nt][0] * 0.125f;
            sacc[nt][1] = z1 ? -1e9f : sacc[nt][1] * 0.125f;
            sacc[nt][2] = z0 ? -1e9f : sacc[nt][2] * 0.125f;
            sacc[nt][3] = z1 ? -1e9f : sacc[nt][3] * 0.125f;
        }

        // ---- online softmax (rows r0 = lane>>2, r1 = r0+8) ----
        float mx0 = -INFINITY, mx1 = -INFINITY;
        #pragma unroll
        for (int nt = 0; nt < 8; nt++) {
            mx0 = fmaxf(mx0, fmaxf(sacc[nt][0], sacc[nt][1]));
            mx1 = fmaxf(mx1, fmaxf(sacc[nt][2], sacc[nt][3]));
        }
        mx0 = fmaxf(mx0, __shfl_xor_sync(0xffffffffu, mx0, 1));
        mx0 = fmaxf(mx0, __shfl_xor_sync(0xffffffffu, mx0, 2));
        mx1 = fmaxf(mx1, __shfl_xor_sync(0xffffffffu, mx1, 1));
        mx1 = fmaxf(mx1, __shfl_xor_sync(0xffffffffu, mx1, 2));
        float mn0 = fmaxf(m0, mx0), mn1 = fmaxf(m1, mx1);
        float f0 = __expf(m0 - mn0), f1 = __expf(m1 - mn1);
        float s0 = 0.f, s1 = 0.f;
        #pragma unroll
        for (int nt = 0; nt < 8; nt++) {
            float p0 = __expf(sacc[nt][0] - mn0);
            float p1 = __expf(sacc[nt][1] - mn0);
            float p2 = __expf(sacc[nt][2] - mn1);
            float p3 = __expf(sacc[nt][3] - mn1);
            sacc[nt][0] = p0; sacc[nt][1] = p1; sacc[nt][2] = p2; sacc[nt][3] = p3;
            s0 += p0 + p1; s1 += p2 + p3;
        }
        s0 += __shfl_xor_sync(0xffffffffu, s0, 1);
        s0 += __shfl_xor_sync(0xffffffffu, s0, 2);
        s1 += __shfl_xor_sync(0xffffffffu, s1, 1);
        s1 += __shfl_xor_sync(0xffffffffu, s1, 2);
        l0 = l0 * f0 + s0; l1 = l1 * f1 + s1;
        m0 = mn0; m1 = mn1;
        #pragma unroll
        for (int nt = 0; nt < 8; nt++) {
            o[nt][0] *= f0; o[nt][1] *= f0;
            o[nt][2] *= f1; o[nt][3] *= f1;
        }

        // ---- O += P V  (bf16x3; P fragments built from S accumulators) ----
        #pragma unroll
        for (int j = 0; j < 4; j++) {
            uint32_t pH[4], pL[4];
            pH[0] = pk2(sacc[2*j][0],   sacc[2*j][1]);
            pH[1] = pk2(sacc[2*j][2],   sacc[2*j][3]);
            pH[2] = pk2(sacc[2*j+1][0], sacc[2*j+1][1]);
            pH[3] = pk2(sacc[2*j+1][2], sacc[2*j+1][3]);
            pL[0] = pk2(bres(sacc[2*j][0]),   bres(sacc[2*j][1]));
            pL[1] = pk2(bres(sacc[2*j][2]),   bres(sacc[2*j][3]));
            pL[2] = pk2(bres(sacc[2*j+1][0]), bres(sacc[2*j+1][1]));
            pL[3] = pk2(bres(sacc[2*j+1][2]), bres(sacc[2*j+1][3]));
            #pragma unroll
            for (int t = 0; t < 4; t++) {
                uint32_t rb = sb + FA_SVH
                    + (t * 16 + (lane >> 4) * 8 + (lane & 7)) * (FA_ST * 2)
                    + (j * 16 + ((lane >> 3) & 1) * 8) * 2;
                uint32_t bH[4], bL[4];
                ldsm_x4(bH, rb);
                ldsm_x4(bL, rb + (FA_SVL - FA_SVH));
                mma16816(o[2*t],   pH, &bH[0]);
                mma16816(o[2*t],   pH, &bL[0]);
                mma16816(o[2*t],   pL, &bH[0]);
                mma16816(o[2*t+1], pH, &bH[2]);
                mma16816(o[2*t+1], pH, &bL[2]);
                mma16816(o[2*t+1], pL, &bH[2]);
            }
        }
        __syncthreads();
    }

    // ---- epilogue: ctx = O / l, hi/lo bf16 ----
    const float i0 = 1.f / l0, i1 = 1.f / l1;
    const size_t r0 = (size_t)b * SEQ + q0 + wid * 16 + (lane >> 2);
    const size_t r1 = r0 + 8;
    #pragma unroll
    for (int nt = 0; nt < 8; nt++) {
        const int col = h * HDm + nt * 8 + kb;
        float v0 = o[nt][0] * i0, v1 = o[nt][1] * i0;
        float v2 = o[nt][2] * i1, v3 = o[nt][3] * i1;
        *(uint32_t*)(Ch + r0 * DIM + col) = pk2(v0, v1);
        *(uint32_t*)(Cl + r0 * DIM + col) = pk2(bres(v0), bres(v1));
        *(uint32_t*)(Ch + r1 * DIM + col) = pk2(v2, v3);
        *(uint32_t*)(Cl + r1 * DIM + col) = pk2(bres(v2), bres(v3));
    }
}

// ---------------- residual add + LayerNorm (+optional hi/lo emit) ----------
template<bool EMIT>
__global__ __launch_bounds__(256)
void ln_residual(const float* __restrict__ A, const float* __restrict__ Bv,
                 const float* __restrict__ g, const float* __restrict__ be,
                 float* __restrict__ out, __nv_bfloat16* __restrict__ oh,
                 __nv_bfloat16* __restrict__ ol, float eps)
{
    const int row = blockIdx.x;
    const int tid = threadIdx.x;
    const float4 va = ((const float4*)(A  + (size_t)row * DIM))[tid];
    const float4 vb = ((const float4*)(Bv + (size_t)row * DIM))[tid];
    float4 v;
    v.x = va.x + vb.x; v.y = va.y + vb.y;
    v.z = va.z + vb.z; v.w = va.w + vb.w;

    float sum = v.x + v.y + v.z + v.w;
    float sq  = v.x * v.x + v.y * v.y + v.z * v.z + v.w * v.w;
    #pragma unroll
    for (int mm = 16; mm; mm >>= 1) {
        sum += __shfl_xor_sync(0xffffffffu, sum, mm);
        sq  += __shfl_xor_sync(0xffffffffu, sq,  mm);
    }
    __shared__ float ssum[8], ssq[8], stats[2];
    const int wid = tid >> 5, lane = tid & 31;
    if (lane == 0) { ssum[wid] = sum; ssq[wid] = sq; }
    __syncthreads();
    if (tid == 0) {
        float S = 0.f, Qq = 0.f;
        #pragma unroll
        for (int i = 0; i < 8; i++) { S += ssum[i]; Qq += ssq[i]; }
        float mean = S * (1.f / DIM);
        float var  = fmaxf(Qq * (1.f / DIM) - mean * mean, 0.f);
        stats[0] = mean;
        stats[1] = rsqrtf(var + eps);
    }
    __syncthreads();
    const float mean = stats[0], rstd = stats[1];
    const float4 gg = ((const float4*)g)[tid];
    const float4 bb = ((const float4*)be)[tid];
    float4 r;
    r.x = (v.x - mean) * rstd * gg.x + bb.x;
    r.y = (v.y - mean) * rstd * gg.y + bb.y;
    r.z = (v.z - mean) * rstd * gg.z + bb.z;
    r.w = (v.w - mean) * rstd * gg.w + bb.w;
    ((float4*)(out + (size_t)row * DIM))[tid] = r;
    if (EMIT) {
        __nv_bfloat16 h0,l0,h1,l1,h2,l2,h3,l3;
        split_hilo(r.x,h0,l0); split_hilo(r.y,h1,l1);
        split_hilo(r.z,h2,l2); split_hilo(r.w,h3,l3);
        __nv_bfloat162 hA(h0,h1), hB(h2,h3), lA(l0,l1), lB(l2,l3);
        ((uint2*)(oh + (size_t)row * DIM))[tid] = make_uint2(*(uint32_t*)&hA, *(uint32_t*)&hB);
        ((uint2*)(ol + (size_t)row * DIM))[tid] = make_uint2(*(uint32_t*)&lA, *(uint32_t*)&lB);
    }
}

// ---------------- launch ----------------------------------------------------
extern "C" void kernel_launch(void* const* d_in, const int* in_sizes, int n_in,
                              void* d_out, int out_size)
{
    const float* x     = (const float*)d_in[0];
    const int*   amask = (const int*  )d_in[1];
    const float* wq = (const float*)d_in[2];
    const float* bq = (const float*)d_in[3];
    const float* wk = (const float*)d_in[4];
    const float* bk = (const float*)d_in[5];
    const float* wv = (const float*)d_in[6];
    const float* bv = (const float*)d_in[7];
    const float* wo = (const float*)d_in[8];
    const float* bo = (const float*)d_in[9];
    const float* ln1_g = (const float*)d_in[10];
    const float* ln1_b = (const float*)d_in[11];
    const float* w1 = (const float*)d_in[12];
    const float* b1 = (const float*)d_in[13];
    const float* w2 = (const float*)d_in[14];
    const float* b2 = (const float*)d_in[15];
    const float* lnf_g = (const float*)d_in[16];
    const float* lnf_b = (const float*)d_in[17];
    const float* ln2_g = (const float*)d_in[18];
    const float* ln2_b = (const float*)d_in[19];
    float* out = (float*)d_out;

    float *tmp, *x1, *ff;
    cudaGetSymbolAddress((void**)&tmp, g_tmp);
    cudaGetSymbolAddress((void**)&x1,  g_x1);
    cudaGetSymbolAddress((void**)&ff,  g_ff);

    __nv_bfloat16 *xh,*xl,*qh,*ql,*kh,*kl,*vh,*vl,*vth,*vtl,*ctxh,*ctxl,*x1h,*x1l,*hh,*hl;
    __nv_bfloat16 *wqh,*wql,*wkh,*wkl,*wvh,*wvl,*woh,*wol,*w1h,*w1l,*w2h,*w2l;
    cudaGetSymbolAddress((void**)&xh,  g_xh);   cudaGetSymbolAddress((void**)&xl,  g_xl);
    cudaGetSymbolAddress((void**)&qh,  g_qh);   cudaGetSymbolAddress((void**)&ql,  g_ql);
    cudaGetSymbolAddress((void**)&kh,  g_kh);   cudaGetSymbolAddress((void**)&kl,  g_kl);
    cudaGetSymbolAddress((void**)&vh,  g_vh);   cudaGetSymbolAddress((void**)&vl,  g_vl);
    cudaGetSymbolAddress((void**)&vth, g_vth);  cudaGetSymbolAddress((void**)&vtl, g_vtl);
    cudaGetSymbolAddress((void**)&ctxh,g_ctxh); cudaGetSymbolAddress((void**)&ctxl,g_ctxl);
    cudaGetSymbolAddress((void**)&x1h, g_x1h);  cudaGetSymbolAddress((void**)&x1l, g_x1l);
    cudaGetSymbolAddress((void**)&hh,  g_hh);   cudaGetSymbolAddress((void**)&hl,  g_hl);
    cudaGetSymbolAddress((void**)&wqh, g_wqh);  cudaGetSymbolAddress((void**)&wql, g_wql);
    cudaGetSymbolAddress((void**)&wkh, g_wkh);  cudaGetSymbolAddress((void**)&wkl, g_wkl);
    cudaGetSymbolAddress((void**)&wvh, g_wvh);  cudaGetSymbolAddress((void**)&wvl, g_wvl);
    cudaGetSymbolAddress((void**)&woh, g_woh);  cudaGetSymbolAddress((void**)&wol, g_wol);
    cudaGetSymbolAddress((void**)&w1h, g_w1h);  cudaGetSymbolAddress((void**)&w1l, g_w1l);
    cudaGetSymbolAddress((void**)&w2h, g_w2h);  cudaGetSymbolAddress((void**)&w2l, g_w2l);

    cudaFuncSetAttribute(flash_attn_bf16,
                         cudaFuncAttributeMaxDynamicSharedMemorySize, FA_SMEM);
    cudaFuncSetAttribute(hmma_gemm<false, true, false>,
                         cudaFuncAttributeMaxDynamicSharedMemorySize, HG_SMEM);
    cudaFuncSetAttribute(hmma_gemm<false, false, true>,
                         cudaFuncAttributeMaxDynamicSharedMemorySize, HG_SMEM);
    cudaFuncSetAttribute(hmma_gemm<true, false, true>,
                         cudaFuncAttributeMaxDynamicSharedMemorySize, HG_SMEM);

    const dim3 blk(256);

    // weight transpose + hi/lo split: in[K][N] -> out[N][K]
    transpose_convert<<<dim3(DIM/32, DIM/32), blk>>>(wq, wqh, wql, DIM, DIM);
    transpose_convert<<<dim3(DIM/32, DIM/32), blk>>>(wk, wkh, wkl, DIM, DIM);
    transpose_convert<<<dim3(DIM/32, DIM/32), blk>>>(wv, wvh, wvl, DIM, DIM);
    transpose_convert<<<dim3(DIM/32, DIM/32), blk>>>(wo, woh, wol, DIM, DIM);
    transpose_convert<<<dim3(FFD/32, DIM/32), blk>>>(w1, w1h, w1l, DIM, FFD);
    transpose_convert<<<dim3(DIM/32, FFD/32), blk>>>(w2, w2h, w2l, FFD, DIM);

    // x -> hi/lo
    convert_hilo<<<(MTOK * DIM) / 1024, blk>>>(x, xh, xl, MTOK * DIM);

    // QKV projections -> bf16 hi/lo directly
    hmma_gemm<false,false,true><<<dim3(DIM/128, MTOK/128), blk, HG_SMEM>>>(
        xh, xl, wqh, wql, bq, nullptr, qh, ql, MTOK, DIM, DIM);
    hmma_gemm<false,false,true><<<dim3(DIM/128, MTOK/128), blk, HG_SMEM>>>(
        xh, xl, wkh, wkl, bk, nullptr, kh, kl, MTOK, DIM, DIM);
    hmma_gemm<false,false,true><<<dim3(DIM/128, MTOK/128), blk, HG_SMEM>>>(
        xh, xl, wvh, wvl, bv, nullptr, vh, vl, MTOK, DIM, DIM);

    // V transpose per head
    transpose_v<<<dim3(SEQ/64, BATCH*NH), blk>>>(vh, vl, vth, vtl);

    // attention (HMMA bf16x3) -> ctx hi/lo
    flash_attn_bf16<<<dim3(SEQ/128, BATCH*NH), blk, FA_SMEM>>>(
        qh, ql, kh, kl, vth, vtl, amask, ctxh, ctxl);

    // O projection + residual LN1
    hmma_gemm<false,true,false><<<dim3(DIM/128, MTOK/128), blk, HG_SMEM>>>(
        ctxh, ctxl, woh, wol, bo, tmp, nullptr, nullptr, MTOK, DIM, DIM);
    ln_residual<true><<<MTOK, blk>>>(x, tmp, ln1_g, ln1_b, x1, x1h, x1l, 1e-5f);

    // FFN
    hmma_gemm<true,false,true><<<dim3(FFD/128, MTOK/128), blk, HG_SMEM>>>(
        x1h, x1l, w1h, w1l, b1, nullptr, hh, hl, MTOK, FFD, DIM);
    hmma_gemm<false,true,false><<<dim3(DIM/128, MTOK/128), blk, HG_SMEM>>>(
        hh, hl, w2h, w2l, b2, tmp, nullptr, nullptr, MTOK, DIM, FFD);
    ln_residual<false><<<MTOK, blk>>>(tmp, x1, lnf_g, lnf_b, ff, nullptr, nullptr, 1e-12f);

    // final LN
    ln_residual<false><<<MTOK, blk>>>(x1, ff, ln2_g, ln2_b, out, nullptr, nullptr, 1e-5f);
}

// round 5
// speedup vs baseline: 2.5235x; 1.0372x over previous
#include <cuda_runtime.h>
#include <cuda_bf16.h>
#include <math.h>
#include <stdint.h>

// Problem constants
constexpr int DIM  = 1024;
constexpr int NH   = 16;
constexpr int HDm  = 64;
constexpr int FFD  = 4096;
constexpr int BATCH= 2;
constexpr int SEQ  = 2048;
constexpr int MTOK = BATCH * SEQ;   // 4096

// ---------------------------------------------------------------------------
// helpers
// ---------------------------------------------------------------------------
__device__ __forceinline__ uint32_t smem_to_u32(const void* p) {
    uint32_t a;
    asm("{ .reg .u64 t; cvta.to.shared.u64 t, %1; cvt.u32.u64 %0, t; }"
        : "=r"(a) : "l"(p));
    return a;
}

__device__ __forceinline__ void ldsm_x4(uint32_t* r, uint32_t addr) {
    asm volatile("ldmatrix.sync.aligned.m8n8.x4.shared.b16 {%0,%1,%2,%3}, [%4];"
                 : "=r"(r[0]), "=r"(r[1]), "=r"(r[2]), "=r"(r[3]) : "r"(addr));
}

__device__ __forceinline__ void mma16816(float* c, const uint32_t* a, const uint32_t* b) {
    asm volatile(
        "mma.sync.aligned.m16n8k16.row.col.f32.bf16.bf16.f32 "
        "{%0,%1,%2,%3}, {%4,%5,%6,%7}, {%8,%9}, {%0,%1,%2,%3};"
        : "+f"(c[0]), "+f"(c[1]), "+f"(c[2]), "+f"(c[3])
        : "r"(a[0]), "r"(a[1]), "r"(a[2]), "r"(a[3]), "r"(b[0]), "r"(b[1]));
}

__device__ __forceinline__ void cpa16(uint32_t dst, const void* src) {
    asm volatile("cp.async.ca.shared.global [%0], [%1], 16;" :: "r"(dst), "l"(src));
}

__device__ __forceinline__ uint32_t pk2(float a, float b) {
    __nv_bfloat162 t(__float2bfloat16(a), __float2bfloat16(b));
    return *(uint32_t*)&t;
}
__device__ __forceinline__ float bres(float a) {
    return a - __bfloat162float(__float2bfloat16(a));
}

// ---------------------------------------------------------------------------
// scratch (device globals; no allocation allowed)
// ---------------------------------------------------------------------------
__device__ __align__(256) float g_tmp[MTOK * DIM];
__device__ __align__(256) float g_x1 [MTOK * DIM];
__device__ __align__(256) float g_ff [MTOK * DIM];

__device__ __align__(256) __nv_bfloat16 g_xh [MTOK * DIM],  g_xl [MTOK * DIM];
__device__ __align__(256) __nv_bfloat16 g_qh [MTOK * DIM],  g_ql [MTOK * DIM];
__device__ __align__(256) __nv_bfloat16 g_kh [MTOK * DIM],  g_kl [MTOK * DIM];
__device__ __align__(256) __nv_bfloat16 g_vh [MTOK * DIM],  g_vl [MTOK * DIM];
__device__ __align__(256) __nv_bfloat16 g_vth[MTOK * DIM],  g_vtl[MTOK * DIM];
__device__ __align__(256) __nv_bfloat16 g_ctxh[MTOK * DIM], g_ctxl[MTOK * DIM];
__device__ __align__(256) __nv_bfloat16 g_x1h[MTOK * DIM],  g_x1l[MTOK * DIM];
__device__ __align__(256) __nv_bfloat16 g_hh [MTOK * FFD],  g_hl [MTOK * FFD];
__device__ __align__(256) __nv_bfloat16 g_wqh[DIM * DIM], g_wql[DIM * DIM];
__device__ __align__(256) __nv_bfloat16 g_wkh[DIM * DIM], g_wkl[DIM * DIM];
__device__ __align__(256) __nv_bfloat16 g_wvh[DIM * DIM], g_wvl[DIM * DIM];
__device__ __align__(256) __nv_bfloat16 g_woh[DIM * DIM], g_wol[DIM * DIM];
__device__ __align__(256) __nv_bfloat16 g_w1h[DIM * FFD], g_w1l[DIM * FFD];
__device__ __align__(256) __nv_bfloat16 g_w2h[FFD * DIM], g_w2l[FFD * DIM];

// ---------------------------------------------------------------------------
// hi/lo split: hi = bf16(x), lo = bf16(x - hi)
// ---------------------------------------------------------------------------
__device__ __forceinline__ void split_hilo(float v, __nv_bfloat16& h, __nv_bfloat16& l) {
    h = __float2bfloat16(v);
    l = __float2bfloat16(v - __bfloat162float(h));
}

__global__ __launch_bounds__(256)
void convert_hilo(const float* __restrict__ in, __nv_bfloat16* __restrict__ oh,
                  __nv_bfloat16* __restrict__ ol, int count)
{
    int i = (blockIdx.x * 256 + threadIdx.x) * 4;
    if (i >= count) return;
    float4 v = *(const float4*)(in + i);
    __nv_bfloat16 h0, l0, h1, l1, h2, l2, h3, l3;
    split_hilo(v.x, h0, l0); split_hilo(v.y, h1, l1);
    split_hilo(v.z, h2, l2); split_hilo(v.w, h3, l3);
    __nv_bfloat162 hA(h0, h1), hB(h2, h3), lA(l0, l1), lB(l2, l3);
    *(uint2*)(oh + i) = make_uint2(*(uint32_t*)&hA, *(uint32_t*)&hB);
    *(uint2*)(ol + i) = make_uint2(*(uint32_t*)&lA, *(uint32_t*)&lB);
}

__global__ __launch_bounds__(256)
void transpose_convert(const float* __restrict__ in, __nv_bfloat16* __restrict__ oh,
                       __nv_bfloat16* __restrict__ ol, int K, int N)
{
    __shared__ float t[32][33];
    const int n0 = blockIdx.x * 32, k0 = blockIdx.y * 32;
    const int tx = threadIdx.x & 31, ty = threadIdx.x >> 5;
    #pragma unroll
    for (int j = 0; j < 32; j += 8)
        t[ty + j][tx] = in[(size_t)(k0 + ty + j) * N + n0 + tx];
    __syncthreads();
    #pragma unroll
    for (int j = 0; j < 32; j += 8) {
        float v = t[tx][ty + j];
        int n = n0 + ty + j, k = k0 + tx;
        __nv_bfloat16 h, l;
        split_hilo(v, h, l);
        oh[(size_t)n * K + k] = h;
        ol[(size_t)n * K + k] = l;
    }
}

__global__ __launch_bounds__(256)
void transpose_v(const __nv_bfloat16* __restrict__ vh, const __nv_bfloat16* __restrict__ vl,
                 __nv_bfloat16* __restrict__ vth, __nv_bfloat16* __restrict__ vtl)
{
    __shared__ __nv_bfloat16 th[64][72], tl[64][72];
    const int tid = threadIdx.x;
    const int s0 = blockIdx.x * 64, bh = blockIdx.y, b = bh >> 4, h = bh & 15;
    #pragma unroll
    for (int i = 0; i < 2; i++) {
        int c = tid + i * 256; int r = c >> 3, cc = (c & 7) * 8;
        *(uint4*)&th[r][cc] = *(const uint4*)(vh + (size_t)(b * SEQ + s0 + r) * DIM + h * HDm + cc);
        *(uint4*)&tl[r][cc] = *(const uint4*)(vl + (size_t)(b * SEQ + s0 + r) * DIM + h * HDm + cc);
    }
    __syncthreads();
    #pragma unroll
    for (int i = 0; i < 2; i++) {
        int c = tid + i * 256; int d = c >> 3, cc = (c & 7) * 8;
        __nv_bfloat16 a[8], bb[8];
        #pragma unroll
        for (int j = 0; j < 8; j++) { a[j] = th[cc + j][d]; bb[j] = tl[cc + j][d]; }
        *(uint4*)(vth + (size_t)(bh * HDm + d) * SEQ + s0 + cc) = *(uint4*)a;
        *(uint4*)(vtl + (size_t)(bh * HDm + d) * SEQ + s0 + cc) = *(uint4*)bb;
    }
}

// ---------------------------------------------------------------------------
// HMMA bf16x3 GEMM, 3-stage cp.async pipeline, one sync per chunk.
// ---------------------------------------------------------------------------
constexpr int HG_RSTRIDE = 80;
constexpr int HG_TILE    = 128 * HG_RSTRIDE;   // 10240 B
constexpr int HG_STAGE   = 4 * HG_TILE;        // 40960 B
constexpr int HG_SMEM    = 3 * HG_STAGE;       // 122880 B

__device__ __forceinline__ void hg_load_tile(const __nv_bfloat16* __restrict__ src,
                                             int rowBase, int K, int k0,
                                             uint32_t dstBase, int tid)
{
    #pragma unroll
    for (int i = 0; i < 2; i++) {
        int c = tid + i * 256;
        int row = c >> 2, cc = c & 3;
        uint32_t dst = dstBase + row * HG_RSTRIDE + cc * 16;
        const void* s = src + (size_t)(rowBase + row) * K + k0 + cc * 8;
        cpa16(dst, s);
    }
}

__device__ __forceinline__ void hg_load_stage(
    const __nv_bfloat16* Ah, const __nv_bfloat16* Al,
    const __nv_bfloat16* Bh, const __nv_bfloat16* Bl,
    int bRow, int bCol, int K, int k0, uint32_t base, int tid)
{
    hg_load_tile(Ah, bRow, K, k0, base + 0 * HG_TILE, tid);
    hg_load_tile(Al, bRow, K, k0, base + 1 * HG_TILE, tid);
    hg_load_tile(Bh, bCol, K, k0, base + 2 * HG_TILE, tid);
    hg_load_tile(Bl, bCol, K, k0, base + 3 * HG_TILE, tid);
    asm volatile("cp.async.commit_group;");
}

template<bool GELU, bool WRITE_F32, bool EMIT_BF16>
__global__ __launch_bounds__(256, 1)
void hmma_gemm(const __nv_bfloat16* __restrict__ Ah, const __nv_bfloat16* __restrict__ Al,
               const __nv_bfloat16* __restrict__ Bh, const __nv_bfloat16* __restrict__ Bl,
               const float* __restrict__ bias, float* __restrict__ C,
               __nv_bfloat16* __restrict__ Ch, __nv_bfloat16* __restrict__ Cl,
               int M, int N, int K)
{
    extern __shared__ char smem[];
    const uint32_t sb = smem_to_u32(smem);
    const int tid = threadIdx.x, wid = tid >> 5, lane = tid & 31;
    const int warpM = wid >> 2, warpN = wid & 3;
    const int bRow = blockIdx.y * 128, bCol = blockIdx.x * 128;

    float acc[4][4][4];
    #pragma unroll
    for (int m = 0; m < 4; m++)
        #pragma unroll
        for (int n = 0; n < 4; n++)
            #pragma unroll
            for (int e = 0; e < 4; e++) acc[m][n][e] = 0.f;

    // prologue: stages 0, 1
    hg_load_stage(Ah, Al, Bh, Bl, bRow, bCol, K, 0,  sb + 0 * HG_STAGE, tid);
    hg_load_stage(Ah, Al, Bh, Bl, bRow, bCol, K, 32, sb + 1 * HG_STAGE, tid);

    const int nk = K >> 5;
    for (int ks = 0; ks < nk; ks++) {
        if (ks == nk - 1) { asm volatile("cp.async.wait_group 0;"); }
        else              { asm volatile("cp.async.wait_group 1;"); }
        __syncthreads();

        if (ks + 2 < nk) {
            int st = ks + 2; st -= (st >= 3) ? ((st / 3) * 3) : 0;  // (ks+2)%3
            hg_load_stage(Ah, Al, Bh, Bl, bRow, bCol, K, (ks + 2) << 5,
                          sb + (uint32_t)((ks + 2) % 3) * HG_STAGE, tid);
        }

        const uint32_t stg = sb + (uint32_t)(ks % 3) * HG_STAGE;
        #pragma unroll
        for (int h = 0; h < 2; h++) {
            const int ke = h * 16;
            uint32_t aHi[4][4], aLo[4][4], bHi[4][2], bLo[4][2];
            #pragma unroll
            for (int m = 0; m < 4; m++) {
                uint32_t ra = stg
                    + (warpM * 64 + m * 16 + (lane & 15)) * HG_RSTRIDE
                    + (ke + (lane >> 4) * 8) * 2;
                ldsm_x4(aHi[m], ra);
                ldsm_x4(aLo[m], ra + HG_TILE);
            }
            #pragma unroll
            for (int jp = 0; jp < 2; jp++) {
                uint32_t rb = stg + 2 * HG_TILE
                    + (warpN * 32 + jp * 16 + (lane >> 4) * 8 + (lane & 7)) * HG_RSTRIDE
                    + (ke + ((lane >> 3) & 1) * 8) * 2;
                uint32_t t4[4];
                ldsm_x4(t4, rb);
                bHi[2*jp][0] = t4[0]; bHi[2*jp][1] = t4[1];
                bHi[2*jp+1][0] = t4[2]; bHi[2*jp+1][1] = t4[3];
                ldsm_x4(t4, rb + HG_TILE);
                bLo[2*jp][0] = t4[0]; bLo[2*jp][1] = t4[1];
                bLo[2*jp+1][0] = t4[2]; bLo[2*jp+1][1] = t4[3];
            }
            #pragma unroll
            for (int m = 0; m < 4; m++)
                #pragma unroll
                for (int n = 0; n < 4; n++) {
                    mma16816(acc[m][n], aHi[m], bHi[n]);
                    mma16816(acc[m][n], aHi[m], bLo[n]);
                    mma16816(acc[m][n], aLo[m], bHi[n]);
                }
        }
        // no trailing sync: next iteration's barrier bounds warp skew, and the
        // prefetch target stage was last read one full iteration ago.
    }

    #pragma unroll
    for (int m = 0; m < 4; m++) {
        #pragma unroll
        for (int half = 0; half < 2; half++) {
            const size_t row = bRow + warpM * 64 + m * 16 + (lane >> 2) + half * 8;
            #pragma unroll
            for (int n = 0; n < 4; n++) {
                const int col = bCol + warpN * 32 + n * 8 + (lane & 3) * 2;
                float v0 = acc[m][n][half * 2 + 0] + bias[col];
                float v1 = acc[m][n][half * 2 + 1] + bias[col + 1];
                if (GELU) {
                    v0 = 0.5f * v0 * (1.f + erff(v0 * 0.70710678118654752f));
                    v1 = 0.5f * v1 * (1.f + erff(v1 * 0.70710678118654752f));
                }
                if (WRITE_F32) {
                    float2 w; w.x = v0; w.y = v1;
                    *(float2*)(C + row * N + col) = w;
                }
                if (EMIT_BF16) {
                    __nv_bfloat16 h0, l0, h1, l1;
                    split_hilo(v0, h0, l0); split_hilo(v1, h1, l1);
                    __nv_bfloat162 hp(h0, h1), lp(l0, l1);
                    *(uint32_t*)(Ch + row * N + col) = *(uint32_t*)&hp;
                    *(uint32_t*)(Cl + row * N + col) = *(uint32_t*)&lp;
                }
            }
        }
    }
}

// ---------------------------------------------------------------------------
// Flash attention, HMMA bf16x3, double-buffered K/V stages.
// Q [128q][64hd] hi/lo static; K/V per-stage: KH,KL (64k x 64hd), VH,VL (64hd x 64k)
// ---------------------------------------------------------------------------
constexpr int FA_ST    = 72;
constexpr int FA_ROW   = FA_ST * 2;             // 144 B
constexpr int FA_QH    = 0;
constexpr int FA_QL    = FA_QH + 128 * FA_ROW;  // 18432
constexpr int FA_KV    = FA_QL + 128 * FA_ROW;  // 36864
constexpr int FA_KVT   = 64 * FA_ROW;           // 9216 per tile
constexpr int FA_KVSTG = 4 * FA_KVT;            // 36864 per stage
constexpr int FA_MSK   = FA_KV + 2 * FA_KVSTG;  // 110592
constexpr int FA_SMEM  = FA_MSK + 2 * 64 * 4;   // 111104

__global__ __launch_bounds__(256, 2)
void flash_attn_bf16(const __nv_bfloat16* __restrict__ Qh, const __nv_bfloat16* __restrict__ Ql,
                     const __nv_bfloat16* __restrict__ Kh, const __nv_bfloat16* __restrict__ Kl,
                     const __nv_bfloat16* __restrict__ Vth, const __nv_bfloat16* __restrict__ Vtl,
                     const int* __restrict__ amask,
                     __nv_bfloat16* __restrict__ Ch, __nv_bfloat16* __restrict__ Cl)
{
    extern __shared__ char smc[];
    const uint32_t sb = smem_to_u32(smc);
    const int tid = threadIdx.x, wid = tid >> 5, lane = tid & 31;
    const int bh = blockIdx.y, b = bh >> 4, h = bh & 15;
    const int q0 = blockIdx.x * 128;

    const __nv_bfloat16* Qhg = Qh + (size_t)(b * SEQ + q0) * DIM + h * HDm;
    const __nv_bfloat16* Qlg = Ql + (size_t)(b * SEQ + q0) * DIM + h * HDm;
    const __nv_bfloat16* Khg = Kh + (size_t)(b * SEQ) * DIM + h * HDm;
    const __nv_bfloat16* Klg = Kl + (size_t)(b * SEQ) * DIM + h * HDm;
    const __nv_bfloat16* Vhg = Vth + (size_t)(bh * HDm) * SEQ;
    const __nv_bfloat16* Vlg = Vtl + (size_t)(bh * HDm) * SEQ;
    int* msk = (int*)(smc + FA_MSK);

    // prologue: Q (hi/lo), mask tile 0, KV stage 0 -> one async group
    #pragma unroll
    for (int i = 0; i < 4; i++) {
        int c = tid + i * 256; int r = c >> 3, cc = c & 7;
        cpa16(sb + FA_QH + r * FA_ROW + cc * 16, Qhg + (size_t)r * DIM + cc * 8);
        cpa16(sb + FA_QL + r * FA_ROW + cc * 16, Qlg + (size_t)r * DIM + cc * 8);
    }
    {
        uint32_t kv0 = sb + FA_KV;
        #pragma unroll
        for (int i = 0; i < 2; i++) {
            int c = tid + i * 256; int r = c >> 3, cc = c & 7;
            cpa16(kv0 + 0 * FA_KVT + r * FA_ROW + cc * 16, Khg + (size_t)r * DIM + cc * 8);
            cpa16(kv0 + 1 * FA_KVT + r * FA_ROW + cc * 16, Klg + (size_t)r * DIM + cc * 8);
            cpa16(kv0 + 2 * FA_KVT + r * FA_ROW + cc * 16, Vhg + (size_t)r * SEQ + cc * 8);
            cpa16(kv0 + 3 * FA_KVT + r * FA_ROW + cc * 16, Vlg + (size_t)r * SEQ + cc * 8);
        }
    }
    if (tid < 64) msk[tid] = amask[b * SEQ + tid];
    asm volatile("cp.async.commit_group;");

    float m0 = -INFINITY, m1 = -INFINITY, l0 = 0.f, l1 = 0.f;
    float o[8][4];
    #pragma unroll
    for (int nt = 0; nt < 8; nt++)
        #pragma unroll
        for (int e = 0; e < 4; e++) o[nt][e] = 0.f;

    const int kb = 2 * (lane & 3);
    constexpr int NT = SEQ / 64;   // 32

    for (int t = 0; t < NT; t++) {
        asm volatile("cp.async.wait_group 0;");
        __syncthreads();

        // prefetch next tile into the other stage (overlaps this tile's mma)
        if (t + 1 < NT) {
            const int k1 = (t + 1) * 64;
            uint32_t kvn = sb + FA_KV + ((t + 1) & 1) * FA_KVSTG;
            #pragma unroll
            for (int i = 0; i < 2; i++) {
                int c = tid + i * 256; int r = c >> 3, cc = c & 7;
                cpa16(kvn + 0 * FA_KVT + r * FA_ROW + cc * 16, Khg + (size_t)(k1 + r) * DIM + cc * 8);
                cpa16(kvn + 1 * FA_KVT + r * FA_ROW + cc * 16, Klg + (size_t)(k1 + r) * DIM + cc * 8);
                cpa16(kvn + 2 * FA_KVT + r * FA_ROW + cc * 16, Vhg + (size_t)r * SEQ + k1 + cc * 8);
                cpa16(kvn + 3 * FA_KVT + r * FA_ROW + cc * 16, Vlg + (size_t)r * SEQ + k1 + cc * 8);
            }
            if (tid < 64) msk[((t + 1) & 1) * 64 + tid] = amask[b * SEQ + k1 + tid];
            asm volatile("cp.async.commit_group;");
        }

        const uint32_t kvb = sb + FA_KV + (t & 1) * FA_KVSTG;
        const int* mrow = msk + (t & 1) * 64;

        // ---- S = Q K^T (bf16x3) ----
        float sacc[8][4];
        #pragma unroll
        for (int nt = 0; nt < 8; nt++)
            #pragma unroll
            for (int e = 0; e < 4; e++) sacc[nt][e] = 0.f;

        #pragma unroll
        for (int kk = 0; kk < 4; kk++) {
            uint32_t aH[4], aL[4];
            uint32_t ra = sb + FA_QH
                + (wid * 16 + (lane & 15)) * FA_ROW
                + (kk * 16 + (lane >> 4) * 8) * 2;
            ldsm_x4(aH, ra);
            ldsm_x4(aL, ra + (FA_QL - FA_QH));
            #pragma unroll
            for (int jp = 0; jp < 4; jp++) {
                uint32_t rb = kvb
                    + (jp * 16 + (lane >> 4) * 8 + (lane & 7)) * FA_ROW
                    + (kk * 16 + ((lane >> 3) & 1) * 8) * 2;
                uint32_t bH[4], bL[4];
                ldsm_x4(bH, rb);
                ldsm_x4(bL, rb + FA_KVT);
                mma16816(sacc[2*jp],   aH, &bH[0]);
                mma16816(sacc[2*jp],   aH, &bL[0]);
                mma16816(sacc[2*jp],   aL, &bH[0]);
                mma16816(sacc[2*jp+1], aH, &bH[2]);
                mma16816(sacc[2*jp+1], aH, &bL[2]);
                mma16816(sacc[2*jp+1], aL, &bH[2]);
            }
        }

        // ---- scale + mask ----
        #pragma unroll
        for (int nt = 0; nt < 8; nt++) {
            bool z0 = mrow[nt * 8 + kb] == 0, z1 = mrow[nt * 8 + kb + 1] == 0;
            sacc[nt][0] = z0 ? -1e9f : sacc[nt][0] * 0.125f;
            sacc[nt][1] = z1 ? -1e9f : sacc[nt][1] * 0.125f;
            sacc[nt][2] = z0 ? -1e9f : sacc[nt][2] * 0.125f;
            sacc[nt][3] = z1 ? -1e9f : sacc[nt][3] * 0.125f;
        }

        // ---- online softmax ----
        float mx0 = -INFINITY, mx1 = -INFINITY;
        #pragma unroll
        for (int nt = 0; nt < 8; nt++) {
            mx0 = fmaxf(mx0, fmaxf(sacc[nt][0], sacc[nt][1]));
            mx1 = fmaxf(mx1, fmaxf(sacc[nt][2], sacc[nt][3]));
        }
        mx0 = fmaxf(mx0, __shfl_xor_sync(0xffffffffu, mx0, 1));
        mx0 = fmaxf(mx0, __shfl_xor_sync(0xffffffffu, mx0, 2));
        mx1 = fmaxf(mx1, __shfl_xor_sync(0xffffffffu, mx1, 1));
        mx1 = fmaxf(mx1, __shfl_xor_sync(0xffffffffu, mx1, 2));
        float mn0 = fmaxf(m0, mx0), mn1 = fmaxf(m1, mx1);
        float f0 = __expf(m0 - mn0), f1 = __expf(m1 - mn1);
        float s0 = 0.f, s1 = 0.f;
        #pragma unroll
        for (int nt = 0; nt < 8; nt++) {
            float p0 = __expf(sacc[nt][0] - mn0);
            float p1 = __expf(sacc[nt][1] - mn0);
            float p2 = __expf(sacc[nt][2] - mn1);
            float p3 = __expf(sacc[nt][3] - mn1);
            sacc[nt][0] = p0; sacc[nt][1] = p1; sacc[nt][2] = p2; sacc[nt][3] = p3;
            s0 += p0 + p1; s1 += p2 + p3;
        }
        s0 += __shfl_xor_sync(0xffffffffu, s0, 1);
        s0 += __shfl_xor_sync(0xffffffffu, s0, 2);
        s1 += __shfl_xor_sync(0xffffffffu, s1, 1);
        s1 += __shfl_xor_sync(0xffffffffu, s1, 2);
        l0 = l0 * f0 + s0; l1 = l1 * f1 + s1;
        m0 = mn0; m1 = mn1;
        #pragma unroll
        for (int nt = 0; nt < 8; nt++) {
            o[nt][0] *= f0; o[nt][1] *= f0;
            o[nt][2] *= f1; o[nt][3] *= f1;
        }

        // ---- O += P V (bf16x3) ----
        #pragma unroll
        for (int j = 0; j < 4; j++) {
            uint32_t pH[4], pL[4];
            pH[0] = pk2(sacc[2*j][0],   sacc[2*j][1]);
            pH[1] = pk2(sacc[2*j][2],   sacc[2*j][3]);
            pH[2] = pk2(sacc[2*j+1][0], sacc[2*j+1][1]);
            pH[3] = pk2(sacc[2*j+1][2], sacc[2*j+1][3]);
            pL[0] = pk2(bres(sacc[2*j][0]),   bres(sacc[2*j][1]));
            pL[1] = pk2(bres(sacc[2*j][2]),   bres(sacc[2*j][3]));
            pL[2] = pk2(bres(sacc[2*j+1][0]), bres(sacc[2*j+1][1]));
            pL[3] = pk2(bres(sacc[2*j+1][2]), bres(sacc[2*j+1][3]));
            #pragma unroll
            for (int t4i = 0; t4i < 4; t4i++) {
                uint32_t rb = kvb + 2 * FA_KVT
                    + (t4i * 16 + (lane >> 4) * 8 + (lane & 7)) * FA_ROW
                    + (j * 16 + ((lane >> 3) & 1) * 8) * 2;
                uint32_t bH[4], bL[4];
                ldsm_x4(bH, rb);
                ldsm_x4(bL, rb + FA_KVT);
                mma16816(o[2*t4i],   pH, &bH[0]);
                mma16816(o[2*t4i],   pH, &bL[0]);
                mma16816(o[2*t4i],   pL, &bH[0]);
                mma16816(o[2*t4i+1], pH, &bH[2]);
                mma16816(o[2*t4i+1], pH, &bL[2]);
                mma16816(o[2*t4i+1], pL, &bH[2]);
            }
        }
        // no trailing sync: next iteration's barrier bounds skew; the prefetch
        // target stage was last read a full iteration ago.
    }

    const float i0 = 1.f / l0, i1 = 1.f / l1;
    const size_t r0 = (size_t)b * SEQ + q0 + wid * 16 + (lane >> 2);
    const size_t r1 = r0 + 8;
    #pragma unroll
    for (int nt = 0; nt < 8; nt++) {
        const int col = h * HDm + nt * 8 + kb;
        float v0 = o[nt][0] * i0, v1 = o[nt][1] * i0;
        float v2 = o[nt][2] * i1, v3 = o[nt][3] * i1;
        *(uint32_t*)(Ch + r0 * DIM + col) = pk2(v0, v1);
        *(uint32_t*)(Cl + r0 * DIM + col) = pk2(bres(v0), bres(v1));
        *(uint32_t*)(Ch + r1 * DIM + col) = pk2(v2, v3);
        *(uint32_t*)(Cl + r1 * DIM + col) = pk2(bres(v2), bres(v3));
    }
}

// ---------------- residual add + LayerNorm (+optional hi/lo emit) ----------
template<bool EMIT>
__global__ __launch_bounds__(256)
void ln_residual(const float* __restrict__ A, const float* __restrict__ Bv,
                 const float* __restrict__ g, const float* __restrict__ be,
                 float* __restrict__ out, __nv_bfloat16* __restrict__ oh,
                 __nv_bfloat16* __restrict__ ol, float eps)
{
    const int row = blockIdx.x;
    const int tid = threadIdx.x;
    const float4 va = ((const float4*)(A  + (size_t)row * DIM))[tid];
    const float4 vb = ((const float4*)(Bv + (size_t)row * DIM))[tid];
    float4 v;
    v.x = va.x + vb.x; v.y = va.y + vb.y;
    v.z = va.z + vb.z; v.w = va.w + vb.w;

    float sum = v.x + v.y + v.z + v.w;
    float sq  = v.x * v.x + v.y * v.y + v.z * v.z + v.w * v.w;
    #pragma unroll
    for (int mm = 16; mm; mm >>= 1) {
        sum += __shfl_xor_sync(0xffffffffu, sum, mm);
        sq  += __shfl_xor_sync(0xffffffffu, sq,  mm);
    }
    __shared__ float ssum[8], ssq[8], stats[2];
    const int wid = tid >> 5, lane = tid & 31;
    if (lane == 0) { ssum[wid] = sum; ssq[wid] = sq; }
    __syncthreads();
    if (tid == 0) {
        float S = 0.f, Qq = 0.f;
        #pragma unroll
        for (int i = 0; i < 8; i++) { S += ssum[i]; Qq += ssq[i]; }
        float mean = S * (1.f / DIM);
        float var  = fmaxf(Qq * (1.f / DIM) - mean * mean, 0.f);
        stats[0] = mean;
        stats[1] = rsqrtf(var + eps);
    }
    __syncthreads();
    const float mean = stats[0], rstd = stats[1];
    const float4 gg = ((const float4*)g)[tid];
    const float4 bb = ((const float4*)be)[tid];
    float4 r;
    r.x = (v.x - mean) * rstd * gg.x + bb.x;
    r.y = (v.y - mean) * rstd * gg.y + bb.y;
    r.z = (v.z - mean) * rstd * gg.z + bb.z;
    r.w = (v.w - mean) * rstd * gg.w + bb.w;
    ((float4*)(out + (size_t)row * DIM))[tid] = r;
    if (EMIT) {
        __nv_bfloat16 h0,l0,h1,l1,h2,l2,h3,l3;
        split_hilo(r.x,h0,l0); split_hilo(r.y,h1,l1);
        split_hilo(r.z,h2,l2); split_hilo(r.w,h3,l3);
        __nv_bfloat162 hA(h0,h1), hB(h2,h3), lA(l0,l1), lB(l2,l3);
        ((uint2*)(oh + (size_t)row * DIM))[tid] = make_uint2(*(uint32_t*)&hA, *(uint32_t*)&hB);
        ((uint2*)(ol + (size_t)row * DIM))[tid] = make_uint2(*(uint32_t*)&lA, *(uint32_t*)&lB);
    }
}

// ---------------- launch ----------------------------------------------------
extern "C" void kernel_launch(void* const* d_in, const int* in_sizes, int n_in,
                              void* d_out, int out_size)
{
    const float* x     = (const float*)d_in[0];
    const int*   amask = (const int*  )d_in[1];
    const float* wq = (const float*)d_in[2];
    const float* bq = (const float*)d_in[3];
    const float* wk = (const float*)d_in[4];
    const float* bk = (const float*)d_in[5];
    const float* wv = (const float*)d_in[6];
    const float* bv = (const float*)d_in[7];
    const float* wo = (const float*)d_in[8];
    const float* bo = (const float*)d_in[9];
    const float* ln1_g = (const float*)d_in[10];
    const float* ln1_b = (const float*)d_in[11];
    const float* w1 = (const float*)d_in[12];
    const float* b1 = (const float*)d_in[13];
    const float* w2 = (const float*)d_in[14];
    const float* b2 = (const float*)d_in[15];
    const float* lnf_g = (const float*)d_in[16];
    const float* lnf_b = (const float*)d_in[17];
    const float* ln2_g = (const float*)d_in[18];
    const float* ln2_b = (const float*)d_in[19];
    float* out = (float*)d_out;

    float *tmp, *x1, *ff;
    cudaGetSymbolAddress((void**)&tmp, g_tmp);
    cudaGetSymbolAddress((void**)&x1,  g_x1);
    cudaGetSymbolAddress((void**)&ff,  g_ff);

    __nv_bfloat16 *xh,*xl,*qh,*ql,*kh,*kl,*vh,*vl,*vth,*vtl,*ctxh,*ctxl,*x1h,*x1l,*hh,*hl;
    __nv_bfloat16 *wqh,*wql,*wkh,*wkl,*wvh,*wvl,*woh,*wol,*w1h,*w1l,*w2h,*w2l;
    cudaGetSymbolAddress((void**)&xh,  g_xh);   cudaGetSymbolAddress((void**)&xl,  g_xl);
    cudaGetSymbolAddress((void**)&qh,  g_qh);   cudaGetSymbolAddress((void**)&ql,  g_ql);
    cudaGetSymbolAddress((void**)&kh,  g_kh);   cudaGetSymbolAddress((void**)&kl,  g_kl);
    cudaGetSymbolAddress((void**)&vh,  g_vh);   cudaGetSymbolAddress((void**)&vl,  g_vl);
    cudaGetSymbolAddress((void**)&vth, g_vth);  cudaGetSymbolAddress((void**)&vtl, g_vtl);
    cudaGetSymbolAddress((void**)&ctxh,g_ctxh); cudaGetSymbolAddress((void**)&ctxl,g_ctxl);
    cudaGetSymbolAddress((void**)&x1h, g_x1h);  cudaGetSymbolAddress((void**)&x1l, g_x1l);
    cudaGetSymbolAddress((void**)&hh,  g_hh);   cudaGetSymbolAddress((void**)&hl,  g_hl);
    cudaGetSymbolAddress((void**)&wqh, g_wqh);  cudaGetSymbolAddress((void**)&wql, g_wql);
    cudaGetSymbolAddress((void**)&wkh, g_wkh);  cudaGetSymbolAddress((void**)&wkl, g_wkl);
    cudaGetSymbolAddress((void**)&wvh, g_wvh);  cudaGetSymbolAddress((void**)&wvl, g_wvl);
    cudaGetSymbolAddress((void**)&woh, g_woh);  cudaGetSymbolAddress((void**)&wol, g_wol);
    cudaGetSymbolAddress((void**)&w1h, g_w1h);  cudaGetSymbolAddress((void**)&w1l, g_w1l);
    cudaGetSymbolAddress((void**)&w2h, g_w2h);  cudaGetSymbolAddress((void**)&w2l, g_w2l);

    cudaFuncSetAttribute(flash_attn_bf16,
                         cudaFuncAttributeMaxDynamicSharedMemorySize, FA_SMEM);
    cudaFuncSetAttribute(hmma_gemm<false, true, false>,
                         cudaFuncAttributeMaxDynamicSharedMemorySize, HG_SMEM);
    cudaFuncSetAttribute(hmma_gemm<false, false, true>,
                         cudaFuncAttributeMaxDynamicSharedMemorySize, HG_SMEM);
    cudaFuncSetAttribute(hmma_gemm<true, false, true>,
                         cudaFuncAttributeMaxDynamicSharedMemorySize, HG_SMEM);

    const dim3 blk(256);

    // weight transpose + hi/lo split
    transpose_convert<<<dim3(DIM/32, DIM/32), blk>>>(wq, wqh, wql, DIM, DIM);
    transpose_convert<<<dim3(DIM/32, DIM/32), blk>>>(wk, wkh, wkl, DIM, DIM);
    transpose_convert<<<dim3(DIM/32, DIM/32), blk>>>(wv, wvh, wvl, DIM, DIM);
    transpose_convert<<<dim3(DIM/32, DIM/32), blk>>>(wo, woh, wol, DIM, DIM);
    transpose_convert<<<dim3(FFD/32, DIM/32), blk>>>(w1, w1h, w1l, DIM, FFD);
    transpose_convert<<<dim3(DIM/32, FFD/32), blk>>>(w2, w2h, w2l, FFD, DIM);

    // x -> hi/lo
    convert_hilo<<<(MTOK * DIM) / 1024, blk>>>(x, xh, xl, MTOK * DIM);

    // QKV projections -> bf16 hi/lo
    hmma_gemm<false,false,true><<<dim3(DIM/128, MTOK/128), blk, HG_SMEM>>>(
        xh, xl, wqh, wql, bq, nullptr, qh, ql, MTOK, DIM, DIM);
    hmma_gemm<false,false,true><<<dim3(DIM/128, MTOK/128), blk, HG_SMEM>>>(
        xh, xl, wkh, wkl, bk, nullptr, kh, kl, MTOK, DIM, DIM);
    hmma_gemm<false,false,true><<<dim3(DIM/128, MTOK/128), blk, HG_SMEM>>>(
        xh, xl, wvh, wvl, bv, nullptr, vh, vl, MTOK, DIM, DIM);

    // V transpose per head
    transpose_v<<<dim3(SEQ/64, BATCH*NH), blk>>>(vh, vl, vth, vtl);

    // attention -> ctx hi/lo
    flash_attn_bf16<<<dim3(SEQ/128, BATCH*NH), blk, FA_SMEM>>>(
        qh, ql, kh, kl, vth, vtl, amask, ctxh, ctxl);

    // O projection + residual LN1
    hmma_gemm<false,true,false><<<dim3(DIM/128, MTOK/128), blk, HG_SMEM>>>(
        ctxh, ctxl, woh, wol, bo, tmp, nullptr, nullptr, MTOK, DIM, DIM);
    ln_residual<true><<<MTOK, blk>>>(x, tmp, ln1_g, ln1_b, x1, x1h, x1l, 1e-5f);

    // FFN
    hmma_gemm<true,false,true><<<dim3(FFD/128, MTOK/128), blk, HG_SMEM>>>(
        x1h, x1l, w1h, w1l, b1, nullptr, hh, hl, MTOK, FFD, DIM);
    hmma_gemm<false,true,false><<<dim3(DIM/128, MTOK/128), blk, HG_SMEM>>>(
        hh, hl, w2h, w2l, b2, tmp, nullptr, nullptr, MTOK, DIM, FFD);
    ln_residual<false><<<MTOK, blk>>>(tmp, x1, lnf_g, lnf_b, ff, nullptr, nullptr, 1e-12f);

    // final LN
    ln_residual<false><<<MTOK, blk>>>(x1, ff, ln2_g, ln2_b, out, nullptr, nullptr, 1e-5f);
}

// round 6
// speedup vs baseline: 3.1685x; 1.2556x over previous
#include <cuda_runtime.h>
#include <cuda_bf16.h>
#include <math.h>
#include <stdint.h>

// Problem constants
constexpr int DIM  = 1024;
constexpr int NH   = 16;
constexpr int HDm  = 64;
constexpr int FFD  = 4096;
constexpr int BATCH= 2;
constexpr int SEQ  = 2048;
constexpr int MTOK = BATCH * SEQ;   // 4096

// ---------------------------------------------------------------------------
// helpers
// ---------------------------------------------------------------------------
__device__ __forceinline__ uint32_t smem_to_u32(const void* p) {
    uint32_t a;
    asm("{ .reg .u64 t; cvta.to.shared.u64 t, %1; cvt.u32.u64 %0, t; }"
        : "=r"(a) : "l"(p));
    return a;
}

__device__ __forceinline__ void ldsm_x4(uint32_t* r, uint32_t addr) {
    asm volatile("ldmatrix.sync.aligned.m8n8.x4.shared.b16 {%0,%1,%2,%3}, [%4];"
                 : "=r"(r[0]), "=r"(r[1]), "=r"(r[2]), "=r"(r[3]) : "r"(addr));
}

__device__ __forceinline__ void mma16816(float* c, const uint32_t* a, const uint32_t* b) {
    asm volatile(
        "mma.sync.aligned.m16n8k16.row.col.f32.bf16.bf16.f32 "
        "{%0,%1,%2,%3}, {%4,%5,%6,%7}, {%8,%9}, {%0,%1,%2,%3};"
        : "+f"(c[0]), "+f"(c[1]), "+f"(c[2]), "+f"(c[3])
        : "r"(a[0]), "r"(a[1]), "r"(a[2]), "r"(a[3]), "r"(b[0]), "r"(b[1]));
}

__device__ __forceinline__ void cpa16(uint32_t dst, const void* src) {
    asm volatile("cp.async.ca.shared.global [%0], [%1], 16;" :: "r"(dst), "l"(src));
}

__device__ __forceinline__ uint32_t pk2(float a, float b) {
    __nv_bfloat162 t(__float2bfloat16(a), __float2bfloat16(b));
    return *(uint32_t*)&t;
}
__device__ __forceinline__ float bres(float a) {
    return a - __bfloat162float(__float2bfloat16(a));
}

// ---------------------------------------------------------------------------
// scratch (device globals; no allocation allowed)
// ---------------------------------------------------------------------------
__device__ __align__(256) float g_tmp[MTOK * DIM];
__device__ __align__(256) float g_x1 [MTOK * DIM];
__device__ __align__(256) float g_ff [MTOK * DIM];

__device__ __align__(256) __nv_bfloat16 g_xh [MTOK * DIM],  g_xl [MTOK * DIM];
__device__ __align__(256) __nv_bfloat16 g_qh [MTOK * DIM],  g_ql [MTOK * DIM];
__device__ __align__(256) __nv_bfloat16 g_kh [MTOK * DIM];
__device__ __align__(256) __nv_bfloat16 g_vh [MTOK * DIM];
__device__ __align__(256) __nv_bfloat16 g_vth[MTOK * DIM];      // [bh*64+d][seq]
__device__ __align__(256) __nv_bfloat16 g_ctxh[MTOK * DIM], g_ctxl[MTOK * DIM];
__device__ __align__(256) __nv_bfloat16 g_x1h[MTOK * DIM];
__device__ __align__(256) __nv_bfloat16 g_hh [MTOK * FFD];
__device__ __align__(256) __nv_bfloat16 g_wqh[DIM * DIM], g_wql[DIM * DIM];
__device__ __align__(256) __nv_bfloat16 g_wkh[DIM * DIM], g_wkl[DIM * DIM];
__device__ __align__(256) __nv_bfloat16 g_wvh[DIM * DIM], g_wvl[DIM * DIM];
__device__ __align__(256) __nv_bfloat16 g_woh[DIM * DIM], g_wol[DIM * DIM];
__device__ __align__(256) __nv_bfloat16 g_w1h[DIM * FFD], g_w1l[DIM * FFD];
__device__ __align__(256) __nv_bfloat16 g_w2h[FFD * DIM], g_w2l[FFD * DIM];

// ---------------------------------------------------------------------------
// hi/lo split: hi = bf16(x), lo = bf16(x - hi)
// ---------------------------------------------------------------------------
__device__ __forceinline__ void split_hilo(float v, __nv_bfloat16& h, __nv_bfloat16& l) {
    h = __float2bfloat16(v);
    l = __float2bfloat16(v - __bfloat162float(h));
}

__global__ __launch_bounds__(256)
void convert_hilo(const float* __restrict__ in, __nv_bfloat16* __restrict__ oh,
                  __nv_bfloat16* __restrict__ ol, int count)
{
    int i = (blockIdx.x * 256 + threadIdx.x) * 4;
    if (i >= count) return;
    float4 v = *(const float4*)(in + i);
    __nv_bfloat16 h0, l0, h1, l1, h2, l2, h3, l3;
    split_hilo(v.x, h0, l0); split_hilo(v.y, h1, l1);
    split_hilo(v.z, h2, l2); split_hilo(v.w, h3, l3);
    __nv_bfloat162 hA(h0, h1), hB(h2, h3), lA(l0, l1), lB(l2, l3);
    *(uint2*)(oh + i) = make_uint2(*(uint32_t*)&hA, *(uint32_t*)&hB);
    *(uint2*)(ol + i) = make_uint2(*(uint32_t*)&lA, *(uint32_t*)&lB);
}

__global__ __launch_bounds__(256)
void transpose_convert(const float* __restrict__ in, __nv_bfloat16* __restrict__ oh,
                       __nv_bfloat16* __restrict__ ol, int K, int N)
{
    __shared__ float t[32][33];
    const int n0 = blockIdx.x * 32, k0 = blockIdx.y * 32;
    const int tx = threadIdx.x & 31, ty = threadIdx.x >> 5;
    #pragma unroll
    for (int j = 0; j < 32; j += 8)
        t[ty + j][tx] = in[(size_t)(k0 + ty + j) * N + n0 + tx];
    __syncthreads();
    #pragma unroll
    for (int j = 0; j < 32; j += 8) {
        float v = t[tx][ty + j];
        int n = n0 + ty + j, k = k0 + tx;
        __nv_bfloat16 h, l;
        split_hilo(v, h, l);
        oh[(size_t)n * K + k] = h;
        ol[(size_t)n * K + k] = l;
    }
}

// transpose V per head (hi limb only): vh[token][DIM] -> vth[(bh*64+d)][seq]
__global__ __launch_bounds__(256)
void transpose_v(const __nv_bfloat16* __restrict__ vh, __nv_bfloat16* __restrict__ vth)
{
    __shared__ __nv_bfloat16 th[64][72];
    const int tid = threadIdx.x;
    const int s0 = blockIdx.x * 64, bh = blockIdx.y, b = bh >> 4, h = bh & 15;
    #pragma unroll
    for (int i = 0; i < 2; i++) {
        int c = tid + i * 256; int r = c >> 3, cc = (c & 7) * 8;
        *(uint4*)&th[r][cc] = *(const uint4*)(vh + (size_t)(b * SEQ + s0 + r) * DIM + h * HDm + cc);
    }
    __syncthreads();
    #pragma unroll
    for (int i = 0; i < 2; i++) {
        int c = tid + i * 256; int d = c >> 3, cc = (c & 7) * 8;
        __nv_bfloat16 a[8];
        #pragma unroll
        for (int j = 0; j < 8; j++) a[j] = th[cc + j][d];
        *(uint4*)(vth + (size_t)(bh * HDm + d) * SEQ + s0 + cc) = *(uint4*)a;
    }
}

// ---------------------------------------------------------------------------
// HMMA GEMM, 3-stage cp.async pipeline.
// MODE 0: bf16x3, C = AhBh + AhBl + AlBh   (tiles: Ah, Al, Bh, Bl)
// MODE 1: bf16x2, C = Ah(Bh + Bl)          (tiles: Ah, Bh, Bl) — weight-corrected
// EMIT 0: none; 1: bf16 hi; 2: bf16 hi+lo
// ---------------------------------------------------------------------------
constexpr int HG_RSTRIDE = 80;
constexpr int HG_TILE    = 128 * HG_RSTRIDE;   // 10240 B

__device__ __forceinline__ void hg_load_tile(const __nv_bfloat16* __restrict__ src,
                                             int rowBase, int K, int k0,
                                             uint32_t dstBase, int tid)
{
    #pragma unroll
    for (int i = 0; i < 2; i++) {
        int c = tid + i * 256;
        int row = c >> 2, cc = c & 3;
        uint32_t dst = dstBase + row * HG_RSTRIDE + cc * 16;
        const void* s = src + (size_t)(rowBase + row) * K + k0 + cc * 8;
        cpa16(dst, s);
    }
}

template<int MODE, bool GELU, bool WRITE_F32, int EMIT>
__global__ __launch_bounds__(256, 1)
void hmma_gemm(const __nv_bfloat16* __restrict__ Ah, const __nv_bfloat16* __restrict__ Al,
               const __nv_bfloat16* __restrict__ Bh, const __nv_bfloat16* __restrict__ Bl,
               const float* __restrict__ bias, float* __restrict__ C,
               __nv_bfloat16* __restrict__ Ch, __nv_bfloat16* __restrict__ Cl,
               int M, int N, int K)
{
    constexpr int NTILES = (MODE == 0) ? 4 : 3;
    constexpr int STG_SZ = NTILES * HG_TILE;
    constexpr int OFF_BH = ((MODE == 0) ? 2 : 1) * HG_TILE;
    constexpr int OFF_BL = ((MODE == 0) ? 3 : 2) * HG_TILE;

    extern __shared__ char smem[];
    const uint32_t sb = smem_to_u32(smem);
    const int tid = threadIdx.x, wid = tid >> 5, lane = tid & 31;
    const int warpM = wid >> 2, warpN = wid & 3;
    const int bRow = blockIdx.y * 128, bCol = blockIdx.x * 128;

    float acc[4][4][4];
    #pragma unroll
    for (int m = 0; m < 4; m++)
        #pragma unroll
        for (int n = 0; n < 4; n++)
            #pragma unroll
            for (int e = 0; e < 4; e++) acc[m][n][e] = 0.f;

    // prologue: stages 0, 1
    #pragma unroll
    for (int p = 0; p < 2; p++) {
        uint32_t base = sb + p * STG_SZ;
        hg_load_tile(Ah, bRow, K, p * 32, base, tid);
        if (MODE == 0) hg_load_tile(Al, bRow, K, p * 32, base + HG_TILE, tid);
        hg_load_tile(Bh, bCol, K, p * 32, base + OFF_BH, tid);
        hg_load_tile(Bl, bCol, K, p * 32, base + OFF_BL, tid);
        asm volatile("cp.async.commit_group;");
    }

    const int nk = K >> 5;
    for (int ks = 0; ks < nk; ks++) {
        if (ks == nk - 1) { asm volatile("cp.async.wait_group 0;"); }
        else              { asm volatile("cp.async.wait_group 1;"); }
        __syncthreads();

        if (ks + 2 < nk) {
            uint32_t base = sb + (uint32_t)((ks + 2) % 3) * STG_SZ;
            const int k0 = (ks + 2) << 5;
            hg_load_tile(Ah, bRow, K, k0, base, tid);
            if (MODE == 0) hg_load_tile(Al, bRow, K, k0, base + HG_TILE, tid);
            hg_load_tile(Bh, bCol, K, k0, base + OFF_BH, tid);
            hg_load_tile(Bl, bCol, K, k0, base + OFF_BL, tid);
            asm volatile("cp.async.commit_group;");
        }

        const uint32_t stg = sb + (uint32_t)(ks % 3) * STG_SZ;
        #pragma unroll
        for (int h = 0; h < 2; h++) {
            const int ke = h * 16;
            uint32_t aHi[4][4], aLo[4][4], bHi[4][2], bLo[4][2];
            #pragma unroll
            for (int m = 0; m < 4; m++) {
                uint32_t ra = stg
                    + (warpM * 64 + m * 16 + (lane & 15)) * HG_RSTRIDE
                    + (ke + (lane >> 4) * 8) * 2;
                ldsm_x4(aHi[m], ra);
                if (MODE == 0) ldsm_x4(aLo[m], ra + HG_TILE);
            }
            #pragma unroll
            for (int jp = 0; jp < 2; jp++) {
                uint32_t rb = stg + OFF_BH
                    + (warpN * 32 + jp * 16 + (lane >> 4) * 8 + (lane & 7)) * HG_RSTRIDE
                    + (ke + ((lane >> 3) & 1) * 8) * 2;
                uint32_t t4[4];
                ldsm_x4(t4, rb);
                bHi[2*jp][0] = t4[0]; bHi[2*jp][1] = t4[1];
                bHi[2*jp+1][0] = t4[2]; bHi[2*jp+1][1] = t4[3];
                ldsm_x4(t4, rb + (OFF_BL - OFF_BH));
                bLo[2*jp][0] = t4[0]; bLo[2*jp][1] = t4[1];
                bLo[2*jp+1][0] = t4[2]; bLo[2*jp+1][1] = t4[3];
            }
            #pragma unroll
            for (int m = 0; m < 4; m++)
                #pragma unroll
                for (int n = 0; n < 4; n++) {
                    mma16816(acc[m][n], aHi[m], bHi[n]);
                    mma16816(acc[m][n], aHi[m], bLo[n]);
                    if (MODE == 0) mma16816(acc[m][n], aLo[m], bHi[n]);
                }
        }
    }

    #pragma unroll
    for (int m = 0; m < 4; m++) {
        #pragma unroll
        for (int half = 0; half < 2; half++) {
            const size_t row = bRow + warpM * 64 + m * 16 + (lane >> 2) + half * 8;
            #pragma unroll
            for (int n = 0; n < 4; n++) {
                const int col = bCol + warpN * 32 + n * 8 + (lane & 3) * 2;
                float v0 = acc[m][n][half * 2 + 0] + bias[col];
                float v1 = acc[m][n][half * 2 + 1] + bias[col + 1];
                if (GELU) {
                    v0 = 0.5f * v0 * (1.f + erff(v0 * 0.70710678118654752f));
                    v1 = 0.5f * v1 * (1.f + erff(v1 * 0.70710678118654752f));
                }
                if (WRITE_F32) {
                    float2 w; w.x = v0; w.y = v1;
                    *(float2*)(C + row * N + col) = w;
                }
                if (EMIT >= 1)
                    *(uint32_t*)(Ch + row * N + col) = pk2(v0, v1);
                if (EMIT == 2)
                    *(uint32_t*)(Cl + row * N + col) = pk2(bres(v0), bres(v1));
            }
        }
    }
}

constexpr int HG_SMEM4 = 3 * 4 * HG_TILE;   // MODE 0: 122880 B
constexpr int HG_SMEM3 = 3 * 3 * HG_TILE;   // MODE 1: 92160 B

// ---------------------------------------------------------------------------
// Flash attention, HMMA, double-buffered K/V stages.
//   S  = (Qh+Ql)·Kh   (K stored single-bf16)
//   O += (Ph+Pl)·Vh   (V stored single-bf16, P-lo in registers)
// ---------------------------------------------------------------------------
constexpr int FA_ST    = 72;
constexpr int FA_ROW   = FA_ST * 2;             // 144 B
constexpr int FA_QH    = 0;
constexpr int FA_QL    = FA_QH + 128 * FA_ROW;  // 18432
constexpr int FA_KV    = FA_QL + 128 * FA_ROW;  // 36864
constexpr int FA_KVT   = 64 * FA_ROW;           // 9216 per tile (Kh or Vh)
constexpr int FA_KVSTG = 2 * FA_KVT;            // 18432 per stage
constexpr int FA_MSK   = FA_KV + 2 * FA_KVSTG;  // 73728
constexpr int FA_SMEM  = FA_MSK + 2 * 64 * 4;   // 74240

__global__ __launch_bounds__(256, 2)
void flash_attn_bf16(const __nv_bfloat16* __restrict__ Qh, const __nv_bfloat16* __restrict__ Ql,
                     const __nv_bfloat16* __restrict__ Kh,
                     const __nv_bfloat16* __restrict__ Vth,
                     const int* __restrict__ amask,
                     __nv_bfloat16* __restrict__ Ch, __nv_bfloat16* __restrict__ Cl)
{
    extern __shared__ char smc[];
    const uint32_t sb = smem_to_u32(smc);
    const int tid = threadIdx.x, wid = tid >> 5, lane = tid & 31;
    const int bh = blockIdx.y, b = bh >> 4, h = bh & 15;
    const int q0 = blockIdx.x * 128;

    const __nv_bfloat16* Qhg = Qh + (size_t)(b * SEQ + q0) * DIM + h * HDm;
    const __nv_bfloat16* Qlg = Ql + (size_t)(b * SEQ + q0) * DIM + h * HDm;
    const __nv_bfloat16* Khg = Kh + (size_t)(b * SEQ) * DIM + h * HDm;
    const __nv_bfloat16* Vhg = Vth + (size_t)(bh * HDm) * SEQ;
    int* msk = (int*)(smc + FA_MSK);

    // prologue: Q (hi/lo), mask tile 0, KV stage 0
    #pragma unroll
    for (int i = 0; i < 4; i++) {
        int c = tid + i * 256; int r = c >> 3, cc = c & 7;
        cpa16(sb + FA_QH + r * FA_ROW + cc * 16, Qhg + (size_t)r * DIM + cc * 8);
        cpa16(sb + FA_QL + r * FA_ROW + cc * 16, Qlg + (size_t)r * DIM + cc * 8);
    }
    {
        uint32_t kv0 = sb + FA_KV;
        #pragma unroll
        for (int i = 0; i < 2; i++) {
            int c = tid + i * 256; int r = c >> 3, cc = c & 7;
            cpa16(kv0 + 0 * FA_KVT + r * FA_ROW + cc * 16, Khg + (size_t)r * DIM + cc * 8);
            cpa16(kv0 + 1 * FA_KVT + r * FA_ROW + cc * 16, Vhg + (size_t)r * SEQ + cc * 8);
        }
    }
    if (tid < 64) msk[tid] = amask[b * SEQ + tid];
    asm volatile("cp.async.commit_group;");

    float m0 = -INFINITY, m1 = -INFINITY, l0 = 0.f, l1 = 0.f;
    float o[8][4];
    #pragma unroll
    for (int nt = 0; nt < 8; nt++)
        #pragma unroll
        for (int e = 0; e < 4; e++) o[nt][e] = 0.f;

    const int kb = 2 * (lane & 3);
    constexpr int NT = SEQ / 64;   // 32

    for (int t = 0; t < NT; t++) {
        asm volatile("cp.async.wait_group 0;");
        __syncthreads();

        if (t + 1 < NT) {
            const int k1 = (t + 1) * 64;
            uint32_t kvn = sb + FA_KV + ((t + 1) & 1) * FA_KVSTG;
            #pragma unroll
            for (int i = 0; i < 2; i++) {
                int c = tid + i * 256; int r = c >> 3, cc = c & 7;
                cpa16(kvn + 0 * FA_KVT + r * FA_ROW + cc * 16, Khg + (size_t)(k1 + r) * DIM + cc * 8);
                cpa16(kvn + 1 * FA_KVT + r * FA_ROW + cc * 16, Vhg + (size_t)r * SEQ + k1 + cc * 8);
            }
            if (tid < 64) msk[((t + 1) & 1) * 64 + tid] = amask[b * SEQ + k1 + tid];
            asm volatile("cp.async.commit_group;");
        }

        const uint32_t kvb = sb + FA_KV + (t & 1) * FA_KVSTG;
        const int* mrow = msk + (t & 1) * 64;

        // ---- S = (Qh+Ql)·Kh ----
        float sacc[8][4];
        #pragma unroll
        for (int nt = 0; nt < 8; nt++)
            #pragma unroll
            for (int e = 0; e < 4; e++) sacc[nt][e] = 0.f;

        #pragma unroll
        for (int kk = 0; kk < 4; kk++) {
            uint32_t aH[4], aL[4];
            uint32_t ra = sb + FA_QH
                + (wid * 16 + (lane & 15)) * FA_ROW
                + (kk * 16 + (lane >> 4) * 8) * 2;
            ldsm_x4(aH, ra);
            ldsm_x4(aL, ra + (FA_QL - FA_QH));
            #pragma unroll
            for (int jp = 0; jp < 4; jp++) {
                uint32_t rb = kvb
                    + (jp * 16 + (lane >> 4) * 8 + (lane & 7)) * FA_ROW
                    + (kk * 16 + ((lane >> 3) & 1) * 8) * 2;
                uint32_t bH[4];
                ldsm_x4(bH, rb);
                mma16816(sacc[2*jp],   aH, &bH[0]);
                mma16816(sacc[2*jp],   aL, &bH[0]);
                mma16816(sacc[2*jp+1], aH, &bH[2]);
                mma16816(sacc[2*jp+1], aL, &bH[2]);
            }
        }

        // ---- scale + mask ----
        #pragma unroll
        for (int nt = 0; nt < 8; nt++) {
            bool z0 = mrow[nt * 8 + kb] == 0, z1 = mrow[nt * 8 + kb + 1] == 0;
            sacc[nt][0] = z0 ? -1e9f : sacc[nt][0] * 0.125f;
            sacc[nt][1] = z1 ? -1e9f : sacc[nt][1] * 0.125f;
            sacc[nt][2] = z0 ? -1e9f : sacc[nt][2] * 0.125f;
            sacc[nt][3] = z1 ? -1e9f : sacc[nt][3] * 0.125f;
        }

        // ---- online softmax ----
        float mx0 = -INFINITY, mx1 = -INFINITY;
        #pragma unroll
        for (int nt = 0; nt < 8; nt++) {
            mx0 = fmaxf(mx0, fmaxf(sacc[nt][0], sacc[nt][1]));
            mx1 = fmaxf(mx1, fmaxf(sacc[nt][2], sacc[nt][3]));
        }
        mx0 = fmaxf(mx0, __shfl_xor_sync(0xffffffffu, mx0, 1));
        mx0 = fmaxf(mx0, __shfl_xor_sync(0xffffffffu, mx0, 2));
        mx1 = fmaxf(mx1, __shfl_xor_sync(0xffffffffu, mx1, 1));
        mx1 = fmaxf(mx1, __shfl_xor_sync(0xffffffffu, mx1, 2));
        float mn0 = fmaxf(m0, mx0), mn1 = fmaxf(m1, mx1);
        float f0 = __expf(m0 - mn0), f1 = __expf(m1 - mn1);
        float s0 = 0.f, s1 = 0.f;
        #pragma unroll
        for (int nt = 0; nt < 8; nt++) {
            float p0 = __expf(sacc[nt][0] - mn0);
            float p1 = __expf(sacc[nt][1] - mn0);
            float p2 = __expf(sacc[nt][2] - mn1);
            float p3 = __expf(sacc[nt][3] - mn1);
            sacc[nt][0] = p0; sacc[nt][1] = p1; sacc[nt][2] = p2; sacc[nt][3] = p3;
            s0 += p0 + p1; s1 += p2 + p3;
        }
        s0 += __shfl_xor_sync(0xffffffffu, s0, 1);
        s0 += __shfl_xor_sync(0xffffffffu, s0, 2);
        s1 += __shfl_xor_sync(0xffffffffu, s1, 1);
        s1 += __shfl_xor_sync(0xffffffffu, s1, 2);
        l0 = l0 * f0 + s0; l1 = l1 * f1 + s1;
        m0 = mn0; m1 = mn1;
        #pragma unroll
        for (int nt = 0; nt < 8; nt++) {
            o[nt][0] *= f0; o[nt][1] *= f0;
            o[nt][2] *= f1; o[nt][3] *= f1;
        }

        // ---- O += (Ph+Pl)·Vh ----
        #pragma unroll
        for (int j = 0; j < 4; j++) {
            uint32_t pH[4], pL[4];
            pH[0] = pk2(sacc[2*j][0],   sacc[2*j][1]);
            pH[1] = pk2(sacc[2*j][2],   sacc[2*j][3]);
            pH[2] = pk2(sacc[2*j+1][0], sacc[2*j+1][1]);
            pH[3] = pk2(sacc[2*j+1][2], sacc[2*j+1][3]);
            pL[0] = pk2(bres(sacc[2*j][0]),   bres(sacc[2*j][1]));
            pL[1] = pk2(bres(sacc[2*j][2]),   bres(sacc[2*j][3]));
            pL[2] = pk2(bres(sacc[2*j+1][0]), bres(sacc[2*j+1][1]));
            pL[3] = pk2(bres(sacc[2*j+1][2]), bres(sacc[2*j+1][3]));
            #pragma unroll
            for (int t4i = 0; t4i < 4; t4i++) {
                uint32_t rb = kvb + FA_KVT
                    + (t4i * 16 + (lane >> 4) * 8 + (lane & 7)) * FA_ROW
                    + (j * 16 + ((lane >> 3) & 1) * 8) * 2;
                uint32_t bH[4];
                ldsm_x4(bH, rb);
                mma16816(o[2*t4i],   pH, &bH[0]);
                mma16816(o[2*t4i],   pL, &bH[0]);
                mma16816(o[2*t4i+1], pH, &bH[2]);
                mma16816(o[2*t4i+1], pL, &bH[2]);
            }
        }
    }

    const float i0 = 1.f / l0, i1 = 1.f / l1;
    const size_t r0 = (size_t)b * SEQ + q0 + wid * 16 + (lane >> 2);
    const size_t r1 = r0 + 8;
    #pragma unroll
    for (int nt = 0; nt < 8; nt++) {
        const int col = h * HDm + nt * 8 + kb;
        float v0 = o[nt][0] * i0, v1 = o[nt][1] * i0;
        float v2 = o[nt][2] * i1, v3 = o[nt][3] * i1;
        *(uint32_t*)(Ch + r0 * DIM + col) = pk2(v0, v1);
        *(uint32_t*)(Cl + r0 * DIM + col) = pk2(bres(v0), bres(v1));
        *(uint32_t*)(Ch + r1 * DIM + col) = pk2(v2, v3);
        *(uint32_t*)(Cl + r1 * DIM + col) = pk2(bres(v2), bres(v3));
    }
}

// ---------------- residual add + LayerNorm (+optional hi emit) -------------
template<bool EMIT>
__global__ __launch_bounds__(256)
void ln_residual(const float* __restrict__ A, const float* __restrict__ Bv,
                 const float* __restrict__ g, const float* __restrict__ be,
                 float* __restrict__ out, __nv_bfloat16* __restrict__ oh,
                 float eps)
{
    const int row = blockIdx.x;
    const int tid = threadIdx.x;
    const float4 va = ((const float4*)(A  + (size_t)row * DIM))[tid];
    const float4 vb = ((const float4*)(Bv + (size_t)row * DIM))[tid];
    float4 v;
    v.x = va.x + vb.x; v.y = va.y + vb.y;
    v.z = va.z + vb.z; v.w = va.w + vb.w;

    float sum = v.x + v.y + v.z + v.w;
    float sq  = v.x * v.x + v.y * v.y + v.z * v.z + v.w * v.w;
    #pragma unroll
    for (int mm = 16; mm; mm >>= 1) {
        sum += __shfl_xor_sync(0xffffffffu, sum, mm);
        sq  += __shfl_xor_sync(0xffffffffu, sq,  mm);
    }
    __shared__ float ssum[8], ssq[8], stats[2];
    const int wid = tid >> 5, lane = tid & 31;
    if (lane == 0) { ssum[wid] = sum; ssq[wid] = sq; }
    __syncthreads();
    if (tid == 0) {
        float S = 0.f, Qq = 0.f;
        #pragma unroll
        for (int i = 0; i < 8; i++) { S += ssum[i]; Qq += ssq[i]; }
        float mean = S * (1.f / DIM);
        float var  = fmaxf(Qq * (1.f / DIM) - mean * mean, 0.f);
        stats[0] = mean;
        stats[1] = rsqrtf(var + eps);
    }
    __syncthreads();
    const float mean = stats[0], rstd = stats[1];
    const float4 gg = ((const float4*)g)[tid];
    const float4 bb = ((const float4*)be)[tid];
    float4 r;
    r.x = (v.x - mean) * rstd * gg.x + bb.x;
    r.y = (v.y - mean) * rstd * gg.y + bb.y;
    r.z = (v.z - mean) * rstd * gg.z + bb.z;
    r.w = (v.w - mean) * rstd * gg.w + bb.w;
    ((float4*)(out + (size_t)row * DIM))[tid] = r;
    if (EMIT) {
        __nv_bfloat162 hA(__float2bfloat16(r.x), __float2bfloat16(r.y));
        __nv_bfloat162 hB(__float2bfloat16(r.z), __float2bfloat16(r.w));
        ((uint2*)(oh + (size_t)row * DIM))[tid] = make_uint2(*(uint32_t*)&hA, *(uint32_t*)&hB);
    }
}

// ---------------- launch ----------------------------------------------------
extern "C" void kernel_launch(void* const* d_in, const int* in_sizes, int n_in,
                              void* d_out, int out_size)
{
    const float* x     = (const float*)d_in[0];
    const int*   amask = (const int*  )d_in[1];
    const float* wq = (const float*)d_in[2];
    const float* bq = (const float*)d_in[3];
    const float* wk = (const float*)d_in[4];
    const float* bk = (const float*)d_in[5];
    const float* wv = (const float*)d_in[6];
    const float* bv = (const float*)d_in[7];
    const float* wo = (const float*)d_in[8];
    const float* bo = (const float*)d_in[9];
    const float* ln1_g = (const float*)d_in[10];
    const float* ln1_b = (const float*)d_in[11];
    const float* w1 = (const float*)d_in[12];
    const float* b1 = (const float*)d_in[13];
    const float* w2 = (const float*)d_in[14];
    const float* b2 = (const float*)d_in[15];
    const float* lnf_g = (const float*)d_in[16];
    const float* lnf_b = (const float*)d_in[17];
    const float* ln2_g = (const float*)d_in[18];
    const float* ln2_b = (const float*)d_in[19];
    float* out = (float*)d_out;

    float *tmp, *x1, *ff;
    cudaGetSymbolAddress((void**)&tmp, g_tmp);
    cudaGetSymbolAddress((void**)&x1,  g_x1);
    cudaGetSymbolAddress((void**)&ff,  g_ff);

    __nv_bfloat16 *xh,*xl,*qh,*ql,*kh,*vh,*vth,*ctxh,*ctxl,*x1h,*hh;
    __nv_bfloat16 *wqh,*wql,*wkh,*wkl,*wvh,*wvl,*woh,*wol,*w1h,*w1l,*w2h,*w2l;
    cudaGetSymbolAddress((void**)&xh,  g_xh);   cudaGetSymbolAddress((void**)&xl,  g_xl);
    cudaGetSymbolAddress((void**)&qh,  g_qh);   cudaGetSymbolAddress((void**)&ql,  g_ql);
    cudaGetSymbolAddress((void**)&kh,  g_kh);
    cudaGetSymbolAddress((void**)&vh,  g_vh);
    cudaGetSymbolAddress((void**)&vth, g_vth);
    cudaGetSymbolAddress((void**)&ctxh,g_ctxh); cudaGetSymbolAddress((void**)&ctxl,g_ctxl);
    cudaGetSymbolAddress((void**)&x1h, g_x1h);
    cudaGetSymbolAddress((void**)&hh,  g_hh);
    cudaGetSymbolAddress((void**)&wqh, g_wqh);  cudaGetSymbolAddress((void**)&wql, g_wql);
    cudaGetSymbolAddress((void**)&wkh, g_wkh);  cudaGetSymbolAddress((void**)&wkl, g_wkl);
    cudaGetSymbolAddress((void**)&wvh, g_wvh);  cudaGetSymbolAddress((void**)&wvl, g_wvl);
    cudaGetSymbolAddress((void**)&woh, g_woh);  cudaGetSymbolAddress((void**)&wol, g_wol);
    cudaGetSymbolAddress((void**)&w1h, g_w1h);  cudaGetSymbolAddress((void**)&w1l, g_w1l);
    cudaGetSymbolAddress((void**)&w2h, g_w2h);  cudaGetSymbolAddress((void**)&w2l, g_w2l);

    cudaFuncSetAttribute(flash_attn_bf16,
                         cudaFuncAttributeMaxDynamicSharedMemorySize, FA_SMEM);
    cudaFuncSetAttribute(hmma_gemm<0,false,false,2>,
                         cudaFuncAttributeMaxDynamicSharedMemorySize, HG_SMEM4);
    cudaFuncSetAttribute(hmma_gemm<0,false,false,1>,
                         cudaFuncAttributeMaxDynamicSharedMemorySize, HG_SMEM4);
    cudaFuncSetAttribute(hmma_gemm<0,false,true,0>,
                         cudaFuncAttributeMaxDynamicSharedMemorySize, HG_SMEM4);
    cudaFuncSetAttribute(hmma_gemm<1,true,false,1>,
                         cudaFuncAttributeMaxDynamicSharedMemorySize, HG_SMEM3);
    cudaFuncSetAttribute(hmma_gemm<1,false,true,0>,
                         cudaFuncAttributeMaxDynamicSharedMemorySize, HG_SMEM3);

    const dim3 blk(256);

    // weight transpose + hi/lo split
    transpose_convert<<<dim3(DIM/32, DIM/32), blk>>>(wq, wqh, wql, DIM, DIM);
    transpose_convert<<<dim3(DIM/32, DIM/32), blk>>>(wk, wkh, wkl, DIM, DIM);
    transpose_convert<<<dim3(DIM/32, DIM/32), blk>>>(wv, wvh, wvl, DIM, DIM);
    transpose_convert<<<dim3(DIM/32, DIM/32), blk>>>(wo, woh, wol, DIM, DIM);
    transpose_convert<<<dim3(FFD/32, DIM/32), blk>>>(w1, w1h, w1l, DIM, FFD);
    transpose_convert<<<dim3(DIM/32, FFD/32), blk>>>(w2, w2h, w2l, FFD, DIM);

    // x -> hi/lo
    convert_hilo<<<(MTOK * DIM) / 1024, blk>>>(x, xh, xl, MTOK * DIM);

    // QKV projections (bf16x3); Q emits hi+lo, K/V emit hi only
    hmma_gemm<0,false,false,2><<<dim3(DIM/128, MTOK/128), blk, HG_SMEM4>>>(
        xh, xl, wqh, wql, bq, nullptr, qh, ql, MTOK, DIM, DIM);
    hmma_gemm<0,false,false,1><<<dim3(DIM/128, MTOK/128), blk, HG_SMEM4>>>(
        xh, xl, wkh, wkl, bk, nullptr, kh, nullptr, MTOK, DIM, DIM);
    hmma_gemm<0,false,false,1><<<dim3(DIM/128, MTOK/128), blk, HG_SMEM4>>>(
        xh, xl, wvh, wvl, bv, nullptr, vh, nullptr, MTOK, DIM, DIM);

    // V transpose per head (hi only)
    transpose_v<<<dim3(SEQ/64, BATCH*NH), blk>>>(vh, vth);

    // attention -> ctx hi/lo
    flash_attn_bf16<<<dim3(SEQ/128, BATCH*NH), blk, FA_SMEM>>>(
        qh, ql, kh, vth, amask, ctxh, ctxl);

    // O projection (bf16x3) + residual LN1 (emit x1 hi)
    hmma_gemm<0,false,true,0><<<dim3(DIM/128, MTOK/128), blk, HG_SMEM4>>>(
        ctxh, ctxl, woh, wol, bo, tmp, nullptr, nullptr, MTOK, DIM, DIM);
    ln_residual<true><<<MTOK, blk>>>(x, tmp, ln1_g, ln1_b, x1, x1h, 1e-5f);

    // FFN (bf16x2, weight-corrected)
    hmma_gemm<1,true,false,1><<<dim3(FFD/128, MTOK/128), blk, HG_SMEM3>>>(
        x1h, nullptr, w1h, w1l, b1, nullptr, hh, nullptr, MTOK, FFD, DIM);
    hmma_gemm<1,false,true,0><<<dim3(DIM/128, MTOK/128), blk, HG_SMEM3>>>(
        hh, nullptr, w2h, w2l, b2, tmp, nullptr, nullptr, MTOK, DIM, FFD);
    ln_residual<false><<<MTOK, blk>>>(tmp, x1, lnf_g, lnf_b, ff, nullptr, 1e-12f);

    // final LN
    ln_residual<false><<<MTOK, blk>>>(x1, ff, ln2_g, ln2_b, out, nullptr, 1e-5f);
}

// round 7
// speedup vs baseline: 4.8405x; 1.5277x over previous
#include <cuda_runtime.h>
#include <cuda_fp16.h>
#include <math.h>
#include <stdint.h>

// Problem constants
constexpr int DIM  = 1024;
constexpr int NH   = 16;
constexpr int HDm  = 64;
constexpr int FFD  = 4096;
constexpr int BATCH= 2;
constexpr int SEQ  = 2048;
constexpr int MTOK = BATCH * SEQ;   // 4096

// ---------------------------------------------------------------------------
// helpers
// ---------------------------------------------------------------------------
__device__ __forceinline__ uint32_t smem_to_u32(const void* p) {
    uint32_t a;
    asm("{ .reg .u64 t; cvta.to.shared.u64 t, %1; cvt.u32.u64 %0, t; }"
        : "=r"(a) : "l"(p));
    return a;
}

__device__ __forceinline__ void ldsm_x4(uint32_t* r, uint32_t addr) {
    asm volatile("ldmatrix.sync.aligned.m8n8.x4.shared.b16 {%0,%1,%2,%3}, [%4];"
                 : "=r"(r[0]), "=r"(r[1]), "=r"(r[2]), "=r"(r[3]) : "r"(addr));
}

__device__ __forceinline__ void mma16816(float* c, const uint32_t* a, const uint32_t* b) {
    asm volatile(
        "mma.sync.aligned.m16n8k16.row.col.f32.f16.f16.f32 "
        "{%0,%1,%2,%3}, {%4,%5,%6,%7}, {%8,%9}, {%0,%1,%2,%3};"
        : "+f"(c[0]), "+f"(c[1]), "+f"(c[2]), "+f"(c[3])
        : "r"(a[0]), "r"(a[1]), "r"(a[2]), "r"(a[3]), "r"(b[0]), "r"(b[1]));
}

__device__ __forceinline__ void cpa16(uint32_t dst, const void* src) {
    asm volatile("cp.async.ca.shared.global [%0], [%1], 16;" :: "r"(dst), "l"(src));
}

__device__ __forceinline__ uint32_t pk2(float a, float b) {
    __half2 t(__float2half_rn(a), __float2half_rn(b));
    return *(uint32_t*)&t;
}

// ---------------------------------------------------------------------------
// scratch (device globals; no allocation allowed)
// ---------------------------------------------------------------------------
__device__ __align__(256) float g_tmp[MTOK * DIM];
__device__ __align__(256) float g_x1 [MTOK * DIM];
__device__ __align__(256) float g_ff [MTOK * DIM];

__device__ __align__(256) __half g_x  [MTOK * DIM];
__device__ __align__(256) __half g_q  [MTOK * DIM];
__device__ __align__(256) __half g_k  [MTOK * DIM];
__device__ __align__(256) __half g_v  [MTOK * DIM];
__device__ __align__(256) __half g_vt [MTOK * DIM];      // [bh*64+d][seq]
__device__ __align__(256) __half g_ctx[MTOK * DIM];
__device__ __align__(256) __half g_x1h[MTOK * DIM];
__device__ __align__(256) __half g_h  [MTOK * FFD];
__device__ __align__(256) __half g_wq [DIM * DIM];
__device__ __align__(256) __half g_wk [DIM * DIM];
__device__ __align__(256) __half g_wv [DIM * DIM];
__device__ __align__(256) __half g_wo [DIM * DIM];
__device__ __align__(256) __half g_w1 [DIM * FFD];       // [FFD][DIM]
__device__ __align__(256) __half g_w2 [FFD * DIM];       // [DIM][FFD]

// ---------------------------------------------------------------------------
// fp32 -> fp16 convert
// ---------------------------------------------------------------------------
__global__ __launch_bounds__(256)
void convert_f16(const float* __restrict__ in, __half* __restrict__ o, int count)
{
    int i = (blockIdx.x * 256 + threadIdx.x) * 4;
    if (i >= count) return;
    float4 v = *(const float4*)(in + i);
    __half2 a(__float2half_rn(v.x), __float2half_rn(v.y));
    __half2 b(__float2half_rn(v.z), __float2half_rn(v.w));
    *(uint2*)(o + i) = make_uint2(*(uint32_t*)&a, *(uint32_t*)&b);
}

// transpose + convert: in[K][N] fp32 -> o[N][K] fp16
__global__ __launch_bounds__(256)
void transpose_convert(const float* __restrict__ in, __half* __restrict__ o,
                       int K, int N)
{
    __shared__ float t[32][33];
    const int n0 = blockIdx.x * 32, k0 = blockIdx.y * 32;
    const int tx = threadIdx.x & 31, ty = threadIdx.x >> 5;
    #pragma unroll
    for (int j = 0; j < 32; j += 8)
        t[ty + j][tx] = in[(size_t)(k0 + ty + j) * N + n0 + tx];
    __syncthreads();
    #pragma unroll
    for (int j = 0; j < 32; j += 8) {
        int n = n0 + ty + j, k = k0 + tx;
        o[(size_t)n * K + k] = __float2half_rn(t[tx][ty + j]);
    }
}

// transpose V per head: v[token][DIM] -> vt[(bh*64+d)][seq]
__global__ __launch_bounds__(256)
void transpose_v(const __half* __restrict__ v, __half* __restrict__ vt)
{
    __shared__ __half th[64][72];
    const int tid = threadIdx.x;
    const int s0 = blockIdx.x * 64, bh = blockIdx.y, b = bh >> 4, h = bh & 15;
    #pragma unroll
    for (int i = 0; i < 2; i++) {
        int c = tid + i * 256; int r = c >> 3, cc = (c & 7) * 8;
        *(uint4*)&th[r][cc] = *(const uint4*)(v + (size_t)(b * SEQ + s0 + r) * DIM + h * HDm + cc);
    }
    __syncthreads();
    #pragma unroll
    for (int i = 0; i < 2; i++) {
        int c = tid + i * 256; int d = c >> 3, cc = (c & 7) * 8;
        __half a[8];
        #pragma unroll
        for (int j = 0; j < 8; j++) a[j] = th[cc + j][d];
        *(uint4*)(vt + (size_t)(bh * HDm + d) * SEQ + s0 + cc) = *(uint4*)a;
    }
}

// ---------------------------------------------------------------------------
// HMMA fp16 GEMM: C[M,N] = A[M,K] @ Bt[N,K]^T + bias (+GELU / f32 / f16 emit)
// 128x128 tile, BK=32, 256 threads (2x4 warps, 64x32 warp tile),
// 3-stage cp.async pipeline, one sync per chunk.
// ---------------------------------------------------------------------------
constexpr int HG_RSTRIDE = 80;                 // 64 B data + 16 pad
constexpr int HG_TILE    = 128 * HG_RSTRIDE;   // 10240 B
constexpr int HG_STAGE   = 2 * HG_TILE;        // A + B = 20480 B
constexpr int HG_SMEM    = 3 * HG_STAGE;       // 61440 B

__device__ __forceinline__ void hg_load_tile(const __half* __restrict__ src,
                                             int rowBase, int K, int k0,
                                             uint32_t dstBase, int tid)
{
    #pragma unroll
    for (int i = 0; i < 2; i++) {
        int c = tid + i * 256;
        int row = c >> 2, cc = c & 3;
        uint32_t dst = dstBase + row * HG_RSTRIDE + cc * 16;
        const void* s = src + (size_t)(rowBase + row) * K + k0 + cc * 8;
        cpa16(dst, s);
    }
}

template<bool GELU, bool WRITE_F32, bool EMIT>
__global__ __launch_bounds__(256, 1)
void hmma_gemm(const __half* __restrict__ A, const __half* __restrict__ B,
               const float* __restrict__ bias, float* __restrict__ C,
               __half* __restrict__ Ch, int M, int N, int K)
{
    extern __shared__ char smem[];
    const uint32_t sb = smem_to_u32(smem);
    const int tid = threadIdx.x, wid = tid >> 5, lane = tid & 31;
    const int warpM = wid >> 2, warpN = wid & 3;
    const int bRow = blockIdx.y * 128, bCol = blockIdx.x * 128;

    float acc[4][4][4];
    #pragma unroll
    for (int m = 0; m < 4; m++)
        #pragma unroll
        for (int n = 0; n < 4; n++)
            #pragma unroll
            for (int e = 0; e < 4; e++) acc[m][n][e] = 0.f;

    #pragma unroll
    for (int p = 0; p < 2; p++) {
        uint32_t base = sb + p * HG_STAGE;
        hg_load_tile(A, bRow, K, p * 32, base, tid);
        hg_load_tile(B, bCol, K, p * 32, base + HG_TILE, tid);
        asm volatile("cp.async.commit_group;");
    }

    const int nk = K >> 5;
    for (int ks = 0; ks < nk; ks++) {
        if (ks == nk - 1) { asm volatile("cp.async.wait_group 0;"); }
        else              { asm volatile("cp.async.wait_group 1;"); }
        __syncthreads();

        if (ks + 2 < nk) {
            uint32_t base = sb + (uint32_t)((ks + 2) % 3) * HG_STAGE;
            const int k0 = (ks + 2) << 5;
            hg_load_tile(A, bRow, K, k0, base, tid);
            hg_load_tile(B, bCol, K, k0, base + HG_TILE, tid);
            asm volatile("cp.async.commit_group;");
        }

        const uint32_t stg = sb + (uint32_t)(ks % 3) * HG_STAGE;
        #pragma unroll
        for (int h = 0; h < 2; h++) {
            const int ke = h * 16;
            uint32_t aF[4][4], bF[4][2];
            #pragma unroll
            for (int m = 0; m < 4; m++) {
                uint32_t ra = stg
                    + (warpM * 64 + m * 16 + (lane & 15)) * HG_RSTRIDE
                    + (ke + (lane >> 4) * 8) * 2;
                ldsm_x4(aF[m], ra);
            }
            #pragma unroll
            for (int jp = 0; jp < 2; jp++) {
                uint32_t rb = stg + HG_TILE
                    + (warpN * 32 + jp * 16 + (lane >> 4) * 8 + (lane & 7)) * HG_RSTRIDE
                    + (ke + ((lane >> 3) & 1) * 8) * 2;
                uint32_t t4[4];
                ldsm_x4(t4, rb);
                bF[2*jp][0] = t4[0]; bF[2*jp][1] = t4[1];
                bF[2*jp+1][0] = t4[2]; bF[2*jp+1][1] = t4[3];
            }
            #pragma unroll
            for (int m = 0; m < 4; m++)
                #pragma unroll
                for (int n = 0; n < 4; n++)
                    mma16816(acc[m][n], aF[m], bF[n]);
        }
    }

    #pragma unroll
    for (int m = 0; m < 4; m++) {
        #pragma unroll
        for (int half = 0; half < 2; half++) {
            const size_t row = bRow + warpM * 64 + m * 16 + (lane >> 2) + half * 8;
            #pragma unroll
            for (int n = 0; n < 4; n++) {
                const int col = bCol + warpN * 32 + n * 8 + (lane & 3) * 2;
                float v0 = acc[m][n][half * 2 + 0] + bias[col];
                float v1 = acc[m][n][half * 2 + 1] + bias[col + 1];
                if (GELU) {
                    v0 = 0.5f * v0 * (1.f + erff(v0 * 0.70710678118654752f));
                    v1 = 0.5f * v1 * (1.f + erff(v1 * 0.70710678118654752f));
                }
                if (WRITE_F32) {
                    float2 w; w.x = v0; w.y = v1;
                    *(float2*)(C + row * N + col) = w;
                }
                if (EMIT)
                    *(uint32_t*)(Ch + row * N + col) = pk2(v0, v1);
            }
        }
    }
}

// ---------------------------------------------------------------------------
// Flash attention, HMMA fp16, double-buffered K/V stages.
// Q [128q][64hd] static; per stage: K (64k x 64hd), Vt (64hd x 64k)
// ---------------------------------------------------------------------------
constexpr int FA_ROW   = 144;                   // 64 fp16 + 16B pad
constexpr int FA_Q     = 0;
constexpr int FA_KV    = FA_Q + 128 * FA_ROW;   // 18432
constexpr int FA_KVT   = 64 * FA_ROW;           // 9216 per tile
constexpr int FA_KVSTG = 2 * FA_KVT;            // 18432 per stage
constexpr int FA_MSK   = FA_KV + 2 * FA_KVSTG;  // 55296
constexpr int FA_SMEM  = FA_MSK + 2 * 64 * 4;   // 55808

__global__ __launch_bounds__(256, 2)
void flash_attn_fp16(const __half* __restrict__ Q, const __half* __restrict__ K,
                     const __half* __restrict__ Vt, const int* __restrict__ amask,
                     __half* __restrict__ Ctx)
{
    extern __shared__ char smc[];
    const uint32_t sb = smem_to_u32(smc);
    const int tid = threadIdx.x, wid = tid >> 5, lane = tid & 31;
    const int bh = blockIdx.y, b = bh >> 4, h = bh & 15;
    const int q0 = blockIdx.x * 128;

    const __half* Qg = Q + (size_t)(b * SEQ + q0) * DIM + h * HDm;
    const __half* Kg = K + (size_t)(b * SEQ) * DIM + h * HDm;
    const __half* Vg = Vt + (size_t)(bh * HDm) * SEQ;
    int* msk = (int*)(smc + FA_MSK);

    // prologue: Q, mask tile 0, KV stage 0
    #pragma unroll
    for (int i = 0; i < 4; i++) {
        int c = tid + i * 256; int r = c >> 3, cc = c & 7;
        cpa16(sb + FA_Q + r * FA_ROW + cc * 16, Qg + (size_t)r * DIM + cc * 8);
    }
    {
        uint32_t kv0 = sb + FA_KV;
        #pragma unroll
        for (int i = 0; i < 2; i++) {
            int c = tid + i * 256; int r = c >> 3, cc = c & 7;
            cpa16(kv0 + 0 * FA_KVT + r * FA_ROW + cc * 16, Kg + (size_t)r * DIM + cc * 8);
            cpa16(kv0 + 1 * FA_KVT + r * FA_ROW + cc * 16, Vg + (size_t)r * SEQ + cc * 8);
        }
    }
    if (tid < 64) msk[tid] = amask[b * SEQ + tid];
    asm volatile("cp.async.commit_group;");

    float m0 = -INFINITY, m1 = -INFINITY, l0 = 0.f, l1 = 0.f;
    float o[8][4];
    #pragma unroll
    for (int nt = 0; nt < 8; nt++)
        #pragma unroll
        for (int e = 0; e < 4; e++) o[nt][e] = 0.f;

    const int kb = 2 * (lane & 3);
    constexpr int NT = SEQ / 64;   // 32

    for (int t = 0; t < NT; t++) {
        asm volatile("cp.async.wait_group 0;");
        __syncthreads();

        if (t + 1 < NT) {
            const int k1 = (t + 1) * 64;
            uint32_t kvn = sb + FA_KV + ((t + 1) & 1) * FA_KVSTG;
            #pragma unroll
            for (int i = 0; i < 2; i++) {
                int c = tid + i * 256; int r = c >> 3, cc = c & 7;
                cpa16(kvn + 0 * FA_KVT + r * FA_ROW + cc * 16, Kg + (size_t)(k1 + r) * DIM + cc * 8);
                cpa16(kvn + 1 * FA_KVT + r * FA_ROW + cc * 16, Vg + (size_t)r * SEQ + k1 + cc * 8);
            }
            if (tid < 64) msk[((t + 1) & 1) * 64 + tid] = amask[b * SEQ + k1 + tid];
            asm volatile("cp.async.commit_group;");
        }

        const uint32_t kvb = sb + FA_KV + (t & 1) * FA_KVSTG;
        const int* mrow = msk + (t & 1) * 64;

        // ---- S = Q K^T ----
        float sacc[8][4];
        #pragma unroll
        for (int nt = 0; nt < 8; nt++)
            #pragma unroll
            for (int e = 0; e < 4; e++) sacc[nt][e] = 0.f;

        #pragma unroll
        for (int kk = 0; kk < 4; kk++) {
            uint32_t aF[4];
            uint32_t ra = sb + FA_Q
                + (wid * 16 + (lane & 15)) * FA_ROW
                + (kk * 16 + (lane >> 4) * 8) * 2;
            ldsm_x4(aF, ra);
            #pragma unroll
            for (int jp = 0; jp < 4; jp++) {
                uint32_t rb = kvb
                    + (jp * 16 + (lane >> 4) * 8 + (lane & 7)) * FA_ROW
                    + (kk * 16 + ((lane >> 3) & 1) * 8) * 2;
                uint32_t bF[4];
                ldsm_x4(bF, rb);
                mma16816(sacc[2*jp],   aF, &bF[0]);
                mma16816(sacc[2*jp+1], aF, &bF[2]);
            }
        }

        // ---- scale + mask ----
        #pragma unroll
        for (int nt = 0; nt < 8; nt++) {
            bool z0 = mrow[nt * 8 + kb] == 0, z1 = mrow[nt * 8 + kb + 1] == 0;
            sacc[nt][0] = z0 ? -1e9f : sacc[nt][0] * 0.125f;
            sacc[nt][1] = z1 ? -1e9f : sacc[nt][1] * 0.125f;
            sacc[nt][2] = z0 ? -1e9f : sacc[nt][2] * 0.125f;
            sacc[nt][3] = z1 ? -1e9f : sacc[nt][3] * 0.125f;
        }

        // ---- online softmax (rows r0 = lane>>2, r1 = r0+8) ----
        float mx0 = -INFINITY, mx1 = -INFINITY;
        #pragma unroll
        for (int nt = 0; nt < 8; nt++) {
            mx0 = fmaxf(mx0, fmaxf(sacc[nt][0], sacc[nt][1]));
            mx1 = fmaxf(mx1, fmaxf(sacc[nt][2], sacc[nt][3]));
        }
        mx0 = fmaxf(mx0, __shfl_xor_sync(0xffffffffu, mx0, 1));
        mx0 = fmaxf(mx0, __shfl_xor_sync(0xffffffffu, mx0, 2));
        mx1 = fmaxf(mx1, __shfl_xor_sync(0xffffffffu, mx1, 1));
        mx1 = fmaxf(mx1, __shfl_xor_sync(0xffffffffu, mx1, 2));
        float mn0 = fmaxf(m0, mx0), mn1 = fmaxf(m1, mx1);
        float f0 = __expf(m0 - mn0), f1 = __expf(m1 - mn1);
        float s0 = 0.f, s1 = 0.f;
        #pragma unroll
        for (int nt = 0; nt < 8; nt++) {
            float p0 = __expf(sacc[nt][0] - mn0);
            float p1 = __expf(sacc[nt][1] - mn0);
            float p2 = __expf(sacc[nt][2] - mn1);
            float p3 = __expf(sacc[nt][3] - mn1);
            sacc[nt][0] = p0; sacc[nt][1] = p1; sacc[nt][2] = p2; sacc[nt][3] = p3;
            s0 += p0 + p1; s1 += p2 + p3;
        }
        s0 += __shfl_xor_sync(0xffffffffu, s0, 1);
        s0 += __shfl_xor_sync(0xffffffffu, s0, 2);
        s1 += __shfl_xor_sync(0xffffffffu, s1, 1);
        s1 += __shfl_xor_sync(0xffffffffu, s1, 2);
        l0 = l0 * f0 + s0; l1 = l1 * f1 + s1;
        m0 = mn0; m1 = mn1;
        #pragma unroll
        for (int nt = 0; nt < 8; nt++) {
            o[nt][0] *= f0; o[nt][1] *= f0;
            o[nt][2] *= f1; o[nt][3] *= f1;
        }

        // ---- O += P V ----
        #pragma unroll
        for (int j = 0; j < 4; j++) {
            uint32_t pF[4];
            pF[0] = pk2(sacc[2*j][0],   sacc[2*j][1]);
            pF[1] = pk2(sacc[2*j][2],   sacc[2*j][3]);
            pF[2] = pk2(sacc[2*j+1][0], sacc[2*j+1][1]);
            pF[3] = pk2(sacc[2*j+1][2], sacc[2*j+1][3]);
            #pragma unroll
            for (int t4i = 0; t4i < 4; t4i++) {
                uint32_t rb = kvb + FA_KVT
                    + (t4i * 16 + (lane >> 4) * 8 + (lane & 7)) * FA_ROW
                    + (j * 16 + ((lane >> 3) & 1) * 8) * 2;
                uint32_t bF[4];
                ldsm_x4(bF, rb);
                mma16816(o[2*t4i],   pF, &bF[0]);
                mma16816(o[2*t4i+1], pF, &bF[2]);
            }
        }
    }

    const float i0 = 1.f / l0, i1 = 1.f / l1;
    const size_t r0 = (size_t)b * SEQ + q0 + wid * 16 + (lane >> 2);
    const size_t r1 = r0 + 8;
    #pragma unroll
    for (int nt = 0; nt < 8; nt++) {
        const int col = h * HDm + nt * 8 + kb;
        *(uint32_t*)(Ctx + r0 * DIM + col) = pk2(o[nt][0] * i0, o[nt][1] * i0);
        *(uint32_t*)(Ctx + r1 * DIM + col) = pk2(o[nt][2] * i1, o[nt][3] * i1);
    }
}

// ---------------- residual add + LayerNorm (+optional fp16 emit) -----------
template<bool EMIT>
__global__ __launch_bounds__(256)
void ln_residual(const float* __restrict__ A, const float* __restrict__ Bv,
                 const float* __restrict__ g, const float* __restrict__ be,
                 float* __restrict__ out, __half* __restrict__ oh, float eps)
{
    const int row = blockIdx.x;
    const int tid = threadIdx.x;
    const float4 va = ((const float4*)(A  + (size_t)row * DIM))[tid];
    const float4 vb = ((const float4*)(Bv + (size_t)row * DIM))[tid];
    float4 v;
    v.x = va.x + vb.x; v.y = va.y + vb.y;
    v.z = va.z + vb.z; v.w = va.w + vb.w;

    float sum = v.x + v.y + v.z + v.w;
    float sq  = v.x * v.x + v.y * v.y + v.z * v.z + v.w * v.w;
    #pragma unroll
    for (int mm = 16; mm; mm >>= 1) {
        sum += __shfl_xor_sync(0xffffffffu, sum, mm);
        sq  += __shfl_xor_sync(0xffffffffu, sq,  mm);
    }
    __shared__ float ssum[8], ssq[8], stats[2];
    const int wid = tid >> 5, lane = tid & 31;
    if (lane == 0) { ssum[wid] = sum; ssq[wid] = sq; }
    __syncthreads();
    if (tid == 0) {
        float S = 0.f, Qq = 0.f;
        #pragma unroll
        for (int i = 0; i < 8; i++) { S += ssum[i]; Qq += ssq[i]; }
        float mean = S * (1.f / DIM);
        float var  = fmaxf(Qq * (1.f / DIM) - mean * mean, 0.f);
        stats[0] = mean;
        stats[1] = rsqrtf(var + eps);
    }
    __syncthreads();
    const float mean = stats[0], rstd = stats[1];
    const float4 gg = ((const float4*)g)[tid];
    const float4 bb = ((const float4*)be)[tid];
    float4 r;
    r.x = (v.x - mean) * rstd * gg.x + bb.x;
    r.y = (v.y - mean) * rstd * gg.y + bb.y;
    r.z = (v.z - mean) * rstd * gg.z + bb.z;
    r.w = (v.w - mean) * rstd * gg.w + bb.w;
    ((float4*)(out + (size_t)row * DIM))[tid] = r;
    if (EMIT) {
        ((uint2*)(oh + (size_t)row * DIM))[tid] =
            make_uint2(pk2(r.x, r.y), pk2(r.z, r.w));
    }
}

// ---------------- launch ----------------------------------------------------
extern "C" void kernel_launch(void* const* d_in, const int* in_sizes, int n_in,
                              void* d_out, int out_size)
{
    const float* x     = (const float*)d_in[0];
    const int*   amask = (const int*  )d_in[1];
    const float* wq = (const float*)d_in[2];
    const float* bq = (const float*)d_in[3];
    const float* wk = (const float*)d_in[4];
    const float* bk = (const float*)d_in[5];
    const float* wv = (const float*)d_in[6];
    const float* bv = (const float*)d_in[7];
    const float* wo = (const float*)d_in[8];
    const float* bo = (const float*)d_in[9];
    const float* ln1_g = (const float*)d_in[10];
    const float* ln1_b = (const float*)d_in[11];
    const float* w1 = (const float*)d_in[12];
    const float* b1 = (const float*)d_in[13];
    const float* w2 = (const float*)d_in[14];
    const float* b2 = (const float*)d_in[15];
    const float* lnf_g = (const float*)d_in[16];
    const float* lnf_b = (const float*)d_in[17];
    const float* ln2_g = (const float*)d_in[18];
    const float* ln2_b = (const float*)d_in[19];
    float* out = (float*)d_out;

    float *tmp, *x1, *ff;
    cudaGetSymbolAddress((void**)&tmp, g_tmp);
    cudaGetSymbolAddress((void**)&x1,  g_x1);
    cudaGetSymbolAddress((void**)&ff,  g_ff);

    __half *xh,*qh,*kh,*vh,*vth,*ctxh,*x1h,*hh;
    __half *wqh,*wkh,*wvh,*woh,*w1h,*w2h;
    cudaGetSymbolAddress((void**)&xh,  g_x);
    cudaGetSymbolAddress((void**)&qh,  g_q);
    cudaGetSymbolAddress((void**)&kh,  g_k);
    cudaGetSymbolAddress((void**)&vh,  g_v);
    cudaGetSymbolAddress((void**)&vth, g_vt);
    cudaGetSymbolAddress((void**)&ctxh,g_ctx);
    cudaGetSymbolAddress((void**)&x1h, g_x1h);
    cudaGetSymbolAddress((void**)&hh,  g_h);
    cudaGetSymbolAddress((void**)&wqh, g_wq);
    cudaGetSymbolAddress((void**)&wkh, g_wk);
    cudaGetSymbolAddress((void**)&wvh, g_wv);
    cudaGetSymbolAddress((void**)&woh, g_wo);
    cudaGetSymbolAddress((void**)&w1h, g_w1);
    cudaGetSymbolAddress((void**)&w2h, g_w2);

    cudaFuncSetAttribute(flash_attn_fp16,
                         cudaFuncAttributeMaxDynamicSharedMemorySize, FA_SMEM);
    cudaFuncSetAttribute(hmma_gemm<false,false,true>,
                         cudaFuncAttributeMaxDynamicSharedMemorySize, HG_SMEM);
    cudaFuncSetAttribute(hmma_gemm<false,true,false>,
                         cudaFuncAttributeMaxDynamicSharedMemorySize, HG_SMEM);
    cudaFuncSetAttribute(hmma_gemm<true,false,true>,
                         cudaFuncAttributeMaxDynamicSharedMemorySize, HG_SMEM);

    const dim3 blk(256);

    // weight transpose + fp16 convert
    transpose_convert<<<dim3(DIM/32, DIM/32), blk>>>(wq, wqh, DIM, DIM);
    transpose_convert<<<dim3(DIM/32, DIM/32), blk>>>(wk, wkh, DIM, DIM);
    transpose_convert<<<dim3(DIM/32, DIM/32), blk>>>(wv, wvh, DIM, DIM);
    transpose_convert<<<dim3(DIM/32, DIM/32), blk>>>(wo, woh, DIM, DIM);
    transpose_convert<<<dim3(FFD/32, DIM/32), blk>>>(w1, w1h, DIM, FFD);
    transpose_convert<<<dim3(DIM/32, FFD/32), blk>>>(w2, w2h, FFD, DIM);

    // x -> fp16
    convert_f16<<<(MTOK * DIM) / 1024, blk>>>(x, xh, MTOK * DIM);

    // QKV projections -> fp16
    hmma_gemm<false,false,true><<<dim3(DIM/128, MTOK/128), blk, HG_SMEM>>>(
        xh, wqh, bq, nullptr, qh, MTOK, DIM, DIM);
    hmma_gemm<false,false,true><<<dim3(DIM/128, MTOK/128), blk, HG_SMEM>>>(
        xh, wkh, bk, nullptr, kh, MTOK, DIM, DIM);
    hmma_gemm<false,false,true><<<dim3(DIM/128, MTOK/128), blk, HG_SMEM>>>(
        xh, wvh, bv, nullptr, vh, MTOK, DIM, DIM);

    // V transpose per head
    transpose_v<<<dim3(SEQ/64, BATCH*NH), blk>>>(vh, vth);

    // attention -> ctx fp16
    flash_attn_fp16<<<dim3(SEQ/128, BATCH*NH), blk, FA_SMEM>>>(
        qh, kh, vth, amask, ctxh);

    // O projection + residual LN1 (emit x1 fp16)
    hmma_gemm<false,true,false><<<dim3(DIM/128, MTOK/128), blk, HG_SMEM>>>(
        ctxh, woh, bo, tmp, nullptr, MTOK, DIM, DIM);
    ln_residual<true><<<MTOK, blk>>>(x, tmp, ln1_g, ln1_b, x1, x1h, 1e-5f);

    // FFN
    hmma_gemm<true,false,true><<<dim3(FFD/128, MTOK/128), blk, HG_SMEM>>>(
        x1h, w1h, b1, nullptr, hh, MTOK, FFD, DIM);
    hmma_gemm<false,true,false><<<dim3(DIM/128, MTOK/128), blk, HG_SMEM>>>(
        hh, w2h, b2, tmp, nullptr, MTOK, DIM, FFD);
    ln_residual<false><<<MTOK, blk>>>(tmp, x1, lnf_g, lnf_b, ff, nullptr, 1e-12f);

    // final LN
    ln_residual<false><<<MTOK, blk>>>(x1, ff, ln2_g, ln2_b, out, nullptr, 1e-5f);
}

// round 8
// speedup vs baseline: 5.9270x; 1.2245x over previous
#include <cuda_runtime.h>
#include <cuda_fp16.h>
#include <math.h>
#include <stdint.h>

// Problem constants
constexpr int DIM  = 1024;
constexpr int NH   = 16;
constexpr int HDm  = 64;
constexpr int FFD  = 4096;
constexpr int BATCH= 2;
constexpr int SEQ  = 2048;
constexpr int MTOK = BATCH * SEQ;   // 4096
constexpr int QKVD = 3 * DIM;       // 3072

// ---------------------------------------------------------------------------
// helpers
// ---------------------------------------------------------------------------
__device__ __forceinline__ uint32_t smem_to_u32(const void* p) {
    uint32_t a;
    asm("{ .reg .u64 t; cvta.to.shared.u64 t, %1; cvt.u32.u64 %0, t; }"
        : "=r"(a) : "l"(p));
    return a;
}

__device__ __forceinline__ void ldsm_x4(uint32_t* r, uint32_t addr) {
    asm volatile("ldmatrix.sync.aligned.m8n8.x4.shared.b16 {%0,%1,%2,%3}, [%4];"
                 : "=r"(r[0]), "=r"(r[1]), "=r"(r[2]), "=r"(r[3]) : "r"(addr));
}

__device__ __forceinline__ void mma16816(float* c, const uint32_t* a, const uint32_t* b) {
    asm volatile(
        "mma.sync.aligned.m16n8k16.row.col.f32.f16.f16.f32 "
        "{%0,%1,%2,%3}, {%4,%5,%6,%7}, {%8,%9}, {%0,%1,%2,%3};"
        : "+f"(c[0]), "+f"(c[1]), "+f"(c[2]), "+f"(c[3])
        : "r"(a[0]), "r"(a[1]), "r"(a[2]), "r"(a[3]), "r"(b[0]), "r"(b[1]));
}

__device__ __forceinline__ void cpa16(uint32_t dst, const void* src) {
    asm volatile("cp.async.ca.shared.global [%0], [%1], 16;" :: "r"(dst), "l"(src));
}

__device__ __forceinline__ uint32_t pk2(float a, float b) {
    __half2 t(__float2half_rn(a), __float2half_rn(b));
    return *(uint32_t*)&t;
}

// ---------------------------------------------------------------------------
// scratch (device globals; no allocation allowed)
// ---------------------------------------------------------------------------
__device__ __align__(256) float g_tmp[MTOK * DIM];
__device__ __align__(256) float g_x1 [MTOK * DIM];

__device__ __align__(256) __half g_x   [MTOK * DIM];
__device__ __align__(256) __half g_qkv [MTOK * QKVD];    // fused q|k|v
__device__ __align__(256) __half g_vt  [MTOK * DIM];     // [bh*64+d][seq]
__device__ __align__(256) __half g_ctx [MTOK * DIM];
__device__ __align__(256) __half g_x1h [MTOK * DIM];
__device__ __align__(256) __half g_h   [MTOK * FFD];
__device__ __align__(256) __half g_wqkv[QKVD * DIM];     // [3072][1024]
__device__ __align__(256) __half g_wo  [DIM * DIM];
__device__ __align__(256) __half g_w1  [DIM * FFD];      // [FFD][DIM]
__device__ __align__(256) __half g_w2  [FFD * DIM];      // [DIM][FFD]
__device__ __align__(256) float  g_bqkv[QKVD];

// ---------------------------------------------------------------------------
// small prep kernels
// ---------------------------------------------------------------------------
__global__ __launch_bounds__(256)
void convert_f16(const float* __restrict__ in, __half* __restrict__ o, int count)
{
    int i = (blockIdx.x * 256 + threadIdx.x) * 4;
    if (i >= count) return;
    float4 v = *(const float4*)(in + i);
    *(uint2*)(o + i) = make_uint2(pk2(v.x, v.y), pk2(v.z, v.w));
}

__global__ __launch_bounds__(256)
void concat_bias3(const float* __restrict__ a, const float* __restrict__ b,
                  const float* __restrict__ c, float* __restrict__ o)
{
    int i = blockIdx.x * 256 + threadIdx.x;
    if (i >= QKVD) return;
    o[i] = (i < DIM) ? a[i] : ((i < 2 * DIM) ? b[i - DIM] : c[i - 2 * DIM]);
}

// transpose + convert: in[K][N] fp32 -> o[N][K] fp16
__global__ __launch_bounds__(256)
void transpose_convert(const float* __restrict__ in, __half* __restrict__ o,
                       int K, int N)
{
    __shared__ float t[32][33];
    const int n0 = blockIdx.x * 32, k0 = blockIdx.y * 32;
    const int tx = threadIdx.x & 31, ty = threadIdx.x >> 5;
    #pragma unroll
    for (int j = 0; j < 32; j += 8)
        t[ty + j][tx] = in[(size_t)(k0 + ty + j) * N + n0 + tx];
    __syncthreads();
    #pragma unroll
    for (int j = 0; j < 32; j += 8) {
        int n = n0 + ty + j, k = k0 + tx;
        o[(size_t)n * K + k] = __float2half_rn(t[tx][ty + j]);
    }
}

// transpose V per head from fused qkv: qkv[tok][2048 + h*64 + d] -> vt[(bh*64+d)][seq]
__global__ __launch_bounds__(256)
void transpose_v(const __half* __restrict__ qkv, __half* __restrict__ vt)
{
    __shared__ __half th[64][72];
    const int tid = threadIdx.x;
    const int s0 = blockIdx.x * 64, bh = blockIdx.y, b = bh >> 4, h = bh & 15;
    #pragma unroll
    for (int i = 0; i < 2; i++) {
        int c = tid + i * 256; int r = c >> 3, cc = (c & 7) * 8;
        *(uint4*)&th[r][cc] = *(const uint4*)(qkv
            + (size_t)(b * SEQ + s0 + r) * QKVD + 2 * DIM + h * HDm + cc);
    }
    __syncthreads();
    #pragma unroll
    for (int i = 0; i < 2; i++) {
        int c = tid + i * 256; int d = c >> 3, cc = (c & 7) * 8;
        __half a[8];
        #pragma unroll
        for (int j = 0; j < 8; j++) a[j] = th[cc + j][d];
        *(uint4*)(vt + (size_t)(bh * HDm + d) * SEQ + s0 + cc) = *(uint4*)a;
    }
}

// ---------------------------------------------------------------------------
// HMMA fp16 GEMM, 3-stage cp.async pipeline, 2 CTAs/SM.
// ---------------------------------------------------------------------------
constexpr int HG_RSTRIDE = 80;
constexpr int HG_TILE    = 128 * HG_RSTRIDE;   // 10240 B
constexpr int HG_STAGE   = 2 * HG_TILE;        // 20480 B
constexpr int HG_SMEM    = 3 * HG_STAGE;       // 61440 B (2 CTAs = 120 KB < 228 KB)

__device__ __forceinline__ void hg_load_tile(const __half* __restrict__ src,
                                             int rowBase, int K, int k0,
                                             uint32_t dstBase, int tid)
{
    #pragma unroll
    for (int i = 0; i < 2; i++) {
        int c = tid + i * 256;
        int row = c >> 2, cc = c & 3;
        uint32_t dst = dstBase + row * HG_RSTRIDE + cc * 16;
        const void* s = src + (size_t)(rowBase + row) * K + k0 + cc * 8;
        cpa16(dst, s);
    }
}

template<bool GELU, bool WRITE_F32, bool EMIT>
__global__ __launch_bounds__(256, 2)
void hmma_gemm(const __half* __restrict__ A, const __half* __restrict__ B,
               const float* __restrict__ bias, float* __restrict__ C,
               __half* __restrict__ Ch, int M, int N, int K)
{
    extern __shared__ char smem[];
    const uint32_t sb = smem_to_u32(smem);
    const int tid = threadIdx.x, wid = tid >> 5, lane = tid & 31;
    const int warpM = wid >> 2, warpN = wid & 3;
    const int bRow = blockIdx.y * 128, bCol = blockIdx.x * 128;

    float acc[4][4][4];
    #pragma unroll
    for (int m = 0; m < 4; m++)
        #pragma unroll
        for (int n = 0; n < 4; n++)
            #pragma unroll
            for (int e = 0; e < 4; e++) acc[m][n][e] = 0.f;

    #pragma unroll
    for (int p = 0; p < 2; p++) {
        uint32_t base = sb + p * HG_STAGE;
        hg_load_tile(A, bRow, K, p * 32, base, tid);
        hg_load_tile(B, bCol, K, p * 32, base + HG_TILE, tid);
        asm volatile("cp.async.commit_group;");
    }

    const int nk = K >> 5;
    for (int ks = 0; ks < nk; ks++) {
        if (ks == nk - 1) { asm volatile("cp.async.wait_group 0;"); }
        else              { asm volatile("cp.async.wait_group 1;"); }
        __syncthreads();

        if (ks + 2 < nk) {
            uint32_t base = sb + (uint32_t)((ks + 2) % 3) * HG_STAGE;
            const int k0 = (ks + 2) << 5;
            hg_load_tile(A, bRow, K, k0, base, tid);
            hg_load_tile(B, bCol, K, k0, base + HG_TILE, tid);
            asm volatile("cp.async.commit_group;");
        }

        const uint32_t stg = sb + (uint32_t)(ks % 3) * HG_STAGE;
        #pragma unroll
        for (int h = 0; h < 2; h++) {
            const int ke = h * 16;
            uint32_t aF[4][4], bF[4][2];
            #pragma unroll
            for (int m = 0; m < 4; m++) {
                uint32_t ra = stg
                    + (warpM * 64 + m * 16 + (lane & 15)) * HG_RSTRIDE
                    + (ke + (lane >> 4) * 8) * 2;
                ldsm_x4(aF[m], ra);
            }
            #pragma unroll
            for (int jp = 0; jp < 2; jp++) {
                uint32_t rb = stg + HG_TILE
                    + (warpN * 32 + jp * 16 + (lane >> 4) * 8 + (lane & 7)) * HG_RSTRIDE
                    + (ke + ((lane >> 3) & 1) * 8) * 2;
                uint32_t t4[4];
                ldsm_x4(t4, rb);
                bF[2*jp][0] = t4[0]; bF[2*jp][1] = t4[1];
                bF[2*jp+1][0] = t4[2]; bF[2*jp+1][1] = t4[3];
            }
            #pragma unroll
            for (int m = 0; m < 4; m++)
                #pragma unroll
                for (int n = 0; n < 4; n++)
                    mma16816(acc[m][n], aF[m], bF[n]);
        }
    }

    #pragma unroll
    for (int m = 0; m < 4; m++) {
        #pragma unroll
        for (int half = 0; half < 2; half++) {
            const size_t row = bRow + warpM * 64 + m * 16 + (lane >> 2) + half * 8;
            #pragma unroll
            for (int n = 0; n < 4; n++) {
                const int col = bCol + warpN * 32 + n * 8 + (lane & 3) * 2;
                float v0 = acc[m][n][half * 2 + 0] + bias[col];
                float v1 = acc[m][n][half * 2 + 1] + bias[col + 1];
                if (GELU) {
                    v0 = 0.5f * v0 * (1.f + erff(v0 * 0.70710678118654752f));
                    v1 = 0.5f * v1 * (1.f + erff(v1 * 0.70710678118654752f));
                }
                if (WRITE_F32) {
                    float2 w; w.x = v0; w.y = v1;
                    *(float2*)(C + row * N + col) = w;
                }
                if (EMIT)
                    *(uint32_t*)(Ch + row * N + col) = pk2(v0, v1);
            }
        }
    }
}

// ---------------------------------------------------------------------------
// Flash attention, HMMA fp16, double-buffered K/V, fixed-max softmax.
// Q/K read from fused qkv (stride QKVD); V from vt (stride SEQ).
// ---------------------------------------------------------------------------
constexpr int FA_ROW   = 144;
constexpr int FA_Q     = 0;
constexpr int FA_KV    = FA_Q + 128 * FA_ROW;   // 18432
constexpr int FA_KVT   = 64 * FA_ROW;           // 9216
constexpr int FA_KVSTG = 2 * FA_KVT;            // 18432
constexpr int FA_MSK   = FA_KV + 2 * FA_KVSTG;  // 55296
constexpr int FA_SMEM  = FA_MSK + 2 * 64 * 4;   // 55808

__global__ __launch_bounds__(256, 2)
void flash_attn_fp16(const __half* __restrict__ QKV, const __half* __restrict__ Vt,
                     const int* __restrict__ amask, __half* __restrict__ Ctx)
{
    extern __shared__ char smc[];
    const uint32_t sb = smem_to_u32(smc);
    const int tid = threadIdx.x, wid = tid >> 5, lane = tid & 31;
    const int bh = blockIdx.y, b = bh >> 4, h = bh & 15;
    const int q0 = blockIdx.x * 128;

    const __half* Qg = QKV + (size_t)(b * SEQ + q0) * QKVD + h * HDm;
    const __half* Kg = QKV + (size_t)(b * SEQ) * QKVD + DIM + h * HDm;
    const __half* Vg = Vt + (size_t)(bh * HDm) * SEQ;
    int* msk = (int*)(smc + FA_MSK);

    #pragma unroll
    for (int i = 0; i < 4; i++) {
        int c = tid + i * 256; int r = c >> 3, cc = c & 7;
        cpa16(sb + FA_Q + r * FA_ROW + cc * 16, Qg + (size_t)r * QKVD + cc * 8);
    }
    {
        uint32_t kv0 = sb + FA_KV;
        #pragma unroll
        for (int i = 0; i < 2; i++) {
            int c = tid + i * 256; int r = c >> 3, cc = c & 7;
            cpa16(kv0 + 0 * FA_KVT + r * FA_ROW + cc * 16, Kg + (size_t)r * QKVD + cc * 8);
            cpa16(kv0 + 1 * FA_KVT + r * FA_ROW + cc * 16, Vg + (size_t)r * SEQ + cc * 8);
        }
    }
    if (tid < 64) msk[tid] = amask[b * SEQ + tid];
    asm volatile("cp.async.commit_group;");

    float l0 = 0.f, l1 = 0.f;
    float o[8][4];
    #pragma unroll
    for (int nt = 0; nt < 8; nt++)
        #pragma unroll
        for (int e = 0; e < 4; e++) o[nt][e] = 0.f;

    const int kb = 2 * (lane & 3);
    constexpr int NT = SEQ / 64;   // 32

    for (int t = 0; t < NT; t++) {
        asm volatile("cp.async.wait_group 0;");
        __syncthreads();

        if (t + 1 < NT) {
            const int k1 = (t + 1) * 64;
            uint32_t kvn = sb + FA_KV + ((t + 1) & 1) * FA_KVSTG;
            #pragma unroll
            for (int i = 0; i < 2; i++) {
                int c = tid + i * 256; int r = c >> 3, cc = c & 7;
                cpa16(kvn + 0 * FA_KVT + r * FA_ROW + cc * 16, Kg + (size_t)(k1 + r) * QKVD + cc * 8);
                cpa16(kvn + 1 * FA_KVT + r * FA_ROW + cc * 16, Vg + (size_t)r * SEQ + k1 + cc * 8);
            }
            if (tid < 64) msk[((t + 1) & 1) * 64 + tid] = amask[b * SEQ + k1 + tid];
            asm volatile("cp.async.commit_group;");
        }

        const uint32_t kvb = sb + FA_KV + (t & 1) * FA_KVSTG;
        const int* mrow = msk + (t & 1) * 64;

        // ---- S = Q K^T ----
        float sacc[8][4];
        #pragma unroll
        for (int nt = 0; nt < 8; nt++)
            #pragma unroll
            for (int e = 0; e < 4; e++) sacc[nt][e] = 0.f;

        #pragma unroll
        for (int kk = 0; kk < 4; kk++) {
            uint32_t aF[4];
            uint32_t ra = sb + FA_Q
                + (wid * 16 + (lane & 15)) * FA_ROW
                + (kk * 16 + (lane >> 4) * 8) * 2;
            ldsm_x4(aF, ra);
            #pragma unroll
            for (int jp = 0; jp < 4; jp++) {
                uint32_t rb = kvb
                    + (jp * 16 + (lane >> 4) * 8 + (lane & 7)) * FA_ROW
                    + (kk * 16 + ((lane >> 3) & 1) * 8) * 2;
                uint32_t bF[4];
                ldsm_x4(bF, rb);
                mma16816(sacc[2*jp],   aF, &bF[0]);
                mma16816(sacc[2*jp+1], aF, &bF[2]);
            }
        }

        // ---- fixed-max softmax: p = exp(s/8) (masked -> 0) ----
        float s0 = 0.f, s1 = 0.f;
        #pragma unroll
        for (int nt = 0; nt < 8; nt++) {
            bool z0 = mrow[nt * 8 + kb] == 0, z1 = mrow[nt * 8 + kb + 1] == 0;
            float p0 = z0 ? 0.f : __expf(sacc[nt][0] * 0.125f);
            float p1 = z1 ? 0.f : __expf(sacc[nt][1] * 0.125f);
            float p2 = z0 ? 0.f : __expf(sacc[nt][2] * 0.125f);
            float p3 = z1 ? 0.f : __expf(sacc[nt][3] * 0.125f);
            sacc[nt][0] = p0; sacc[nt][1] = p1; sacc[nt][2] = p2; sacc[nt][3] = p3;
            s0 += p0 + p1; s1 += p2 + p3;
        }
        s0 += __shfl_xor_sync(0xffffffffu, s0, 1);
        s0 += __shfl_xor_sync(0xffffffffu, s0, 2);
        s1 += __shfl_xor_sync(0xffffffffu, s1, 1);
        s1 += __shfl_xor_sync(0xffffffffu, s1, 2);
        l0 += s0; l1 += s1;

        // ---- O += P V ----
        #pragma unroll
        for (int j = 0; j < 4; j++) {
            uint32_t pF[4];
            pF[0] = pk2(sacc[2*j][0],   sacc[2*j][1]);
            pF[1] = pk2(sacc[2*j][2],   sacc[2*j][3]);
            pF[2] = pk2(sacc[2*j+1][0], sacc[2*j+1][1]);
            pF[3] = pk2(sacc[2*j+1][2], sacc[2*j+1][3]);
            #pragma unroll
            for (int t4i = 0; t4i < 4; t4i++) {
                uint32_t rb = kvb + FA_KVT
                    + (t4i * 16 + (lane >> 4) * 8 + (lane & 7)) * FA_ROW
                    + (j * 16 + ((lane >> 3) & 1) * 8) * 2;
                uint32_t bF[4];
                ldsm_x4(bF, rb);
                mma16816(o[2*t4i],   pF, &bF[0]);
                mma16816(o[2*t4i+1], pF, &bF[2]);
            }
        }
    }

    const float i0 = 1.f / l0, i1 = 1.f / l1;
    const size_t r0 = (size_t)b * SEQ + q0 + wid * 16 + (lane >> 2);
    const size_t r1 = r0 + 8;
    #pragma unroll
    for (int nt = 0; nt < 8; nt++) {
        const int col = h * HDm + nt * 8 + kb;
        *(uint32_t*)(Ctx + r0 * DIM + col) = pk2(o[nt][0] * i0, o[nt][1] * i0);
        *(uint32_t*)(Ctx + r1 * DIM + col) = pk2(o[nt][2] * i1, o[nt][3] * i1);
    }
}

// ---------------- LN building block --------------------------------------
__device__ __forceinline__ void block_ln_stats(float4 v, float& mean, float& rstd,
                                               float eps, float* ssum, float* ssq,
                                               float* stats, int tid)
{
    float sum = v.x + v.y + v.z + v.w;
    float sq  = v.x * v.x + v.y * v.y + v.z * v.z + v.w * v.w;
    #pragma unroll
    for (int mm = 16; mm; mm >>= 1) {
        sum += __shfl_xor_sync(0xffffffffu, sum, mm);
        sq  += __shfl_xor_sync(0xffffffffu, sq,  mm);
    }
    const int wid = tid >> 5, lane = tid & 31;
    if (lane == 0) { ssum[wid] = sum; ssq[wid] = sq; }
    __syncthreads();
    if (tid == 0) {
        float S = 0.f, Qq = 0.f;
        #pragma unroll
        for (int i = 0; i < 8; i++) { S += ssum[i]; Qq += ssq[i]; }
        float mu = S * (1.f / DIM);
        float var = fmaxf(Qq * (1.f / DIM) - mu * mu, 0.f);
        stats[0] = mu;
        stats[1] = rsqrtf(var + eps);
    }
    __syncthreads();
    mean = stats[0]; rstd = stats[1];
}

// out = LN(a + b; g, beta, eps)  (+fp16 emit)
template<bool EMIT>
__global__ __launch_bounds__(256)
void ln_residual(const float* __restrict__ A, const float* __restrict__ Bv,
                 const float* __restrict__ g, const float* __restrict__ be,
                 float* __restrict__ out, __half* __restrict__ oh, float eps)
{
    const int row = blockIdx.x;
    const int tid = threadIdx.x;
    __shared__ float ssum[8], ssq[8], stats[2];
    const float4 va = ((const float4*)(A  + (size_t)row * DIM))[tid];
    const float4 vb = ((const float4*)(Bv + (size_t)row * DIM))[tid];
    float4 v;
    v.x = va.x + vb.x; v.y = va.y + vb.y;
    v.z = va.z + vb.z; v.w = va.w + vb.w;
    float mean, rstd;
    block_ln_stats(v, mean, rstd, eps, ssum, ssq, stats, tid);
    const float4 gg = ((const float4*)g)[tid];
    const float4 bb = ((const float4*)be)[tid];
    float4 r;
    r.x = (v.x - mean) * rstd * gg.x + bb.x;
    r.y = (v.y - mean) * rstd * gg.y + bb.y;
    r.z = (v.z - mean) * rstd * gg.z + bb.z;
    r.w = (v.w - mean) * rstd * gg.w + bb.w;
    ((float4*)(out + (size_t)row * DIM))[tid] = r;
    if (EMIT) {
        ((uint2*)(oh + (size_t)row * DIM))[tid] =
            make_uint2(pk2(r.x, r.y), pk2(r.z, r.w));
    }
}

// fused: ff = LN(tmp + x1; lnf, 1e-12); out = LN(x1 + ff; ln2, 1e-5)
__global__ __launch_bounds__(256)
void ln_double(const float* __restrict__ Tmp, const float* __restrict__ X1,
               const float* __restrict__ gf, const float* __restrict__ bf,
               const float* __restrict__ g2, const float* __restrict__ b2,
               float* __restrict__ out)
{
    const int row = blockIdx.x;
    const int tid = threadIdx.x;
    __shared__ float ssum[8], ssq[8], stats[2];
    const float4 vt = ((const float4*)(Tmp + (size_t)row * DIM))[tid];
    const float4 vx = ((const float4*)(X1  + (size_t)row * DIM))[tid];
    float4 v;
    v.x = vt.x + vx.x; v.y = vt.y + vx.y;
    v.z = vt.z + vx.z; v.w = vt.w + vx.w;
    float mean, rstd;
    block_ln_stats(v, mean, rstd, 1e-12f, ssum, ssq, stats, tid);
    const float4 gg = ((const float4*)gf)[tid];
    const float4 bb = ((const float4*)bf)[tid];
    float4 u;
    u.x = (v.x - mean) * rstd * gg.x + bb.x + vx.x;
    u.y = (v.y - mean) * rstd * gg.y + bb.y + vx.y;
    u.z = (v.z - mean) * rstd * gg.z + bb.z + vx.z;
    u.w = (v.w - mean) * rstd * gg.w + bb.w + vx.w;
    __syncthreads();   // reuse reduction smem safely
    float mean2, rstd2;
    block_ln_stats(u, mean2, rstd2, 1e-5f, ssum, ssq, stats, tid);
    const float4 g2v = ((const float4*)g2)[tid];
    const float4 b2v = ((const float4*)b2)[tid];
    float4 r;
    r.x = (u.x - mean2) * rstd2 * g2v.x + b2v.x;
    r.y = (u.y - mean2) * rstd2 * g2v.y + b2v.y;
    r.z = (u.z - mean2) * rstd2 * g2v.z + b2v.z;
    r.w = (u.w - mean2) * rstd2 * g2v.w + b2v.w;
    ((float4*)(out + (size_t)row * DIM))[tid] = r;
}

// ---------------- launch ----------------------------------------------------
extern "C" void kernel_launch(void* const* d_in, const int* in_sizes, int n_in,
                              void* d_out, int out_size)
{
    const float* x     = (const float*)d_in[0];
    const int*   amask = (const int*  )d_in[1];
    const float* wq = (const float*)d_in[2];
    const float* bq = (const float*)d_in[3];
    const float* wk = (const float*)d_in[4];
    const float* bk = (const float*)d_in[5];
    const float* wv = (const float*)d_in[6];
    const float* bv = (const float*)d_in[7];
    const float* wo = (const float*)d_in[8];
    const float* bo = (const float*)d_in[9];
    const float* ln1_g = (const float*)d_in[10];
    const float* ln1_b = (const float*)d_in[11];
    const float* w1 = (const float*)d_in[12];
    const float* b1 = (const float*)d_in[13];
    const float* w2 = (const float*)d_in[14];
    const float* b2 = (const float*)d_in[15];
    const float* lnf_g = (const float*)d_in[16];
    const float* lnf_b = (const float*)d_in[17];
    const float* ln2_g = (const float*)d_in[18];
    const float* ln2_b = (const float*)d_in[19];
    float* out = (float*)d_out;

    float *tmp, *x1, *bqkv;
    cudaGetSymbolAddress((void**)&tmp,  g_tmp);
    cudaGetSymbolAddress((void**)&x1,   g_x1);
    cudaGetSymbolAddress((void**)&bqkv, g_bqkv);

    __half *xh,*qkv,*vth,*ctxh,*x1h,*hh,*wqkvh,*woh,*w1h,*w2h;
    cudaGetSymbolAddress((void**)&xh,   g_x);
    cudaGetSymbolAddress((void**)&qkv,  g_qkv);
    cudaGetSymbolAddress((void**)&vth,  g_vt);
    cudaGetSymbolAddress((void**)&ctxh, g_ctx);
    cudaGetSymbolAddress((void**)&x1h,  g_x1h);
    cudaGetSymbolAddress((void**)&hh,   g_h);
    cudaGetSymbolAddress((void**)&wqkvh,g_wqkv);
    cudaGetSymbolAddress((void**)&woh,  g_wo);
    cudaGetSymbolAddress((void**)&w1h,  g_w1);
    cudaGetSymbolAddress((void**)&w2h,  g_w2);

    cudaFuncSetAttribute(flash_attn_fp16,
                         cudaFuncAttributeMaxDynamicSharedMemorySize, FA_SMEM);
    cudaFuncSetAttribute(hmma_gemm<false,false,true>,
                         cudaFuncAttributeMaxDynamicSharedMemorySize, HG_SMEM);
    cudaFuncSetAttribute(hmma_gemm<false,true,false>,
                         cudaFuncAttributeMaxDynamicSharedMemorySize, HG_SMEM);
    cudaFuncSetAttribute(hmma_gemm<true,false,true>,
                         cudaFuncAttributeMaxDynamicSharedMemorySize, HG_SMEM);

    const dim3 blk(256);

    // weight prep: wq|wk|wv -> fused [3072][1024]; others as before
    transpose_convert<<<dim3(DIM/32, DIM/32), blk>>>(wq, wqkvh,                 DIM, DIM);
    transpose_convert<<<dim3(DIM/32, DIM/32), blk>>>(wk, wqkvh + DIM * DIM,     DIM, DIM);
    transpose_convert<<<dim3(DIM/32, DIM/32), blk>>>(wv, wqkvh + 2 * DIM * DIM, DIM, DIM);
    transpose_convert<<<dim3(DIM/32, DIM/32), blk>>>(wo, woh, DIM, DIM);
    transpose_convert<<<dim3(FFD/32, DIM/32), blk>>>(w1, w1h, DIM, FFD);
    transpose_convert<<<dim3(DIM/32, FFD/32), blk>>>(w2, w2h, FFD, DIM);
    concat_bias3<<<(QKVD + 255) / 256, blk>>>(bq, bk, bv, bqkv);

    // x -> fp16
    convert_f16<<<(MTOK * DIM) / 1024, blk>>>(x, xh, MTOK * DIM);

    // fused QKV projection (N = 3072)
    hmma_gemm<false,false,true><<<dim3(QKVD/128, MTOK/128), blk, HG_SMEM>>>(
        xh, wqkvh, bqkv, nullptr, qkv, MTOK, QKVD, DIM);

    // V transpose per head
    transpose_v<<<dim3(SEQ/64, BATCH*NH), blk>>>(qkv, vth);

    // attention -> ctx fp16
    flash_attn_fp16<<<dim3(SEQ/128, BATCH*NH), blk, FA_SMEM>>>(
        qkv, vth, amask, ctxh);

    // O projection + residual LN1 (emit x1 fp16)
    hmma_gemm<false,true,false><<<dim3(DIM/128, MTOK/128), blk, HG_SMEM>>>(
        ctxh, woh, bo, tmp, nullptr, MTOK, DIM, DIM);
    ln_residual<true><<<MTOK, blk>>>(x, tmp, ln1_g, ln1_b, x1, x1h, 1e-5f);

    // FFN
    hmma_gemm<true,false,true><<<dim3(FFD/128, MTOK/128), blk, HG_SMEM>>>(
        x1h, w1h, b1, nullptr, hh, MTOK, FFD, DIM);
    hmma_gemm<false,true,false><<<dim3(DIM/128, MTOK/128), blk, HG_SMEM>>>(
        hh, w2h, b2, tmp, nullptr, MTOK, DIM, FFD);

    // fused LNf + LN2
    ln_double<<<MTOK, blk>>>(tmp, x1, lnf_g, lnf_b, ln2_g, ln2_b, out);
}

// round 9
// speedup vs baseline: 6.1131x; 1.0314x over previous
#include <cuda_runtime.h>
#include <cuda_fp16.h>
#include <math.h>
#include <stdint.h>

// Problem constants
constexpr int DIM  = 1024;
constexpr int NH   = 16;
constexpr int HDm  = 64;
constexpr int FFD  = 4096;
constexpr int BATCH= 2;
constexpr int SEQ  = 2048;
constexpr int MTOK = BATCH * SEQ;   // 4096
constexpr int QKVD = 3 * DIM;       // 3072

// ---------------------------------------------------------------------------
// helpers
// ---------------------------------------------------------------------------
__device__ __forceinline__ uint32_t smem_to_u32(const void* p) {
    uint32_t a;
    asm("{ .reg .u64 t; cvta.to.shared.u64 t, %1; cvt.u32.u64 %0, t; }"
        : "=r"(a) : "l"(p));
    return a;
}

__device__ __forceinline__ void ldsm_x4(uint32_t* r, uint32_t addr) {
    asm volatile("ldmatrix.sync.aligned.m8n8.x4.shared.b16 {%0,%1,%2,%3}, [%4];"
                 : "=r"(r[0]), "=r"(r[1]), "=r"(r[2]), "=r"(r[3]) : "r"(addr));
}

__device__ __forceinline__ void ldsm_x4_trans(uint32_t* r, uint32_t addr) {
    asm volatile("ldmatrix.sync.aligned.m8n8.x4.trans.shared.b16 {%0,%1,%2,%3}, [%4];"
                 : "=r"(r[0]), "=r"(r[1]), "=r"(r[2]), "=r"(r[3]) : "r"(addr));
}

__device__ __forceinline__ void mma16816(float* c, const uint32_t* a, const uint32_t* b) {
    asm volatile(
        "mma.sync.aligned.m16n8k16.row.col.f32.f16.f16.f32 "
        "{%0,%1,%2,%3}, {%4,%5,%6,%7}, {%8,%9}, {%0,%1,%2,%3};"
        : "+f"(c[0]), "+f"(c[1]), "+f"(c[2]), "+f"(c[3])
        : "r"(a[0]), "r"(a[1]), "r"(a[2]), "r"(a[3]), "r"(b[0]), "r"(b[1]));
}

__device__ __forceinline__ void cpa16(uint32_t dst, const void* src) {
    asm volatile("cp.async.ca.shared.global [%0], [%1], 16;" :: "r"(dst), "l"(src));
}

__device__ __forceinline__ uint32_t pk2(float a, float b) {
    __half2 t(__float2half_rn(a), __float2half_rn(b));
    return *(uint32_t*)&t;
}

// ---------------------------------------------------------------------------
// scratch (device globals; no allocation allowed)
// ---------------------------------------------------------------------------
__device__ __align__(256) float g_tmp[MTOK * DIM];
__device__ __align__(256) float g_x1 [MTOK * DIM];

__device__ __align__(256) __half g_x   [MTOK * DIM];
__device__ __align__(256) __half g_qkv [MTOK * QKVD];    // fused q|k|v
__device__ __align__(256) __half g_ctx [MTOK * DIM];
__device__ __align__(256) __half g_x1h [MTOK * DIM];
__device__ __align__(256) __half g_h   [MTOK * FFD];
__device__ __align__(256) __half g_wqkv[QKVD * DIM];     // [3072][1024]
__device__ __align__(256) __half g_wo  [DIM * DIM];
__device__ __align__(256) __half g_w1  [DIM * FFD];      // [FFD][DIM]
__device__ __align__(256) __half g_w2  [FFD * DIM];      // [DIM][FFD]
__device__ __align__(256) float  g_bqkv[QKVD];

// ---------------------------------------------------------------------------
// fused prep kernel: all weight transposes + x convert + bias concat
// ---------------------------------------------------------------------------
constexpr int NB_X  = (MTOK * DIM) / 1024;      // 4096  (x -> fp16)
constexpr int NB_B  = 3;                        // bias concat
constexpr int NB_SQ = (DIM/32) * (DIM/32);      // 1024 per square weight
constexpr int NB_W1 = (FFD/32) * (DIM/32);      // 4096
constexpr int NB_W2 = (DIM/32) * (FFD/32);      // 4096
constexpr int NB_PREP = NB_X + NB_B + 4 * NB_SQ + NB_W1 + NB_W2;  // 16387

__device__ __forceinline__ void tr_tile(const float* __restrict__ in,
                                        __half* __restrict__ o,
                                        int K, int N, int t, float (*ts)[33])
{
    const int tn = N / 32;
    const int n0 = (t % tn) * 32, k0 = (t / tn) * 32;
    const int tx = threadIdx.x & 31, ty = threadIdx.x >> 5;
    #pragma unroll
    for (int j = 0; j < 32; j += 8)
        ts[ty + j][tx] = in[(size_t)(k0 + ty + j) * N + n0 + tx];
    __syncthreads();
    #pragma unroll
    for (int j = 0; j < 32; j += 8) {
        int n = n0 + ty + j, k = k0 + tx;
        o[(size_t)n * K + k] = __float2half_rn(ts[tx][ty + j]);
    }
}

__global__ __launch_bounds__(256)
void prep_all(const float* __restrict__ x,
              const float* __restrict__ wq, const float* __restrict__ wk,
              const float* __restrict__ wv, const float* __restrict__ wo,
              const float* __restrict__ w1, const float* __restrict__ w2,
              const float* __restrict__ bq, const float* __restrict__ bk,
              const float* __restrict__ bv,
              __half* __restrict__ xh, __half* __restrict__ wqkvh,
              __half* __restrict__ woh, __half* __restrict__ w1h,
              __half* __restrict__ w2h, float* __restrict__ bqkv)
{
    __shared__ float ts[32][33];
    int bid = blockIdx.x;
    if (bid < NB_X) {
        int i = (bid * 256 + threadIdx.x) * 4;
        float4 v = *(const float4*)(x + i);
        *(uint2*)(xh + i) = make_uint2(pk2(v.x, v.y), pk2(v.z, v.w));
        return;
    }
    bid -= NB_X;
    if (bid < NB_B) {
        int i = bid * 1024 + threadIdx.x * 4;
        #pragma unroll
        for (int j = 0; j < 4; j++) {
            int idx = i + j;
            if (idx < QKVD)
                bqkv[idx] = (idx < DIM) ? bq[idx]
                          : ((idx < 2 * DIM) ? bk[idx - DIM] : bv[idx - 2 * DIM]);
        }
        return;
    }
    bid -= NB_B;
    if (bid < NB_SQ)       { tr_tile(wq, wqkvh,                 DIM, DIM, bid, ts); return; }
    bid -= NB_SQ;
    if (bid < NB_SQ)       { tr_tile(wk, wqkvh + DIM * DIM,     DIM, DIM, bid, ts); return; }
    bid -= NB_SQ;
    if (bid < NB_SQ)       { tr_tile(wv, wqkvh + 2 * DIM * DIM, DIM, DIM, bid, ts); return; }
    bid -= NB_SQ;
    if (bid < NB_SQ)       { tr_tile(wo, woh, DIM, DIM, bid, ts); return; }
    bid -= NB_SQ;
    if (bid < NB_W1)       { tr_tile(w1, w1h, DIM, FFD, bid, ts); return; }
    bid -= NB_W1;
    tr_tile(w2, w2h, FFD, DIM, bid, ts);
}

// ---------------------------------------------------------------------------
// HMMA fp16 GEMM, 3-stage cp.async pipeline, 2 CTAs/SM.
// ---------------------------------------------------------------------------
constexpr int HG_RSTRIDE = 80;
constexpr int HG_TILE    = 128 * HG_RSTRIDE;   // 10240 B
constexpr int HG_STAGE   = 2 * HG_TILE;        // 20480 B
constexpr int HG_SMEM    = 3 * HG_STAGE;       // 61440 B

__device__ __forceinline__ void hg_load_tile(const __half* __restrict__ src,
                                             int rowBase, int K, int k0,
                                             uint32_t dstBase, int tid)
{
    #pragma unroll
    for (int i = 0; i < 2; i++) {
        int c = tid + i * 256;
        int row = c >> 2, cc = c & 3;
        uint32_t dst = dstBase + row * HG_RSTRIDE + cc * 16;
        const void* s = src + (size_t)(rowBase + row) * K + k0 + cc * 8;
        cpa16(dst, s);
    }
}

template<bool GELU, bool WRITE_F32, bool EMIT>
__global__ __launch_bounds__(256, 2)
void hmma_gemm(const __half* __restrict__ A, const __half* __restrict__ B,
               const float* __restrict__ bias, float* __restrict__ C,
               __half* __restrict__ Ch, int M, int N, int K)
{
    extern __shared__ char smem[];
    const uint32_t sb = smem_to_u32(smem);
    const int tid = threadIdx.x, wid = tid >> 5, lane = tid & 31;
    const int warpM = wid >> 2, warpN = wid & 3;
    const int bRow = blockIdx.y * 128, bCol = blockIdx.x * 128;

    float acc[4][4][4];
    #pragma unroll
    for (int m = 0; m < 4; m++)
        #pragma unroll
        for (int n = 0; n < 4; n++)
            #pragma unroll
            for (int e = 0; e < 4; e++) acc[m][n][e] = 0.f;

    #pragma unroll
    for (int p = 0; p < 2; p++) {
        uint32_t base = sb + p * HG_STAGE;
        hg_load_tile(A, bRow, K, p * 32, base, tid);
        hg_load_tile(B, bCol, K, p * 32, base + HG_TILE, tid);
        asm volatile("cp.async.commit_group;");
    }

    const int nk = K >> 5;
    for (int ks = 0; ks < nk; ks++) {
        if (ks == nk - 1) { asm volatile("cp.async.wait_group 0;"); }
        else              { asm volatile("cp.async.wait_group 1;"); }
        __syncthreads();

        if (ks + 2 < nk) {
            uint32_t base = sb + (uint32_t)((ks + 2) % 3) * HG_STAGE;
            const int k0 = (ks + 2) << 5;
            hg_load_tile(A, bRow, K, k0, base, tid);
            hg_load_tile(B, bCol, K, k0, base + HG_TILE, tid);
            asm volatile("cp.async.commit_group;");
        }

        const uint32_t stg = sb + (uint32_t)(ks % 3) * HG_STAGE;
        #pragma unroll
        for (int h = 0; h < 2; h++) {
            const int ke = h * 16;
            uint32_t aF[4][4], bF[4][2];
            #pragma unroll
            for (int m = 0; m < 4; m++) {
                uint32_t ra = stg
                    + (warpM * 64 + m * 16 + (lane & 15)) * HG_RSTRIDE
                    + (ke + (lane >> 4) * 8) * 2;
                ldsm_x4(aF[m], ra);
            }
            #pragma unroll
            for (int jp = 0; jp < 2; jp++) {
                uint32_t rb = stg + HG_TILE
                    + (warpN * 32 + jp * 16 + (lane >> 4) * 8 + (lane & 7)) * HG_RSTRIDE
                    + (ke + ((lane >> 3) & 1) * 8) * 2;
                uint32_t t4[4];
                ldsm_x4(t4, rb);
                bF[2*jp][0] = t4[0]; bF[2*jp][1] = t4[1];
                bF[2*jp+1][0] = t4[2]; bF[2*jp+1][1] = t4[3];
            }
            #pragma unroll
            for (int m = 0; m < 4; m++)
                #pragma unroll
                for (int n = 0; n < 4; n++)
                    mma16816(acc[m][n], aF[m], bF[n]);
        }
    }

    #pragma unroll
    for (int m = 0; m < 4; m++) {
        #pragma unroll
        for (int half = 0; half < 2; half++) {
            const size_t row = bRow + warpM * 64 + m * 16 + (lane >> 2) + half * 8;
            #pragma unroll
            for (int n = 0; n < 4; n++) {
                const int col = bCol + warpN * 32 + n * 8 + (lane & 3) * 2;
                float v0 = acc[m][n][half * 2 + 0] + bias[col];
                float v1 = acc[m][n][half * 2 + 1] + bias[col + 1];
                if (GELU) {
                    v0 = 0.5f * v0 * (1.f + erff(v0 * 0.70710678118654752f));
                    v1 = 0.5f * v1 * (1.f + erff(v1 * 0.70710678118654752f));
                }
                if (WRITE_F32) {
                    float2 w; w.x = v0; w.y = v1;
                    *(float2*)(C + row * N + col) = w;
                }
                if (EMIT)
                    *(uint32_t*)(Ch + row * N + col) = pk2(v0, v1);
            }
        }
    }
}

// ---------------------------------------------------------------------------
// Flash attention, HMMA fp16, double-buffered K/V, fixed-max softmax.
// Q/K/V all read from fused qkv (stride QKVD). V staged token-major and
// consumed via ldmatrix.trans (no pre-transpose kernel).
// ---------------------------------------------------------------------------
constexpr int FA_ROW   = 144;
constexpr int FA_Q     = 0;
constexpr int FA_KV    = FA_Q + 128 * FA_ROW;   // 18432
constexpr int FA_KVT   = 64 * FA_ROW;           // 9216
constexpr int FA_KVSTG = 2 * FA_KVT;            // 18432
constexpr int FA_MSK   = FA_KV + 2 * FA_KVSTG;  // 55296
constexpr int FA_SMEM  = FA_MSK + 2 * 64 * 4;   // 55808

__global__ __launch_bounds__(256, 2)
void flash_attn_fp16(const __half* __restrict__ QKV, const int* __restrict__ amask,
                     __half* __restrict__ Ctx)
{
    extern __shared__ char smc[];
    const uint32_t sb = smem_to_u32(smc);
    const int tid = threadIdx.x, wid = tid >> 5, lane = tid & 31;
    const int bh = blockIdx.y, b = bh >> 4, h = bh & 15;
    const int q0 = blockIdx.x * 128;

    const __half* Qg = QKV + (size_t)(b * SEQ + q0) * QKVD + h * HDm;
    const __half* Kg = QKV + (size_t)(b * SEQ) * QKVD + DIM + h * HDm;
    const __half* Vg = QKV + (size_t)(b * SEQ) * QKVD + 2 * DIM + h * HDm;
    int* msk = (int*)(smc + FA_MSK);

    #pragma unroll
    for (int i = 0; i < 4; i++) {
        int c = tid + i * 256; int r = c >> 3, cc = c & 7;
        cpa16(sb + FA_Q + r * FA_ROW + cc * 16, Qg + (size_t)r * QKVD + cc * 8);
    }
    {
        uint32_t kv0 = sb + FA_KV;
        #pragma unroll
        for (int i = 0; i < 2; i++) {
            int c = tid + i * 256; int r = c >> 3, cc = c & 7;
            cpa16(kv0 + 0 * FA_KVT + r * FA_ROW + cc * 16, Kg + (size_t)r * QKVD + cc * 8);
            cpa16(kv0 + 1 * FA_KVT + r * FA_ROW + cc * 16, Vg + (size_t)r * QKVD + cc * 8);
        }
    }
    if (tid < 64) msk[tid] = amask[b * SEQ + tid];
    asm volatile("cp.async.commit_group;");

    float l0 = 0.f, l1 = 0.f;
    float o[8][4];
    #pragma unroll
    for (int nt = 0; nt < 8; nt++)
        #pragma unroll
        for (int e = 0; e < 4; e++) o[nt][e] = 0.f;

    const int kb = 2 * (lane & 3);
    constexpr int NT = SEQ / 64;   // 32

    for (int t = 0; t < NT; t++) {
        asm volatile("cp.async.wait_group 0;");
        __syncthreads();

        if (t + 1 < NT) {
            const int k1 = (t + 1) * 64;
            uint32_t kvn = sb + FA_KV + ((t + 1) & 1) * FA_KVSTG;
            #pragma unroll
            for (int i = 0; i < 2; i++) {
                int c = tid + i * 256; int r = c >> 3, cc = c & 7;
                cpa16(kvn + 0 * FA_KVT + r * FA_ROW + cc * 16, Kg + (size_t)(k1 + r) * QKVD + cc * 8);
                cpa16(kvn + 1 * FA_KVT + r * FA_ROW + cc * 16, Vg + (size_t)(k1 + r) * QKVD + cc * 8);
            }
            if (tid < 64) msk[((t + 1) & 1) * 64 + tid] = amask[b * SEQ + k1 + tid];
            asm volatile("cp.async.commit_group;");
        }

        const uint32_t kvb = sb + FA_KV + (t & 1) * FA_KVSTG;
        const int* mrow = msk + (t & 1) * 64;

        // ---- S = Q K^T ----
        float sacc[8][4];
        #pragma unroll
        for (int nt = 0; nt < 8; nt++)
            #pragma unroll
            for (int e = 0; e < 4; e++) sacc[nt][e] = 0.f;

        #pragma unroll
        for (int kk = 0; kk < 4; kk++) {
            uint32_t aF[4];
            uint32_t ra = sb + FA_Q
                + (wid * 16 + (lane & 15)) * FA_ROW
                + (kk * 16 + (lane >> 4) * 8) * 2;
            ldsm_x4(aF, ra);
            #pragma unroll
            for (int jp = 0; jp < 4; jp++) {
                uint32_t rb = kvb
                    + (jp * 16 + (lane >> 4) * 8 + (lane & 7)) * FA_ROW
                    + (kk * 16 + ((lane >> 3) & 1) * 8) * 2;
                uint32_t bF[4];
                ldsm_x4(bF, rb);
                mma16816(sacc[2*jp],   aF, &bF[0]);
                mma16816(sacc[2*jp+1], aF, &bF[2]);
            }
        }

        // ---- fixed-max softmax: p = exp(s/8) (masked -> 0) ----
        float s0 = 0.f, s1 = 0.f;
        #pragma unroll
        for (int nt = 0; nt < 8; nt++) {
            bool z0 = mrow[nt * 8 + kb] == 0, z1 = mrow[nt * 8 + kb + 1] == 0;
            float p0 = z0 ? 0.f : __expf(sacc[nt][0] * 0.125f);
            float p1 = z1 ? 0.f : __expf(sacc[nt][1] * 0.125f);
            float p2 = z0 ? 0.f : __expf(sacc[nt][2] * 0.125f);
            float p3 = z1 ? 0.f : __expf(sacc[nt][3] * 0.125f);
            sacc[nt][0] = p0; sacc[nt][1] = p1; sacc[nt][2] = p2; sacc[nt][3] = p3;
            s0 += p0 + p1; s1 += p2 + p3;
        }
        s0 += __shfl_xor_sync(0xffffffffu, s0, 1);
        s0 += __shfl_xor_sync(0xffffffffu, s0, 2);
        s1 += __shfl_xor_sync(0xffffffffu, s1, 1);
        s1 += __shfl_xor_sync(0xffffffffu, s1, 2);
        l0 += s0; l1 += s1;

        // ---- O += P V  (V token-major, ldmatrix.trans) ----
        #pragma unroll
        for (int j = 0; j < 4; j++) {
            uint32_t pF[4];
            pF[0] = pk2(sacc[2*j][0],   sacc[2*j][1]);
            pF[1] = pk2(sacc[2*j][2],   sacc[2*j][3]);
            pF[2] = pk2(sacc[2*j+1][0], sacc[2*j+1][1]);
            pF[3] = pk2(sacc[2*j+1][2], sacc[2*j+1][3]);
            #pragma unroll
            for (int t4i = 0; t4i < 4; t4i++) {
                uint32_t rb = kvb + FA_KVT
                    + (j * 16 + ((lane >> 3) & 1) * 8 + (lane & 7)) * FA_ROW
                    + (t4i * 16 + (lane >> 4) * 8) * 2;
                uint32_t bF[4];
                ldsm_x4_trans(bF, rb);
                mma16816(o[2*t4i],   pF, &bF[0]);
                mma16816(o[2*t4i+1], pF, &bF[2]);
            }
        }
    }

    const float i0 = 1.f / l0, i1 = 1.f / l1;
    const size_t r0 = (size_t)b * SEQ + q0 + wid * 16 + (lane >> 2);
    const size_t r1 = r0 + 8;
    #pragma unroll
    for (int nt = 0; nt < 8; nt++) {
        const int col = h * HDm + nt * 8 + kb;
        *(uint32_t*)(Ctx + r0 * DIM + col) = pk2(o[nt][0] * i0, o[nt][1] * i0);
        *(uint32_t*)(Ctx + r1 * DIM + col) = pk2(o[nt][2] * i1, o[nt][3] * i1);
    }
}

// ---------------- LN building block --------------------------------------
__device__ __forceinline__ void block_ln_stats(float4 v, float& mean, float& rstd,
                                               float eps, float* ssum, float* ssq,
                                               float* stats, int tid)
{
    float sum = v.x + v.y + v.z + v.w;
    float sq  = v.x * v.x + v.y * v.y + v.z * v.z + v.w * v.w;
    #pragma unroll
    for (int mm = 16; mm; mm >>= 1) {
        sum += __shfl_xor_sync(0xffffffffu, sum, mm);
        sq  += __shfl_xor_sync(0xffffffffu, sq,  mm);
    }
    const int wid = tid >> 5, lane = tid & 31;
    if (lane == 0) { ssum[wid] = sum; ssq[wid] = sq; }
    __syncthreads();
    if (tid == 0) {
        float S = 0.f, Qq = 0.f;
        #pragma unroll
        for (int i = 0; i < 8; i++) { S += ssum[i]; Qq += ssq[i]; }
        float mu = S * (1.f / DIM);
        float var = fmaxf(Qq * (1.f / DIM) - mu * mu, 0.f);
        stats[0] = mu;
        stats[1] = rsqrtf(var + eps);
    }
    __syncthreads();
    mean = stats[0]; rstd = stats[1];
}

// out = LN(a + b; g, beta, eps)  (+fp16 emit)
template<bool EMIT>
__global__ __launch_bounds__(256)
void ln_residual(const float* __restrict__ A, const float* __restrict__ Bv,
                 const float* __restrict__ g, const float* __restrict__ be,
                 float* __restrict__ out, __half* __restrict__ oh, float eps)
{
    const int row = blockIdx.x;
    const int tid = threadIdx.x;
    __shared__ float ssum[8], ssq[8], stats[2];
    const float4 va = ((const float4*)(A  + (size_t)row * DIM))[tid];
    const float4 vb = ((const float4*)(Bv + (size_t)row * DIM))[tid];
    float4 v;
    v.x = va.x + vb.x; v.y = va.y + vb.y;
    v.z = va.z + vb.z; v.w = va.w + vb.w;
    float mean, rstd;
    block_ln_stats(v, mean, rstd, eps, ssum, ssq, stats, tid);
    const float4 gg = ((const float4*)g)[tid];
    const float4 bb = ((const float4*)be)[tid];
    float4 r;
    r.x = (v.x - mean) * rstd * gg.x + bb.x;
    r.y = (v.y - mean) * rstd * gg.y + bb.y;
    r.z = (v.z - mean) * rstd * gg.z + bb.z;
    r.w = (v.w - mean) * rstd * gg.w + bb.w;
    ((float4*)(out + (size_t)row * DIM))[tid] = r;
    if (EMIT) {
        ((uint2*)(oh + (size_t)row * DIM))[tid] =
            make_uint2(pk2(r.x, r.y), pk2(r.z, r.w));
    }
}

// fused: ff = LN(tmp + x1; lnf, 1e-12); out = LN(x1 + ff; ln2, 1e-5)
__global__ __launch_bounds__(256)
void ln_double(const float* __restrict__ Tmp, const float* __restrict__ X1,
               const float* __restrict__ gf, const float* __restrict__ bf,
               const float* __restrict__ g2, const float* __restrict__ b2,
               float* __restrict__ out)
{
    const int row = blockIdx.x;
    const int tid = threadIdx.x;
    __shared__ float ssum[8], ssq[8], stats[2];
    const float4 vt = ((const float4*)(Tmp + (size_t)row * DIM))[tid];
    const float4 vx = ((const float4*)(X1  + (size_t)row * DIM))[tid];
    float4 v;
    v.x = vt.x + vx.x; v.y = vt.y + vx.y;
    v.z = vt.z + vx.z; v.w = vt.w + vx.w;
    float mean, rstd;
    block_ln_stats(v, mean, rstd, 1e-12f, ssum, ssq, stats, tid);
    const float4 gg = ((const float4*)gf)[tid];
    const float4 bb = ((const float4*)bf)[tid];
    float4 u;
    u.x = (v.x - mean) * rstd * gg.x + bb.x + vx.x;
    u.y = (v.y - mean) * rstd * gg.y + bb.y + vx.y;
    u.z = (v.z - mean) * rstd * gg.z + bb.z + vx.z;
    u.w = (v.w - mean) * rstd * gg.w + bb.w + vx.w;
    __syncthreads();
    float mean2, rstd2;
    block_ln_stats(u, mean2, rstd2, 1e-5f, ssum, ssq, stats, tid);
    const float4 g2v = ((const float4*)g2)[tid];
    const float4 b2v = ((const float4*)b2)[tid];
    float4 r;
    r.x = (u.x - mean2) * rstd2 * g2v.x + b2v.x;
    r.y = (u.y - mean2) * rstd2 * g2v.y + b2v.y;
    r.z = (u.z - mean2) * rstd2 * g2v.z + b2v.z;
    r.w = (u.w - mean2) * rstd2 * g2v.w + b2v.w;
    ((float4*)(out + (size_t)row * DIM))[tid] = r;
}

// ---------------- launch ----------------------------------------------------
extern "C" void kernel_launch(void* const* d_in, const int* in_sizes, int n_in,
                              void* d_out, int out_size)
{
    const float* x     = (const float*)d_in[0];
    const int*   amask = (const int*  )d_in[1];
    const float* wq = (const float*)d_in[2];
    const float* bq = (const float*)d_in[3];
    const float* wk = (const float*)d_in[4];
    const float* bk = (const float*)d_in[5];
    const float* wv = (const float*)d_in[6];
    const float* bv = (const float*)d_in[7];
    const float* wo = (const float*)d_in[8];
    const float* bo = (const float*)d_in[9];
    const float* ln1_g = (const float*)d_in[10];
    const float* ln1_b = (const float*)d_in[11];
    const float* w1 = (const float*)d_in[12];
    const float* b1 = (const float*)d_in[13];
    const float* w2 = (const float*)d_in[14];
    const float* b2 = (const float*)d_in[15];
    const float* lnf_g = (const float*)d_in[16];
    const float* lnf_b = (const float*)d_in[17];
    const float* ln2_g = (const float*)d_in[18];
    const float* ln2_b = (const float*)d_in[19];
    float* out = (float*)d_out;

    float *tmp, *x1, *bqkv;
    cudaGetSymbolAddress((void**)&tmp,  g_tmp);
    cudaGetSymbolAddress((void**)&x1,   g_x1);
    cudaGetSymbolAddress((void**)&bqkv, g_bqkv);

    __half *xh,*qkv,*ctxh,*x1h,*hh,*wqkvh,*woh,*w1h,*w2h;
    cudaGetSymbolAddress((void**)&xh,   g_x);
    cudaGetSymbolAddress((void**)&qkv,  g_qkv);
    cudaGetSymbolAddress((void**)&ctxh, g_ctx);
    cudaGetSymbolAddress((void**)&x1h,  g_x1h);
    cudaGetSymbolAddress((void**)&hh,   g_h);
    cudaGetSymbolAddress((void**)&wqkvh,g_wqkv);
    cudaGetSymbolAddress((void**)&woh,  g_wo);
    cudaGetSymbolAddress((void**)&w1h,  g_w1);
    cudaGetSymbolAddress((void**)&w2h,  g_w2);

    cudaFuncSetAttribute(flash_attn_fp16,
                         cudaFuncAttributeMaxDynamicSharedMemorySize, FA_SMEM);
    cudaFuncSetAttribute(hmma_gemm<false,false,true>,
                         cudaFuncAttributeMaxDynamicSharedMemorySize, HG_SMEM);
    cudaFuncSetAttribute(hmma_gemm<false,true,false>,
                         cudaFuncAttributeMaxDynamicSharedMemorySize, HG_SMEM);
    cudaFuncSetAttribute(hmma_gemm<true,false,true>,
                         cudaFuncAttributeMaxDynamicSharedMemorySize, HG_SMEM);

    const dim3 blk(256);

    // one fused prep kernel: all transposes + x convert + bias concat
    prep_all<<<NB_PREP, blk>>>(x, wq, wk, wv, wo, w1, w2, bq, bk, bv,
                               xh, wqkvh, woh, w1h, w2h, bqkv);

    // fused QKV projection (N = 3072)
    hmma_gemm<false,false,true><<<dim3(QKVD/128, MTOK/128), blk, HG_SMEM>>>(
        xh, wqkvh, bqkv, nullptr, qkv, MTOK, QKVD, DIM);

    // attention -> ctx fp16 (V consumed via ldmatrix.trans, no pre-transpose)
    flash_attn_fp16<<<dim3(SEQ/128, BATCH*NH), blk, FA_SMEM>>>(
        qkv, amask, ctxh);

    // O projection + residual LN1 (emit x1 fp16)
    hmma_gemm<false,true,false><<<dim3(DIM/128, MTOK/128), blk, HG_SMEM>>>(
        ctxh, woh, bo, tmp, nullptr, MTOK, DIM, DIM);
    ln_residual<true><<<MTOK, blk>>>(x, tmp, ln1_g, ln1_b, x1, x1h, 1e-5f);

    // FFN
    hmma_gemm<true,false,true><<<dim3(FFD/128, MTOK/128), blk, HG_SMEM>>>(
        x1h, w1h, b1, nullptr, hh, MTOK, FFD, DIM);
    hmma_gemm<false,true,false><<<dim3(DIM/128, MTOK/128), blk, HG_SMEM>>>(
        hh, w2h, b2, tmp, nullptr, MTOK, DIM, FFD);

    // fused LNf + LN2
    ln_double<<<MTOK, blk>>>(tmp, x1, lnf_g, lnf_b, ln2_g, ln2_b, out);
}